// round 10
// baseline (speedup 1.0000x reference)
#include <cuda_runtime.h>
#include <cuda_bf16.h>
#include <cuda_fp16.h>
#include <math.h>
#include <stdint.h>

#define BB 2
#define TT 2048
#define DIM 4096
#define NH 32
#define NKV 8
#define HD 128
#define MTOK (BB * TT)
#define GK 4096
#define NKVD (NKV * HD)             // 1024
#define NQKV (DIM + 2 * NKVD)       // 6144

// ---------------- device scratch ---------------------------------------
__device__ __align__(16) __half g_xh[(size_t)MTOK * DIM];
__device__ __align__(16) __half g_xl[(size_t)MTOK * DIM];
__device__ __align__(16) __half g_wqkv[(size_t)NQKV * GK];
__device__ __align__(16) __half g_wo[(size_t)DIM * DIM];
__device__ __align__(16) __half g_ch[(size_t)MTOK * DIM];
__device__ __align__(16) __half g_cl[(size_t)MTOK * DIM];

// head-major fp16 q/k/v for flash
__device__ __align__(16) __half g_fqh[(size_t)BB * NH * TT * HD];
__device__ __align__(16) __half g_fql[(size_t)BB * NH * TT * HD];
__device__ __align__(16) __half g_fkh[(size_t)BB * NKV * TT * HD];
__device__ __align__(16) __half g_fkl[(size_t)BB * NKV * TT * HD];
__device__ __align__(16) __half g_fv [(size_t)BB * NKV * TT * HD];

// ---------------- helpers ----------------------------------------------
__device__ __forceinline__ uint32_t smem_u32(const void* p) {
    uint32_t a;
    asm("{ .reg .u64 t; cvta.to.shared.u64 t, %1; cvt.u32.u64 %0, t; }"
        : "=r"(a) : "l"(p));
    return a;
}
__device__ __forceinline__ void cpa16(uint32_t dst, const void* src) {
    asm volatile("cp.async.cg.shared.global [%0], [%1], 16;"
                 :: "r"(dst), "l"(src) : "memory");
}
__device__ __forceinline__ void cp_commit() {
    asm volatile("cp.async.commit_group;" ::: "memory");
}
__device__ __forceinline__ void cp_wait1() {
    asm volatile("cp.async.wait_group 1;" ::: "memory");
}
__device__ __forceinline__ void cp_wait0() {
    asm volatile("cp.async.wait_group 0;" ::: "memory");
}
__device__ __forceinline__ void ldsm4(uint32_t* r, uint32_t addr) {
    asm volatile("ldmatrix.sync.aligned.m8n8.x4.shared.b16 {%0,%1,%2,%3}, [%4];"
                 : "=r"(r[0]), "=r"(r[1]), "=r"(r[2]), "=r"(r[3]) : "r"(addr));
}
__device__ __forceinline__ void ldsm4t(uint32_t* r, uint32_t addr) {
    asm volatile("ldmatrix.sync.aligned.m8n8.x4.trans.shared.b16 {%0,%1,%2,%3}, [%4];"
                 : "=r"(r[0]), "=r"(r[1]), "=r"(r[2]), "=r"(r[3]) : "r"(addr));
}
__device__ __forceinline__ void mma_f16(float* d, const uint32_t* a, const uint32_t* b) {
    asm volatile(
        "mma.sync.aligned.m16n8k16.row.col.f32.f16.f16.f32 "
        "{%0,%1,%2,%3}, {%4,%5,%6,%7}, {%8,%9}, {%0,%1,%2,%3};\n"
        : "+f"(d[0]), "+f"(d[1]), "+f"(d[2]), "+f"(d[3])
        : "r"(a[0]), "r"(a[1]), "r"(a[2]), "r"(a[3]), "r"(b[0]), "r"(b[1]));
}
__device__ __forceinline__ uint32_t pack_h2(float lo, float hi) {
    __half2 h = __floats2half2_rn(lo, hi);
    return *(uint32_t*)&h;
}

// ---------------- fused prepack (vectorized, 4 elems/thread) -------------
#define NX  (MTOK * DIM)        // 16777216
#define NWQ (DIM * GK)          // 16777216
#define NWK (NKVD * GK)         // 4194304
#define TOTP4 ((NX + NWQ + 2 * NWK + NWQ) / 4)   // 14680064
__global__ void prep_all(const float4* __restrict__ x,
                         const float4* __restrict__ wq,
                         const float4* __restrict__ wk,
                         const float4* __restrict__ wv,
                         const float4* __restrict__ wo) {
    int i = blockIdx.x * blockDim.x + threadIdx.x;
    if (i >= TOTP4) return;
    if (i < NX / 4) {
        float4 v = x[i];
        __half2 h01 = __floats2half2_rn(v.x, v.y);
        __half2 h23 = __floats2half2_rn(v.z, v.w);
        __half2 l01 = __floats2half2_rn(v.x - __half2float(h01.x),
                                        v.y - __half2float(h01.y));
        __half2 l23 = __floats2half2_rn(v.z - __half2float(h23.x),
                                        v.w - __half2float(h23.y));
        uint2 hp; hp.x = *(uint32_t*)&h01; hp.y = *(uint32_t*)&h23;
        uint2 lp; lp.x = *(uint32_t*)&l01; lp.y = *(uint32_t*)&l23;
        *(uint2*)(g_xh + (size_t)i * 4) = hp;
        *(uint2*)(g_xl + (size_t)i * 4) = lp;
    } else {
        const float4* src;
        __half* dst;
        size_t j;
        if (i < (NX + NWQ) / 4) {
            j = i - NX / 4; src = wq; dst = g_wqkv;
        } else if (i < (NX + NWQ + NWK) / 4) {
            j = i - (NX + NWQ) / 4; src = wk; dst = g_wqkv + (size_t)DIM * GK;
        } else if (i < (NX + NWQ + 2 * NWK) / 4) {
            j = i - (NX + NWQ + NWK) / 4; src = wv;
            dst = g_wqkv + (size_t)(DIM + NKVD) * GK;
        } else {
            j = i - (NX + NWQ + 2 * NWK) / 4; src = wo; dst = g_wo;
        }
        float4 v = src[j];
        __half2 h01 = __floats2half2_rn(v.x, v.y);
        __half2 h23 = __floats2half2_rn(v.z, v.w);
        uint2 hp; hp.x = *(uint32_t*)&h01; hp.y = *(uint32_t*)&h23;
        *(uint2*)(dst + j * 4) = hp;
    }
}

// ---------------- HMMA fp16x2 GEMM mainloop (warp tile 32x64) ------------
#define BKC 64
#define ROWB 144
#define MAT_BYTES (128 * ROWB)         // 18432
#define STAGE_BYTES (3 * MAT_BYTES)    // 55296
#define GNC (GK / BKC)                 // 64
#define GEMM_SMEM (2 * STAGE_BYTES)    // 110592

// warp layout: 4 (m) x 2 (n); warp tile 32x64; accum d[2][8][4]
// bm uses bmofs (tile-row offset) so kernels can be split by M for overlap.
#define GEMM_MAINLOOP(Ah, Al, Bh)                                              \
    extern __shared__ char sm[];                                               \
    const uint32_t sbase = smem_u32(sm);                                       \
    const int tid  = threadIdx.x;                                              \
    const int lane = tid & 31;                                                 \
    const int wid  = tid >> 5;                                                 \
    const int wm   = wid & 3;                                                  \
    const int wn   = wid >> 2;                                                 \
    const int bm   = (blockIdx.y + bmofs) * 128;                               \
    const int bn   = blockIdx.x * 128;                                         \
    const __half* mats[3] = {Ah, Al, Bh};                                      \
    float d[2][8][4];                                                          \
    _Pragma("unroll")                                                          \
    for (int i = 0; i < 2; i++)                                                \
        _Pragma("unroll")                                                      \
        for (int j = 0; j < 8; j++)                                            \
            _Pragma("unroll")                                                  \
            for (int r = 0; r < 4; r++) d[i][j][r] = 0.f;                      \
    auto load_chunk = [&](int buf, int c) {                                    \
        const int kofs = c * BKC;                                              \
        const uint32_t base = sbase + buf * STAGE_BYTES;                       \
        _Pragma("unroll")                                                      \
        for (int t = 0; t < 12; t++) {                                         \
            int i   = tid + t * 256;                                           \
            int mat = i >> 10;                                                 \
            int idx = i & 1023;                                                \
            int row = idx >> 3;                                                \
            int ch  = idx & 7;                                                 \
            int grow = ((mat < 2) ? bm : bn) + row;                            \
            cpa16(base + mat * MAT_BYTES + row * ROWB + ch * 16,               \
                  mats[mat] + (size_t)grow * GK + kofs + ch * 8);              \
        }                                                                      \
    };                                                                         \
    load_chunk(0, 0); cp_commit();                                             \
    const uint32_t a_off =                                                     \
        (uint32_t)((wm * 32 + (lane & 15)) * ROWB + (lane >> 4) * 16);         \
    const uint32_t b_off = (uint32_t)(2 * MAT_BYTES +                          \
        (wn * 64 + (lane & 7) + ((lane >> 4) & 1) * 8) * ROWB +                \
        ((lane >> 3) & 1) * 16);                                               \
    for (int c = 0; c < GNC; ++c) {                                            \
        const int b = c & 1;                                                   \
        if (c + 1 < GNC) {                                                     \
            load_chunk(b ^ 1, c + 1);                                          \
            cp_commit();                                                       \
            cp_wait1();                                                        \
        } else {                                                               \
            cp_wait0();                                                        \
        }                                                                      \
        __syncthreads();                                                       \
        const uint32_t stg = sbase + b * STAGE_BYTES;                          \
        _Pragma("unroll")                                                      \
        for (int ks = 0; ks < 4; ks++) {                                       \
            uint32_t ah[2][4], al[2][4], bh[4][4];                             \
            _Pragma("unroll")                                                  \
            for (int i = 0; i < 2; i++)                                        \
                ldsm4(ah[i], stg + a_off + i * (16 * ROWB) + ks * 32);         \
            _Pragma("unroll")                                                  \
            for (int i = 0; i < 2; i++)                                        \
                ldsm4(al[i], stg + MAT_BYTES + a_off + i * (16 * ROWB) + ks * 32); \
            _Pragma("unroll")                                                  \
            for (int jj = 0; jj < 4; jj++)                                     \
                ldsm4(bh[jj], stg + b_off + jj * (16 * ROWB) + ks * 32);       \
            _Pragma("unroll")                                                  \
            for (int i = 0; i < 2; i++)                                        \
                _Pragma("unroll")                                              \
                for (int j = 0; j < 8; j++) {                                  \
                    const uint32_t* ph = &bh[j >> 1][(j & 1) * 2];             \
                    mma_f16(d[i][j], ah[i], ph);                               \
                    mma_f16(d[i][j], al[i], ph);                               \
                }                                                              \
        }                                                                      \
        __syncthreads();                                                       \
    }

// ---- GEMM 1: qkv projection with fused RoPE + fp16 hi/lo pack ----------
__global__ __launch_bounds__(256, 2)
void gemm_qkv_rope(const __half* __restrict__ Ah,
                   const __half* __restrict__ Al,
                   const __half* __restrict__ Bh,
                   const float* __restrict__ fc,
                   const float* __restrict__ fs,
                   int bmofs) {
    GEMM_MAINLOOP(Ah, Al, Bh)

    const int r0 = bm + wm * 32 + (lane >> 2);
    const int c0 = bn + wn * 64 + (lane & 3) * 2;

    auto store_pair = [&](int row, int col, float v0, float v1) {
        int b = row >> 11, t = row & 2047;
        if (col < DIM) {                       // q: rope
            int hh = col >> 7, dp = (col & 127) >> 1;
            float c = fc[t * 64 + dp], s = fs[t * 64 + dp];
            float o0 = v0 * c - v1 * s;
            float o1 = v0 * s + v1 * c;
            size_t dst = (((size_t)(b * NH + hh) * TT + t) << 7) + 2 * dp;
            __half h0 = __float2half_rn(o0), h1 = __float2half_rn(o1);
            __half2 hv; hv.x = h0; hv.y = h1;
            *(uint32_t*)(g_fqh + dst) = *(uint32_t*)&hv;
            __half2 lv;
            lv.x = __float2half_rn(o0 - __half2float(h0));
            lv.y = __float2half_rn(o1 - __half2float(h1));
            *(uint32_t*)(g_fql + dst) = *(uint32_t*)&lv;
        } else if (col < DIM + NKVD) {         // k: rope
            int cc = col - DIM;
            int hh = cc >> 7, dp = (cc & 127) >> 1;
            float c = fc[t * 64 + dp], s = fs[t * 64 + dp];
            float o0 = v0 * c - v1 * s;
            float o1 = v0 * s + v1 * c;
            size_t dst = (((size_t)(b * NKV + hh) * TT + t) << 7) + 2 * dp;
            __half h0 = __float2half_rn(o0), h1 = __float2half_rn(o1);
            __half2 hv; hv.x = h0; hv.y = h1;
            *(uint32_t*)(g_fkh + dst) = *(uint32_t*)&hv;
            __half2 lv;
            lv.x = __float2half_rn(o0 - __half2float(h0));
            lv.y = __float2half_rn(o1 - __half2float(h1));
            *(uint32_t*)(g_fkl + dst) = *(uint32_t*)&lv;
        } else {                               // v: plain fp16
            int cc = col - DIM - NKVD;
            int hh = cc >> 7, dd = cc & 127;
            size_t dst = (((size_t)(b * NKV + hh) * TT + t) << 7) + dd;
            __half2 hv; hv.x = __float2half_rn(v0); hv.y = __float2half_rn(v1);
            *(uint32_t*)(g_fv + dst) = *(uint32_t*)&hv;
        }
    };

#pragma unroll
    for (int i = 0; i < 2; i++)
#pragma unroll
        for (int j = 0; j < 8; j++) {
            int col = c0 + j * 8;
            store_pair(r0 + i * 16,     col, d[i][j][0], d[i][j][1]);
            store_pair(r0 + i * 16 + 8, col, d[i][j][2], d[i][j][3]);
        }
}

// ---- GEMM 2: output projection, fp32 C --------------------------------
__global__ __launch_bounds__(256, 2)
void gemm_f16x2(const __half* __restrict__ Ah,
                const __half* __restrict__ Al,
                const __half* __restrict__ Bh,
                float* __restrict__ C, int N, int bmofs) {
    GEMM_MAINLOOP(Ah, Al, Bh)

    const int r0 = bm + wm * 32 + (lane >> 2);
    const int c0 = bn + wn * 64 + (lane & 3) * 2;
#pragma unroll
    for (int i = 0; i < 2; i++)
#pragma unroll
        for (int j = 0; j < 8; j++) {
            int row = r0 + i * 16;
            int col = c0 + j * 8;
            *(float2*)&C[(size_t)row * N + col] =
                make_float2(d[i][j][0], d[i][j][1]);
            *(float2*)&C[(size_t)(row + 8) * N + col] =
                make_float2(d[i][j][2], d[i][j][3]);
        }
}

// ---------------- flash attention: fp16 HMMA, FA2 register softmax -----
#define FSTG 65536
#define FSTGB 49152
#define FSMEM (FSTG + 2 * FSTGB)        // 163840
#define NSTILE (TT / 64)                // 32

__global__ __launch_bounds__(256, 1)
void flash_hmma(const __half* __restrict__ Qh, const __half* __restrict__ Ql,
                const __half* __restrict__ Kh, const __half* __restrict__ Kl,
                const __half* __restrict__ Vv,
                __half* __restrict__ Ch, __half* __restrict__ Cl,
                int b) {
    extern __shared__ char sm[];
    const uint32_t sb = smem_u32(sm);
    const int tid = threadIdx.x, lane = tid & 31, w = tid >> 5;
    const int t0 = blockIdx.x * 128;
    const int h  = blockIdx.y;
    const int kh = h & 7;

    const __half* qhp = Qh + (((size_t)(b * NH + h) * TT + t0) << 7);
    const __half* qlp = Ql + (((size_t)(b * NH + h) * TT + t0) << 7);
    const __half* khp = Kh + (((size_t)(b * NKV + kh) * TT) << 7);
    const __half* klp = Kl + (((size_t)(b * NKV + kh) * TT) << 7);
    const __half* vhp = Vv + (((size_t)(b * NKV + kh) * TT) << 7);

#pragma unroll
    for (int it = 0; it < 16; it++) {
        int i = tid + it * 256;
        int arr = i >> 11, ci = i & 2047;
        int r = ci >> 4, c = ci & 15;
        cpa16(sb + arr * 32768 + r * 256 + ((c ^ (r & 7)) * 16),
              (arr ? qlp : qhp) + r * HD + c * 8);
    }
    cp_commit();

    auto load_kv = [&](int stg, int s) {
        const uint32_t bs = sb + FSTG + stg * FSTGB;
        const __half* srcs[3] = {khp + (size_t)s * 64 * HD,
                                 klp + (size_t)s * 64 * HD,
                                 vhp + (size_t)s * 64 * HD};
#pragma unroll
        for (int it = 0; it < 12; it++) {
            int i = tid + it * 256;
            int arr = i >> 10, ci = i & 1023;
            int r = ci >> 4, c = ci & 15;
            cpa16(bs + arr * 16384 + r * 256 + ((c ^ (r & 7)) * 16),
                  srcs[arr] + r * HD + c * 8);
        }
    };
    load_kv(0, 0); cp_commit();
    load_kv(1, 1); cp_commit();

    float oa[16][4];
#pragma unroll
    for (int nt = 0; nt < 16; nt++)
#pragma unroll
        for (int c = 0; c < 4; c++) oa[nt][c] = 0.f;
    float m0 = -1e30f, m1 = -1e30f, l0 = 0.f, l1 = 0.f;
    const float scale = 0.08838834764831845f;

    const int qr = w * 16 + (lane & 15);
    const uint32_t qrow = sb + qr * 256;
    const int kr = (lane & 7) + ((lane >> 4) & 1) * 8;
    const int vr = lane & 15;

    for (int s = 0; s < NSTILE; s++) {
        if (s + 1 < NSTILE) cp_wait1(); else cp_wait0();
        __syncthreads();
        const uint32_t kb = sb + FSTG + (s & 1) * FSTGB;

        float sa[8][4];
#pragma unroll
        for (int j = 0; j < 8; j++)
#pragma unroll
            for (int c = 0; c < 4; c++) sa[j][c] = 0.f;

#pragma unroll
        for (int kc = 0; kc < 8; kc++) {
            uint32_t qa[4], qb[4];
            {
                int c = 2 * kc + (lane >> 4);
                uint32_t a = qrow + ((c ^ (qr & 7)) * 16);
                ldsm4(qa, a);
                ldsm4(qb, a + 32768);
            }
#pragma unroll
            for (int kt = 0; kt < 4; kt++) {
                uint32_t kfh[4], kfl[4];
                int krr = kt * 16 + kr;
                int kcc = 2 * kc + ((lane >> 3) & 1);
                uint32_t ka = kb + krr * 256 + ((kcc ^ (krr & 7)) * 16);
                ldsm4(kfh, ka);
                ldsm4(kfl, ka + 16384);
#pragma unroll
                for (int hn = 0; hn < 2; hn++) {
                    int j = kt * 2 + hn;
                    mma_f16(sa[j], qa, &kfh[hn * 2]);
                    mma_f16(sa[j], qa, &kfl[hn * 2]);
                    mma_f16(sa[j], qb, &kfh[hn * 2]);
                }
            }
        }

        float mx0 = -1e30f, mx1 = -1e30f;
#pragma unroll
        for (int j = 0; j < 8; j++) {
#pragma unroll
            for (int c = 0; c < 4; c++) sa[j][c] *= scale;
            mx0 = fmaxf(mx0, fmaxf(sa[j][0], sa[j][1]));
            mx1 = fmaxf(mx1, fmaxf(sa[j][2], sa[j][3]));
        }
#pragma unroll
        for (int off = 1; off <= 2; off <<= 1) {
            mx0 = fmaxf(mx0, __shfl_xor_sync(0xffffffffu, mx0, off));
            mx1 = fmaxf(mx1, __shfl_xor_sync(0xffffffffu, mx1, off));
        }
        float nm0 = fmaxf(m0, mx0), nm1 = fmaxf(m1, mx1);
        float al0 = __expf(m0 - nm0), al1 = __expf(m1 - nm1);
        float rs0 = 0.f, rs1 = 0.f;
#pragma unroll
        for (int j = 0; j < 8; j++) {
            sa[j][0] = __expf(sa[j][0] - nm0);
            sa[j][1] = __expf(sa[j][1] - nm0);
            sa[j][2] = __expf(sa[j][2] - nm1);
            sa[j][3] = __expf(sa[j][3] - nm1);
            rs0 += sa[j][0] + sa[j][1];
            rs1 += sa[j][2] + sa[j][3];
        }
#pragma unroll
        for (int off = 1; off <= 2; off <<= 1) {
            rs0 += __shfl_xor_sync(0xffffffffu, rs0, off);
            rs1 += __shfl_xor_sync(0xffffffffu, rs1, off);
        }
        l0 = l0 * al0 + rs0;  l1 = l1 * al1 + rs1;
        m0 = nm0;  m1 = nm1;
#pragma unroll
        for (int nt = 0; nt < 16; nt++) {
            oa[nt][0] *= al0; oa[nt][1] *= al0;
            oa[nt][2] *= al1; oa[nt][3] *= al1;
        }

#pragma unroll
        for (int kc2 = 0; kc2 < 4; kc2++) {
            uint32_t pa[4];
            pa[0] = pack_h2(sa[2 * kc2][0],     sa[2 * kc2][1]);
            pa[1] = pack_h2(sa[2 * kc2][2],     sa[2 * kc2][3]);
            pa[2] = pack_h2(sa[2 * kc2 + 1][0], sa[2 * kc2 + 1][1]);
            pa[3] = pack_h2(sa[2 * kc2 + 1][2], sa[2 * kc2 + 1][3]);
            int vrr = kc2 * 16 + vr;
            uint32_t vrow = kb + 32768 + vrr * 256;
#pragma unroll
            for (int nt2 = 0; nt2 < 8; nt2++) {
                uint32_t vf[4];
                int vc = nt2 * 2 + (lane >> 4);
                ldsm4t(vf, vrow + ((vc ^ (vrr & 7)) * 16));
                mma_f16(oa[nt2 * 2],     pa, &vf[0]);
                mma_f16(oa[nt2 * 2 + 1], pa, &vf[2]);
            }
        }

        __syncthreads();
        if (s + 2 < NSTILE) { load_kv(s & 1, s + 2); cp_commit(); }
    }

    float i0 = 1.f / l0, i1 = 1.f / l1;
    int rg0 = t0 + w * 16 + (lane >> 2);
    size_t row0 = (size_t)(b * TT + rg0) * DIM;
    size_t row1 = row0 + 8 * DIM;
#pragma unroll
    for (int nt = 0; nt < 16; nt++) {
        int col = h * HD + nt * 8 + (lane & 3) * 2;
        {
            float f0 = oa[nt][0] * i0, f1 = oa[nt][1] * i0;
            __half h0 = __float2half_rn(f0), h1 = __float2half_rn(f1);
            __half2 hv; hv.x = h0; hv.y = h1;
            *(uint32_t*)(Ch + row0 + col) = *(uint32_t*)&hv;
            __half2 lv;
            lv.x = __float2half_rn(f0 - __half2float(h0));
            lv.y = __float2half_rn(f1 - __half2float(h1));
            *(uint32_t*)(Cl + row0 + col) = *(uint32_t*)&lv;
        }
        {
            float f0 = oa[nt][2] * i1, f1 = oa[nt][3] * i1;
            __half h0 = __float2half_rn(f0), h1 = __float2half_rn(f1);
            __half2 hv; hv.x = h0; hv.y = h1;
            *(uint32_t*)(Ch + row1 + col) = *(uint32_t*)&hv;
            __half2 lv;
            lv.x = __float2half_rn(f0 - __half2float(h0));
            lv.y = __float2half_rn(f1 - __half2float(h1));
            *(uint32_t*)(Cl + row1 + col) = *(uint32_t*)&lv;
        }
    }
}

// ---------------------------------------------------------------------------
extern "C" void kernel_launch(void* const* d_in, const int* in_sizes, int n_in,
                              void* d_out, int out_size) {
    const float* x  = (const float*)d_in[0];
    const float* wq = (const float*)d_in[1];
    const float* wk = (const float*)d_in[2];
    const float* wv = (const float*)d_in[3];
    const float* wo = (const float*)d_in[4];
    const float* fc = (const float*)d_in[5];
    const float* fs = (const float*)d_in[6];
    float* out = (float*)d_out;

    __half *xh, *xl, *wqkv, *wop, *ch, *cl;
    cudaGetSymbolAddress((void**)&xh,   g_xh);
    cudaGetSymbolAddress((void**)&xl,   g_xl);
    cudaGetSymbolAddress((void**)&wqkv, g_wqkv);
    cudaGetSymbolAddress((void**)&wop,  g_wo);
    cudaGetSymbolAddress((void**)&ch,   g_ch);
    cudaGetSymbolAddress((void**)&cl,   g_cl);
    __half *fqh, *fql, *fkh, *fkl, *fv;
    cudaGetSymbolAddress((void**)&fqh, g_fqh); cudaGetSymbolAddress((void**)&fql, g_fql);
    cudaGetSymbolAddress((void**)&fkh, g_fkh); cudaGetSymbolAddress((void**)&fkl, g_fkl);
    cudaGetSymbolAddress((void**)&fv,  g_fv);

    // one-time side stream + events (identical launched work every call)
    static cudaStream_t s1 = []() {
        cudaStream_t s;
        cudaStreamCreateWithFlags(&s, cudaStreamNonBlocking);
        return s;
    }();
    static cudaEvent_t eq0 = []() { cudaEvent_t e; cudaEventCreateWithFlags(&e, cudaEventDisableTiming); return e; }();
    static cudaEvent_t eq1 = []() { cudaEvent_t e; cudaEventCreateWithFlags(&e, cudaEventDisableTiming); return e; }();
    static cudaEvent_t ef0 = []() { cudaEvent_t e; cudaEventCreateWithFlags(&e, cudaEventDisableTiming); return e; }();
    static cudaEvent_t ef1 = []() { cudaEvent_t e; cudaEventCreateWithFlags(&e, cudaEventDisableTiming); return e; }();

    static bool attrset = []() {
        cudaFuncSetAttribute(gemm_qkv_rope,
                             cudaFuncAttributeMaxDynamicSharedMemorySize, GEMM_SMEM);
        cudaFuncSetAttribute(gemm_f16x2,
                             cudaFuncAttributeMaxDynamicSharedMemorySize, GEMM_SMEM);
        cudaFuncSetAttribute(flash_hmma,
                             cudaFuncAttributeMaxDynamicSharedMemorySize, FSMEM);
        return true;
    }();
    (void)attrset;

    // prepack (legacy stream)
    prep_all<<<(TOTP4 + 255) / 256, 256>>>((const float4*)x, (const float4*)wq,
                                           (const float4*)wk, (const float4*)wv,
                                           (const float4*)wo);

    // qkv projection split by batch half (M rows): h0 = rows 0..2047
    gemm_qkv_rope<<<dim3(NQKV / 128, 16), 256, GEMM_SMEM>>>(xh, xl, wqkv, fc, fs, 0);
    cudaEventRecord(eq0, 0);
    gemm_qkv_rope<<<dim3(NQKV / 128, 16), 256, GEMM_SMEM>>>(xh, xl, wqkv, fc, fs, 16);
    cudaEventRecord(eq1, 0);

    // flash on side stream, per batch
    cudaStreamWaitEvent(s1, eq0, 0);
    flash_hmma<<<dim3(TT / 128, NH), 256, FSMEM, s1>>>(fqh, fql, fkh, fkl, fv, ch, cl, 0);
    cudaEventRecord(ef0, s1);
    cudaStreamWaitEvent(s1, eq1, 0);
    flash_hmma<<<dim3(TT / 128, NH), 256, FSMEM, s1>>>(fqh, fql, fkh, fkl, fv, ch, cl, 1);
    cudaEventRecord(ef1, s1);

    // output projection split by batch half, joined back on legacy stream
    cudaStreamWaitEvent(0, ef0, 0);
    gemm_f16x2<<<dim3(DIM / 128, 16), 256, GEMM_SMEM>>>(ch, cl, wop, out, DIM, 0);
    cudaStreamWaitEvent(0, ef1, 0);
    gemm_f16x2<<<dim3(DIM / 128, 16), 256, GEMM_SMEM>>>(ch, cl, wop, out, DIM, 16);
}

// round 11
// speedup vs baseline: 1.1120x; 1.1120x over previous
#include <cuda_runtime.h>
#include <cuda_bf16.h>
#include <cuda_fp16.h>
#include <math.h>
#include <stdint.h>

#define BB 2
#define TT 2048
#define DIM 4096
#define NH 32
#define NKV 8
#define HD 128
#define MTOK (BB * TT)
#define GK 4096
#define NKVD (NKV * HD)             // 1024
#define NQKV (DIM + 2 * NKVD)       // 6144

// ---------------- device scratch ---------------------------------------
__device__ __align__(16) __half g_xh[(size_t)MTOK * DIM];
__device__ __align__(16) __half g_xl[(size_t)MTOK * DIM];
__device__ __align__(16) __half g_wqkv[(size_t)NQKV * GK];
__device__ __align__(16) __half g_wo[(size_t)DIM * DIM];
__device__ __align__(16) __half g_ch[(size_t)MTOK * DIM];
__device__ __align__(16) __half g_cl[(size_t)MTOK * DIM];

// head-major fp16 q (hi/lo), k (single), v (single) for flash
__device__ __align__(16) __half g_fqh[(size_t)BB * NH * TT * HD];
__device__ __align__(16) __half g_fql[(size_t)BB * NH * TT * HD];
__device__ __align__(16) __half g_fkh[(size_t)BB * NKV * TT * HD];
__device__ __align__(16) __half g_fv [(size_t)BB * NKV * TT * HD];

// ---------------- helpers ----------------------------------------------
__device__ __forceinline__ uint32_t smem_u32(const void* p) {
    uint32_t a;
    asm("{ .reg .u64 t; cvta.to.shared.u64 t, %1; cvt.u32.u64 %0, t; }"
        : "=r"(a) : "l"(p));
    return a;
}
__device__ __forceinline__ void cpa16(uint32_t dst, const void* src) {
    asm volatile("cp.async.cg.shared.global [%0], [%1], 16;"
                 :: "r"(dst), "l"(src) : "memory");
}
__device__ __forceinline__ void cp_commit() {
    asm volatile("cp.async.commit_group;" ::: "memory");
}
__device__ __forceinline__ void cp_wait1() {
    asm volatile("cp.async.wait_group 1;" ::: "memory");
}
__device__ __forceinline__ void cp_wait0() {
    asm volatile("cp.async.wait_group 0;" ::: "memory");
}
__device__ __forceinline__ void ldsm4(uint32_t* r, uint32_t addr) {
    asm volatile("ldmatrix.sync.aligned.m8n8.x4.shared.b16 {%0,%1,%2,%3}, [%4];"
                 : "=r"(r[0]), "=r"(r[1]), "=r"(r[2]), "=r"(r[3]) : "r"(addr));
}
__device__ __forceinline__ void ldsm4t(uint32_t* r, uint32_t addr) {
    asm volatile("ldmatrix.sync.aligned.m8n8.x4.trans.shared.b16 {%0,%1,%2,%3}, [%4];"
                 : "=r"(r[0]), "=r"(r[1]), "=r"(r[2]), "=r"(r[3]) : "r"(addr));
}
__device__ __forceinline__ void mma_f16(float* d, const uint32_t* a, const uint32_t* b) {
    asm volatile(
        "mma.sync.aligned.m16n8k16.row.col.f32.f16.f16.f32 "
        "{%0,%1,%2,%3}, {%4,%5,%6,%7}, {%8,%9}, {%0,%1,%2,%3};\n"
        : "+f"(d[0]), "+f"(d[1]), "+f"(d[2]), "+f"(d[3])
        : "r"(a[0]), "r"(a[1]), "r"(a[2]), "r"(a[3]), "r"(b[0]), "r"(b[1]));
}
__device__ __forceinline__ uint32_t pack_h2(float lo, float hi) {
    __half2 h = __floats2half2_rn(lo, hi);
    return *(uint32_t*)&h;
}

// ---------------- fused prepack (vectorized, 4 elems/thread) -------------
#define NX  (MTOK * DIM)        // 16777216
#define NWQ (DIM * GK)          // 16777216
#define NWK (NKVD * GK)         // 4194304
#define TOTP4 ((NX + NWQ + 2 * NWK + NWQ) / 4)   // 14680064
__global__ void prep_all(const float4* __restrict__ x,
                         const float4* __restrict__ wq,
                         const float4* __restrict__ wk,
                         const float4* __restrict__ wv,
                         const float4* __restrict__ wo) {
    int i = blockIdx.x * blockDim.x + threadIdx.x;
    if (i >= TOTP4) return;
    if (i < NX / 4) {
        float4 v = x[i];
        __half2 h01 = __floats2half2_rn(v.x, v.y);
        __half2 h23 = __floats2half2_rn(v.z, v.w);
        __half2 l01 = __floats2half2_rn(v.x - __half2float(h01.x),
                                        v.y - __half2float(h01.y));
        __half2 l23 = __floats2half2_rn(v.z - __half2float(h23.x),
                                        v.w - __half2float(h23.y));
        uint2 hp; hp.x = *(uint32_t*)&h01; hp.y = *(uint32_t*)&h23;
        uint2 lp; lp.x = *(uint32_t*)&l01; lp.y = *(uint32_t*)&l23;
        *(uint2*)(g_xh + (size_t)i * 4) = hp;
        *(uint2*)(g_xl + (size_t)i * 4) = lp;
    } else {
        const float4* src;
        __half* dst;
        size_t j;
        if (i < (NX + NWQ) / 4) {
            j = i - NX / 4; src = wq; dst = g_wqkv;
        } else if (i < (NX + NWQ + NWK) / 4) {
            j = i - (NX + NWQ) / 4; src = wk; dst = g_wqkv + (size_t)DIM * GK;
        } else if (i < (NX + NWQ + 2 * NWK) / 4) {
            j = i - (NX + NWQ + NWK) / 4; src = wv;
            dst = g_wqkv + (size_t)(DIM + NKVD) * GK;
        } else {
            j = i - (NX + NWQ + 2 * NWK) / 4; src = wo; dst = g_wo;
        }
        float4 v = src[j];
        __half2 h01 = __floats2half2_rn(v.x, v.y);
        __half2 h23 = __floats2half2_rn(v.z, v.w);
        uint2 hp; hp.x = *(uint32_t*)&h01; hp.y = *(uint32_t*)&h23;
        *(uint2*)(dst + j * 4) = hp;
    }
}

// ---------------- HMMA fp16x2 GEMM mainloop (warp tile 32x64) ------------
#define BKC 64
#define ROWB 144
#define MAT_BYTES (128 * ROWB)         // 18432
#define STAGE_BYTES (3 * MAT_BYTES)    // 55296
#define GNC (GK / BKC)                 // 64
#define GEMM_SMEM (2 * STAGE_BYTES)    // 110592

// warp layout: 4 (m) x 2 (n); warp tile 32x64; accum d[2][8][4]
#define GEMM_MAINLOOP(Ah, Al, Bh)                                              \
    extern __shared__ char sm[];                                               \
    const uint32_t sbase = smem_u32(sm);                                       \
    const int tid  = threadIdx.x;                                              \
    const int lane = tid & 31;                                                 \
    const int wid  = tid >> 5;                                                 \
    const int wm   = wid & 3;                                                  \
    const int wn   = wid >> 2;                                                 \
    const int bm   = blockIdx.y * 128;                                         \
    const int bn   = blockIdx.x * 128;                                         \
    const __half* mats[3] = {Ah, Al, Bh};                                      \
    float d[2][8][4];                                                          \
    _Pragma("unroll")                                                          \
    for (int i = 0; i < 2; i++)                                                \
        _Pragma("unroll")                                                      \
        for (int j = 0; j < 8; j++)                                            \
            _Pragma("unroll")                                                  \
            for (int r = 0; r < 4; r++) d[i][j][r] = 0.f;                      \
    auto load_chunk = [&](int buf, int c) {                                    \
        const int kofs = c * BKC;                                              \
        const uint32_t base = sbase + buf * STAGE_BYTES;                       \
        _Pragma("unroll")                                                      \
        for (int t = 0; t < 12; t++) {                                         \
            int i   = tid + t * 256;                                           \
            int mat = i >> 10;                                                 \
            int idx = i & 1023;                                                \
            int row = idx >> 3;                                                \
            int ch  = idx & 7;                                                 \
            int grow = ((mat < 2) ? bm : bn) + row;                            \
            cpa16(base + mat * MAT_BYTES + row * ROWB + ch * 16,               \
                  mats[mat] + (size_t)grow * GK + kofs + ch * 8);              \
        }                                                                      \
    };                                                                         \
    load_chunk(0, 0); cp_commit();                                             \
    const uint32_t a_off =                                                     \
        (uint32_t)((wm * 32 + (lane & 15)) * ROWB + (lane >> 4) * 16);         \
    const uint32_t b_off = (uint32_t)(2 * MAT_BYTES +                          \
        (wn * 64 + (lane & 7) + ((lane >> 4) & 1) * 8) * ROWB +                \
        ((lane >> 3) & 1) * 16);                                               \
    for (int c = 0; c < GNC; ++c) {                                            \
        const int b = c & 1;                                                   \
        if (c + 1 < GNC) {                                                     \
            load_chunk(b ^ 1, c + 1);                                          \
            cp_commit();                                                       \
            cp_wait1();                                                        \
        } else {                                                               \
            cp_wait0();                                                        \
        }                                                                      \
        __syncthreads();                                                       \
        const uint32_t stg = sbase + b * STAGE_BYTES;                          \
        _Pragma("unroll")                                                      \
        for (int ks = 0; ks < 4; ks++) {                                       \
            uint32_t ah[2][4], al[2][4], bh[4][4];                             \
            _Pragma("unroll")                                                  \
            for (int i = 0; i < 2; i++)                                        \
                ldsm4(ah[i], stg + a_off + i * (16 * ROWB) + ks * 32);         \
            _Pragma("unroll")                                                  \
            for (int i = 0; i < 2; i++)                                        \
                ldsm4(al[i], stg + MAT_BYTES + a_off + i * (16 * ROWB) + ks * 32); \
            _Pragma("unroll")                                                  \
            for (int jj = 0; jj < 4; jj++)                                     \
                ldsm4(bh[jj], stg + b_off + jj * (16 * ROWB) + ks * 32);       \
            _Pragma("unroll")                                                  \
            for (int i = 0; i < 2; i++)                                        \
                _Pragma("unroll")                                              \
                for (int j = 0; j < 8; j++) {                                  \
                    const uint32_t* ph = &bh[j >> 1][(j & 1) * 2];             \
                    mma_f16(d[i][j], ah[i], ph);                               \
                    mma_f16(d[i][j], al[i], ph);                               \
                }                                                              \
        }                                                                      \
        __syncthreads();                                                       \
    }

// ---- GEMM 1: qkv projection with fused RoPE + fp16 pack ----------------
__global__ __launch_bounds__(256, 2)
void gemm_qkv_rope(const __half* __restrict__ Ah,
                   const __half* __restrict__ Al,
                   const __half* __restrict__ Bh,
                   const float* __restrict__ fc,
                   const float* __restrict__ fs) {
    GEMM_MAINLOOP(Ah, Al, Bh)

    const int r0 = bm + wm * 32 + (lane >> 2);
    const int c0 = bn + wn * 64 + (lane & 3) * 2;

    auto store_pair = [&](int row, int col, float v0, float v1) {
        int b = row >> 11, t = row & 2047;
        if (col < DIM) {                       // q: rope, hi/lo
            int hh = col >> 7, dp = (col & 127) >> 1;
            float c = fc[t * 64 + dp], s = fs[t * 64 + dp];
            float o0 = v0 * c - v1 * s;
            float o1 = v0 * s + v1 * c;
            size_t dst = (((size_t)(b * NH + hh) * TT + t) << 7) + 2 * dp;
            __half h0 = __float2half_rn(o0), h1 = __float2half_rn(o1);
            __half2 hv; hv.x = h0; hv.y = h1;
            *(uint32_t*)(g_fqh + dst) = *(uint32_t*)&hv;
            __half2 lv;
            lv.x = __float2half_rn(o0 - __half2float(h0));
            lv.y = __float2half_rn(o1 - __half2float(h1));
            *(uint32_t*)(g_fql + dst) = *(uint32_t*)&lv;
        } else if (col < DIM + NKVD) {         // k: rope, single fp16
            int cc = col - DIM;
            int hh = cc >> 7, dp = (cc & 127) >> 1;
            float c = fc[t * 64 + dp], s = fs[t * 64 + dp];
            float o0 = v0 * c - v1 * s;
            float o1 = v0 * s + v1 * c;
            size_t dst = (((size_t)(b * NKV + hh) * TT + t) << 7) + 2 * dp;
            __half2 hv; hv.x = __float2half_rn(o0); hv.y = __float2half_rn(o1);
            *(uint32_t*)(g_fkh + dst) = *(uint32_t*)&hv;
        } else {                               // v: plain fp16
            int cc = col - DIM - NKVD;
            int hh = cc >> 7, dd = cc & 127;
            size_t dst = (((size_t)(b * NKV + hh) * TT + t) << 7) + dd;
            __half2 hv; hv.x = __float2half_rn(v0); hv.y = __float2half_rn(v1);
            *(uint32_t*)(g_fv + dst) = *(uint32_t*)&hv;
        }
    };

#pragma unroll
    for (int i = 0; i < 2; i++)
#pragma unroll
        for (int j = 0; j < 8; j++) {
            int col = c0 + j * 8;
            store_pair(r0 + i * 16,     col, d[i][j][0], d[i][j][1]);
            store_pair(r0 + i * 16 + 8, col, d[i][j][2], d[i][j][3]);
        }
}

// ---- GEMM 2: output projection, fp32 C --------------------------------
__global__ __launch_bounds__(256, 2)
void gemm_f16x2(const __half* __restrict__ Ah,
                const __half* __restrict__ Al,
                const __half* __restrict__ Bh,
                float* __restrict__ C, int N) {
    GEMM_MAINLOOP(Ah, Al, Bh)

    const int r0 = bm + wm * 32 + (lane >> 2);
    const int c0 = bn + wn * 64 + (lane & 3) * 2;
#pragma unroll
    for (int i = 0; i < 2; i++)
#pragma unroll
        for (int j = 0; j < 8; j++) {
            int row = r0 + i * 16;
            int col = c0 + j * 8;
            *(float2*)&C[(size_t)row * N + col] =
                make_float2(d[i][j][0], d[i][j][1]);
            *(float2*)&C[(size_t)(row + 8) * N + col] =
                make_float2(d[i][j][2], d[i][j][3]);
        }
}

// ---------------- flash attention: fp16 HMMA, 2-pass QK -----------------
// smem: Qh [0,32K) Ql [32K,64K); stage s at 64K + s*32K: Kh 16K | V 16K
#define FSTG 65536
#define FSTGB 32768
#define FSMEM (FSTG + 2 * FSTGB)        // 131072
#define NSTILE (TT / 64)                // 32

__global__ __launch_bounds__(256, 1)
void flash_hmma(const __half* __restrict__ Qh, const __half* __restrict__ Ql,
                const __half* __restrict__ Kh, const __half* __restrict__ Vv,
                __half* __restrict__ Ch, __half* __restrict__ Cl) {
    extern __shared__ char sm[];
    const uint32_t sb = smem_u32(sm);
    const int tid = threadIdx.x, lane = tid & 31, w = tid >> 5;
    const int t0 = blockIdx.x * 128;
    const int h  = blockIdx.y;
    const int b  = blockIdx.z;
    const int kh = h & 7;

    const __half* qhp = Qh + (((size_t)(b * NH + h) * TT + t0) << 7);
    const __half* qlp = Ql + (((size_t)(b * NH + h) * TT + t0) << 7);
    const __half* khp = Kh + (((size_t)(b * NKV + kh) * TT) << 7);
    const __half* vhp = Vv + (((size_t)(b * NKV + kh) * TT) << 7);

    // Q tile hi/lo: 128 rows x 16 chunks x 2 arrays = 4096 16B chunks
#pragma unroll
    for (int it = 0; it < 16; it++) {
        int i = tid + it * 256;
        int arr = i >> 11, ci = i & 2047;
        int r = ci >> 4, c = ci & 15;
        cpa16(sb + arr * 32768 + r * 256 + ((c ^ (r & 7)) * 16),
              (arr ? qlp : qhp) + r * HD + c * 8);
    }
    cp_commit();

    auto load_kv = [&](int stg, int s) {
        const uint32_t bs = sb + FSTG + stg * FSTGB;
        const __half* srcs[2] = {khp + (size_t)s * 64 * HD,
                                 vhp + (size_t)s * 64 * HD};
#pragma unroll
        for (int it = 0; it < 8; it++) {
            int i = tid + it * 256;
            int arr = i >> 10, ci = i & 1023;
            int r = ci >> 4, c = ci & 15;
            cpa16(bs + arr * 16384 + r * 256 + ((c ^ (r & 7)) * 16),
                  srcs[arr] + r * HD + c * 8);
        }
    };
    load_kv(0, 0); cp_commit();
    load_kv(1, 1); cp_commit();

    float oa[16][4];
#pragma unroll
    for (int nt = 0; nt < 16; nt++)
#pragma unroll
        for (int c = 0; c < 4; c++) oa[nt][c] = 0.f;
    float m0 = -1e30f, m1 = -1e30f, l0 = 0.f, l1 = 0.f;
    const float scale = 0.08838834764831845f;

    const int qr = w * 16 + (lane & 15);
    const uint32_t qrow = sb + qr * 256;
    const int kr = (lane & 7) + ((lane >> 4) & 1) * 8;
    const int vr = lane & 15;

    for (int s = 0; s < NSTILE; s++) {
        if (s + 1 < NSTILE) cp_wait1(); else cp_wait0();
        __syncthreads();
        const uint32_t kb = sb + FSTG + (s & 1) * FSTGB;

        // ---- S = Q K^T (2-pass: qh*kh + ql*kh) ----
        float sa[8][4];
#pragma unroll
        for (int j = 0; j < 8; j++)
#pragma unroll
            for (int c = 0; c < 4; c++) sa[j][c] = 0.f;

#pragma unroll
        for (int kc = 0; kc < 8; kc++) {
            uint32_t qa[4], qb[4];
            {
                int c = 2 * kc + (lane >> 4);
                uint32_t a = qrow + ((c ^ (qr & 7)) * 16);
                ldsm4(qa, a);
                ldsm4(qb, a + 32768);
            }
#pragma unroll
            for (int kt = 0; kt < 4; kt++) {
                uint32_t kfh[4];
                int krr = kt * 16 + kr;
                int kcc = 2 * kc + ((lane >> 3) & 1);
                uint32_t ka = kb + krr * 256 + ((kcc ^ (krr & 7)) * 16);
                ldsm4(kfh, ka);
#pragma unroll
                for (int hn = 0; hn < 2; hn++) {
                    int j = kt * 2 + hn;
                    mma_f16(sa[j], qa, &kfh[hn * 2]);
                    mma_f16(sa[j], qb, &kfh[hn * 2]);
                }
            }
        }

        // ---- online softmax (registers) ----
        float mx0 = -1e30f, mx1 = -1e30f;
#pragma unroll
        for (int j = 0; j < 8; j++) {
#pragma unroll
            for (int c = 0; c < 4; c++) sa[j][c] *= scale;
            mx0 = fmaxf(mx0, fmaxf(sa[j][0], sa[j][1]));
            mx1 = fmaxf(mx1, fmaxf(sa[j][2], sa[j][3]));
        }
#pragma unroll
        for (int off = 1; off <= 2; off <<= 1) {
            mx0 = fmaxf(mx0, __shfl_xor_sync(0xffffffffu, mx0, off));
            mx1 = fmaxf(mx1, __shfl_xor_sync(0xffffffffu, mx1, off));
        }
        float nm0 = fmaxf(m0, mx0), nm1 = fmaxf(m1, mx1);
        float al0 = __expf(m0 - nm0), al1 = __expf(m1 - nm1);
        float rs0 = 0.f, rs1 = 0.f;
#pragma unroll
        for (int j = 0; j < 8; j++) {
            sa[j][0] = __expf(sa[j][0] - nm0);
            sa[j][1] = __expf(sa[j][1] - nm0);
            sa[j][2] = __expf(sa[j][2] - nm1);
            sa[j][3] = __expf(sa[j][3] - nm1);
            rs0 += sa[j][0] + sa[j][1];
            rs1 += sa[j][2] + sa[j][3];
        }
#pragma unroll
        for (int off = 1; off <= 2; off <<= 1) {
            rs0 += __shfl_xor_sync(0xffffffffu, rs0, off);
            rs1 += __shfl_xor_sync(0xffffffffu, rs1, off);
        }
        l0 = l0 * al0 + rs0;  l1 = l1 * al1 + rs1;
        m0 = nm0;  m1 = nm1;
#pragma unroll
        for (int nt = 0; nt < 16; nt++) {
            oa[nt][0] *= al0; oa[nt][1] *= al0;
            oa[nt][2] *= al1; oa[nt][3] *= al1;
        }

        // ---- O += P V ----
#pragma unroll
        for (int kc2 = 0; kc2 < 4; kc2++) {
            uint32_t pa[4];
            pa[0] = pack_h2(sa[2 * kc2][0],     sa[2 * kc2][1]);
            pa[1] = pack_h2(sa[2 * kc2][2],     sa[2 * kc2][3]);
            pa[2] = pack_h2(sa[2 * kc2 + 1][0], sa[2 * kc2 + 1][1]);
            pa[3] = pack_h2(sa[2 * kc2 + 1][2], sa[2 * kc2 + 1][3]);
            int vrr = kc2 * 16 + vr;
            uint32_t vrow = kb + 16384 + vrr * 256;
#pragma unroll
            for (int nt2 = 0; nt2 < 8; nt2++) {
                uint32_t vf[4];
                int vc = nt2 * 2 + (lane >> 4);
                ldsm4t(vf, vrow + ((vc ^ (vrr & 7)) * 16));
                mma_f16(oa[nt2 * 2],     pa, &vf[0]);
                mma_f16(oa[nt2 * 2 + 1], pa, &vf[2]);
            }
        }

        __syncthreads();
        if (s + 2 < NSTILE) { load_kv(s & 1, s + 2); cp_commit(); }
    }

    // ---- epilogue: normalize, split fp16 hi/lo, store ctx --------------
    float i0 = 1.f / l0, i1 = 1.f / l1;
    int rg0 = t0 + w * 16 + (lane >> 2);
    size_t row0 = (size_t)(b * TT + rg0) * DIM;
    size_t row1 = row0 + 8 * DIM;
#pragma unroll
    for (int nt = 0; nt < 16; nt++) {
        int col = h * HD + nt * 8 + (lane & 3) * 2;
        {
            float f0 = oa[nt][0] * i0, f1 = oa[nt][1] * i0;
            __half h0 = __float2half_rn(f0), h1 = __float2half_rn(f1);
            __half2 hv; hv.x = h0; hv.y = h1;
            *(uint32_t*)(Ch + row0 + col) = *(uint32_t*)&hv;
            __half2 lv;
            lv.x = __float2half_rn(f0 - __half2float(h0));
            lv.y = __float2half_rn(f1 - __half2float(h1));
            *(uint32_t*)(Cl + row0 + col) = *(uint32_t*)&lv;
        }
        {
            float f0 = oa[nt][2] * i1, f1 = oa[nt][3] * i1;
            __half h0 = __float2half_rn(f0), h1 = __float2half_rn(f1);
            __half2 hv; hv.x = h0; hv.y = h1;
            *(uint32_t*)(Ch + row1 + col) = *(uint32_t*)&hv;
            __half2 lv;
            lv.x = __float2half_rn(f0 - __half2float(h0));
            lv.y = __float2half_rn(f1 - __half2float(h1));
            *(uint32_t*)(Cl + row1 + col) = *(uint32_t*)&lv;
        }
    }
}

// ---------------------------------------------------------------------------
extern "C" void kernel_launch(void* const* d_in, const int* in_sizes, int n_in,
                              void* d_out, int out_size) {
    const float* x  = (const float*)d_in[0];
    const float* wq = (const float*)d_in[1];
    const float* wk = (const float*)d_in[2];
    const float* wv = (const float*)d_in[3];
    const float* wo = (const float*)d_in[4];
    const float* fc = (const float*)d_in[5];
    const float* fs = (const float*)d_in[6];
    float* out = (float*)d_out;

    __half *xh, *xl, *wqkv, *wop, *ch, *cl;
    cudaGetSymbolAddress((void**)&xh,   g_xh);
    cudaGetSymbolAddress((void**)&xl,   g_xl);
    cudaGetSymbolAddress((void**)&wqkv, g_wqkv);
    cudaGetSymbolAddress((void**)&wop,  g_wo);
    cudaGetSymbolAddress((void**)&ch,   g_ch);
    cudaGetSymbolAddress((void**)&cl,   g_cl);
    __half *fqh, *fql, *fkh, *fv;
    cudaGetSymbolAddress((void**)&fqh, g_fqh); cudaGetSymbolAddress((void**)&fql, g_fql);
    cudaGetSymbolAddress((void**)&fkh, g_fkh);
    cudaGetSymbolAddress((void**)&fv,  g_fv);

    // fused, vectorized prepack (1 launch)
    prep_all<<<(TOTP4 + 255) / 256, 256>>>((const float4*)x, (const float4*)wq,
                                           (const float4*)wk, (const float4*)wv,
                                           (const float4*)wo);

    cudaFuncSetAttribute(gemm_qkv_rope,
                         cudaFuncAttributeMaxDynamicSharedMemorySize, GEMM_SMEM);
    cudaFuncSetAttribute(gemm_f16x2,
                         cudaFuncAttributeMaxDynamicSharedMemorySize, GEMM_SMEM);

    // qkv projection + fused rope + head-major fp16 pack
    gemm_qkv_rope<<<dim3(NQKV / 128, MTOK / 128), 256, GEMM_SMEM>>>(xh, xl, wqkv, fc, fs);

    cudaFuncSetAttribute(flash_hmma,
                         cudaFuncAttributeMaxDynamicSharedMemorySize, FSMEM);
    flash_hmma<<<dim3(TT / 128, NH, BB), 256, FSMEM>>>(fqh, fql, fkh, fv, ch, cl);

    // output projection
    gemm_f16x2<<<dim3(DIM / 128, MTOK / 128), 256, GEMM_SMEM>>>(ch, cl, wop, out, DIM);
}

// round 12
// speedup vs baseline: 1.2761x; 1.1476x over previous
#include <cuda_runtime.h>
#include <cuda_bf16.h>
#include <cuda_fp16.h>
#include <math.h>
#include <stdint.h>

#define BB 2
#define TT 2048
#define DIM 4096
#define NH 32
#define NKV 8
#define HD 128
#define MTOK (BB * TT)
#define GK 4096
#define NKVD (NKV * HD)             // 1024
#define NQKV (DIM + 2 * NKVD)       // 6144

// ---------------- device scratch ---------------------------------------
__device__ __align__(16) __half g_xh[(size_t)MTOK * DIM];
__device__ __align__(16) __half g_xl[(size_t)MTOK * DIM];
__device__ __align__(16) __half g_wqkv[(size_t)NQKV * GK];
__device__ __align__(16) __half g_wo[(size_t)DIM * DIM];
__device__ __align__(16) __half g_ch[(size_t)MTOK * DIM];

// head-major fp16 q (hi/lo), k (single), v (single) for flash
__device__ __align__(16) __half g_fqh[(size_t)BB * NH * TT * HD];
__device__ __align__(16) __half g_fql[(size_t)BB * NH * TT * HD];
__device__ __align__(16) __half g_fkh[(size_t)BB * NKV * TT * HD];
__device__ __align__(16) __half g_fv [(size_t)BB * NKV * TT * HD];

// ---------------- helpers ----------------------------------------------
__device__ __forceinline__ uint32_t smem_u32(const void* p) {
    uint32_t a;
    asm("{ .reg .u64 t; cvta.to.shared.u64 t, %1; cvt.u32.u64 %0, t; }"
        : "=r"(a) : "l"(p));
    return a;
}
__device__ __forceinline__ void cpa16(uint32_t dst, const void* src) {
    asm volatile("cp.async.cg.shared.global [%0], [%1], 16;"
                 :: "r"(dst), "l"(src) : "memory");
}
__device__ __forceinline__ void cp_commit() {
    asm volatile("cp.async.commit_group;" ::: "memory");
}
__device__ __forceinline__ void cp_wait1() {
    asm volatile("cp.async.wait_group 1;" ::: "memory");
}
__device__ __forceinline__ void cp_wait0() {
    asm volatile("cp.async.wait_group 0;" ::: "memory");
}
__device__ __forceinline__ void ldsm4(uint32_t* r, uint32_t addr) {
    asm volatile("ldmatrix.sync.aligned.m8n8.x4.shared.b16 {%0,%1,%2,%3}, [%4];"
                 : "=r"(r[0]), "=r"(r[1]), "=r"(r[2]), "=r"(r[3]) : "r"(addr));
}
__device__ __forceinline__ void ldsm4t(uint32_t* r, uint32_t addr) {
    asm volatile("ldmatrix.sync.aligned.m8n8.x4.trans.shared.b16 {%0,%1,%2,%3}, [%4];"
                 : "=r"(r[0]), "=r"(r[1]), "=r"(r[2]), "=r"(r[3]) : "r"(addr));
}
__device__ __forceinline__ void mma_f16(float* d, const uint32_t* a, const uint32_t* b) {
    asm volatile(
        "mma.sync.aligned.m16n8k16.row.col.f32.f16.f16.f32 "
        "{%0,%1,%2,%3}, {%4,%5,%6,%7}, {%8,%9}, {%0,%1,%2,%3};\n"
        : "+f"(d[0]), "+f"(d[1]), "+f"(d[2]), "+f"(d[3])
        : "r"(a[0]), "r"(a[1]), "r"(a[2]), "r"(a[3]), "r"(b[0]), "r"(b[1]));
}
__device__ __forceinline__ uint32_t pack_h2(float lo, float hi) {
    __half2 h = __floats2half2_rn(lo, hi);
    return *(uint32_t*)&h;
}

// ---------------- fused prepack (vectorized, 4 elems/thread) -------------
#define NX  (MTOK * DIM)        // 16777216
#define NWQ (DIM * GK)          // 16777216
#define NWK (NKVD * GK)         // 4194304
#define TOTP4 ((NX + NWQ + 2 * NWK + NWQ) / 4)   // 14680064
__global__ void prep_all(const float4* __restrict__ x,
                         const float4* __restrict__ wq,
                         const float4* __restrict__ wk,
                         const float4* __restrict__ wv,
                         const float4* __restrict__ wo) {
    int i = blockIdx.x * blockDim.x + threadIdx.x;
    if (i >= TOTP4) return;
    if (i < NX / 4) {
        float4 v = x[i];
        __half2 h01 = __floats2half2_rn(v.x, v.y);
        __half2 h23 = __floats2half2_rn(v.z, v.w);
        __half2 l01 = __floats2half2_rn(v.x - __half2float(h01.x),
                                        v.y - __half2float(h01.y));
        __half2 l23 = __floats2half2_rn(v.z - __half2float(h23.x),
                                        v.w - __half2float(h23.y));
        uint2 hp; hp.x = *(uint32_t*)&h01; hp.y = *(uint32_t*)&h23;
        uint2 lp; lp.x = *(uint32_t*)&l01; lp.y = *(uint32_t*)&l23;
        *(uint2*)(g_xh + (size_t)i * 4) = hp;
        *(uint2*)(g_xl + (size_t)i * 4) = lp;
    } else {
        const float4* src;
        __half* dst;
        size_t j;
        if (i < (NX + NWQ) / 4) {
            j = i - NX / 4; src = wq; dst = g_wqkv;
        } else if (i < (NX + NWQ + NWK) / 4) {
            j = i - (NX + NWQ) / 4; src = wk; dst = g_wqkv + (size_t)DIM * GK;
        } else if (i < (NX + NWQ + 2 * NWK) / 4) {
            j = i - (NX + NWQ + NWK) / 4; src = wv;
            dst = g_wqkv + (size_t)(DIM + NKVD) * GK;
        } else {
            j = i - (NX + NWQ + 2 * NWK) / 4; src = wo; dst = g_wo;
        }
        float4 v = src[j];
        __half2 h01 = __floats2half2_rn(v.x, v.y);
        __half2 h23 = __floats2half2_rn(v.z, v.w);
        uint2 hp; hp.x = *(uint32_t*)&h01; hp.y = *(uint32_t*)&h23;
        *(uint2*)(dst + j * 4) = hp;
    }
}

// ---------------- HMMA fp16x2 GEMM mainloop (warp tile 32x64) ------------
#define BKC 64
#define ROWB 144
#define MAT_BYTES (128 * ROWB)         // 18432
#define STAGE_BYTES (3 * MAT_BYTES)    // 55296
#define GNC (GK / BKC)                 // 64
#define GEMM_SMEM (2 * STAGE_BYTES)    // 110592

// warp layout: 4 (m) x 2 (n); warp tile 32x64; accum d[2][8][4]
#define GEMM_MAINLOOP(Ah, Al, Bh)                                              \
    extern __shared__ char sm[];                                               \
    const uint32_t sbase = smem_u32(sm);                                       \
    const int tid  = threadIdx.x;                                              \
    const int lane = tid & 31;                                                 \
    const int wid  = tid >> 5;                                                 \
    const int wm   = wid & 3;                                                  \
    const int wn   = wid >> 2;                                                 \
    const int bm   = blockIdx.y * 128;                                         \
    const int bn   = blockIdx.x * 128;                                         \
    const __half* mats[3] = {Ah, Al, Bh};                                      \
    float d[2][8][4];                                                          \
    _Pragma("unroll")                                                          \
    for (int i = 0; i < 2; i++)                                                \
        _Pragma("unroll")                                                      \
        for (int j = 0; j < 8; j++)                                            \
            _Pragma("unroll")                                                  \
            for (int r = 0; r < 4; r++) d[i][j][r] = 0.f;                      \
    auto load_chunk = [&](int buf, int c) {                                    \
        const int kofs = c * BKC;                                              \
        const uint32_t base = sbase + buf * STAGE_BYTES;                       \
        _Pragma("unroll")                                                      \
        for (int t = 0; t < 12; t++) {                                         \
            int i   = tid + t * 256;                                           \
            int mat = i >> 10;                                                 \
            int idx = i & 1023;                                                \
            int row = idx >> 3;                                                \
            int ch  = idx & 7;                                                 \
            int grow = ((mat < 2) ? bm : bn) + row;                            \
            cpa16(base + mat * MAT_BYTES + row * ROWB + ch * 16,               \
                  mats[mat] + (size_t)grow * GK + kofs + ch * 8);              \
        }                                                                      \
    };                                                                         \
    load_chunk(0, 0); cp_commit();                                             \
    const uint32_t a_off =                                                     \
        (uint32_t)((wm * 32 + (lane & 15)) * ROWB + (lane >> 4) * 16);         \
    const uint32_t b_off = (uint32_t)(2 * MAT_BYTES +                          \
        (wn * 64 + (lane & 7) + ((lane >> 4) & 1) * 8) * ROWB +                \
        ((lane >> 3) & 1) * 16);                                               \
    for (int c = 0; c < GNC; ++c) {                                            \
        const int b = c & 1;                                                   \
        if (c + 1 < GNC) {                                                     \
            load_chunk(b ^ 1, c + 1);                                          \
            cp_commit();                                                       \
            cp_wait1();                                                        \
        } else {                                                               \
            cp_wait0();                                                        \
        }                                                                      \
        __syncthreads();                                                       \
        const uint32_t stg = sbase + b * STAGE_BYTES;                          \
        _Pragma("unroll")                                                      \
        for (int ks = 0; ks < 4; ks++) {                                       \
            uint32_t ah[2][4], al[2][4], bh[4][4];                             \
            _Pragma("unroll")                                                  \
            for (int i = 0; i < 2; i++)                                        \
                ldsm4(ah[i], stg + a_off + i * (16 * ROWB) + ks * 32);         \
            _Pragma("unroll")                                                  \
            for (int i = 0; i < 2; i++)                                        \
                ldsm4(al[i], stg + MAT_BYTES + a_off + i * (16 * ROWB) + ks * 32); \
            _Pragma("unroll")                                                  \
            for (int jj = 0; jj < 4; jj++)                                     \
                ldsm4(bh[jj], stg + b_off + jj * (16 * ROWB) + ks * 32);       \
            _Pragma("unroll")                                                  \
            for (int i = 0; i < 2; i++)                                        \
                _Pragma("unroll")                                              \
                for (int j = 0; j < 8; j++) {                                  \
                    const uint32_t* ph = &bh[j >> 1][(j & 1) * 2];             \
                    mma_f16(d[i][j], ah[i], ph);                               \
                    mma_f16(d[i][j], al[i], ph);                               \
                }                                                              \
        }                                                                      \
        __syncthreads();                                                       \
    }

// ---- GEMM 1: qkv projection with fused RoPE + fp16 pack ----------------
__global__ __launch_bounds__(256, 2)
void gemm_qkv_rope(const __half* __restrict__ Ah,
                   const __half* __restrict__ Al,
                   const __half* __restrict__ Bh,
                   const float* __restrict__ fc,
                   const float* __restrict__ fs) {
    GEMM_MAINLOOP(Ah, Al, Bh)

    const int r0 = bm + wm * 32 + (lane >> 2);
    const int c0 = bn + wn * 64 + (lane & 3) * 2;

    auto store_pair = [&](int row, int col, float v0, float v1) {
        int b = row >> 11, t = row & 2047;
        if (col < DIM) {                       // q: rope, hi/lo
            int hh = col >> 7, dp = (col & 127) >> 1;
            float c = fc[t * 64 + dp], s = fs[t * 64 + dp];
            float o0 = v0 * c - v1 * s;
            float o1 = v0 * s + v1 * c;
            size_t dst = (((size_t)(b * NH + hh) * TT + t) << 7) + 2 * dp;
            __half h0 = __float2half_rn(o0), h1 = __float2half_rn(o1);
            __half2 hv; hv.x = h0; hv.y = h1;
            *(uint32_t*)(g_fqh + dst) = *(uint32_t*)&hv;
            __half2 lv;
            lv.x = __float2half_rn(o0 - __half2float(h0));
            lv.y = __float2half_rn(o1 - __half2float(h1));
            *(uint32_t*)(g_fql + dst) = *(uint32_t*)&lv;
        } else if (col < DIM + NKVD) {         // k: rope, single fp16
            int cc = col - DIM;
            int hh = cc >> 7, dp = (cc & 127) >> 1;
            float c = fc[t * 64 + dp], s = fs[t * 64 + dp];
            float o0 = v0 * c - v1 * s;
            float o1 = v0 * s + v1 * c;
            size_t dst = (((size_t)(b * NKV + hh) * TT + t) << 7) + 2 * dp;
            __half2 hv; hv.x = __float2half_rn(o0); hv.y = __float2half_rn(o1);
            *(uint32_t*)(g_fkh + dst) = *(uint32_t*)&hv;
        } else {                               // v: plain fp16
            int cc = col - DIM - NKVD;
            int hh = cc >> 7, dd = cc & 127;
            size_t dst = (((size_t)(b * NKV + hh) * TT + t) << 7) + dd;
            __half2 hv; hv.x = __float2half_rn(v0); hv.y = __float2half_rn(v1);
            *(uint32_t*)(g_fv + dst) = *(uint32_t*)&hv;
        }
    };

#pragma unroll
    for (int i = 0; i < 2; i++)
#pragma unroll
        for (int j = 0; j < 8; j++) {
            int col = c0 + j * 8;
            store_pair(r0 + i * 16,     col, d[i][j][0], d[i][j][1]);
            store_pair(r0 + i * 16 + 8, col, d[i][j][2], d[i][j][3]);
        }
}

// ---- GEMM 2: output projection, SINGLE-pass A (ctx fp16), fp32 C -------
#define STAGE2_BYTES (2 * MAT_BYTES)    // 36864
#define WO_SMEM (2 * STAGE2_BYTES)      // 73728

__global__ __launch_bounds__(256, 2)
void gemm_wo(const __half* __restrict__ A,
             const __half* __restrict__ Bh,
             float* __restrict__ C, int N) {
    extern __shared__ char sm[];
    const uint32_t sbase = smem_u32(sm);
    const int tid  = threadIdx.x;
    const int lane = tid & 31;
    const int wid  = tid >> 5;
    const int wm   = wid & 3;
    const int wn   = wid >> 2;
    const int bm   = blockIdx.y * 128;
    const int bn   = blockIdx.x * 128;
    const __half* mats[2] = {A, Bh};

    float d[2][8][4];
#pragma unroll
    for (int i = 0; i < 2; i++)
#pragma unroll
        for (int j = 0; j < 8; j++)
#pragma unroll
            for (int r = 0; r < 4; r++) d[i][j][r] = 0.f;

    // per stage: 2 mats x 128 rows x 8 chunks = 2048 chunks, 8/thread
    auto load_chunk = [&](int buf, int c) {
        const int kofs = c * BKC;
        const uint32_t base = sbase + buf * STAGE2_BYTES;
#pragma unroll
        for (int t = 0; t < 8; t++) {
            int i   = tid + t * 256;
            int mat = i >> 10;
            int idx = i & 1023;
            int row = idx >> 3;
            int ch  = idx & 7;
            int grow = ((mat == 0) ? bm : bn) + row;
            cpa16(base + mat * MAT_BYTES + row * ROWB + ch * 16,
                  mats[mat] + (size_t)grow * GK + kofs + ch * 8);
        }
    };

    load_chunk(0, 0); cp_commit();

    const uint32_t a_off =
        (uint32_t)((wm * 32 + (lane & 15)) * ROWB + (lane >> 4) * 16);
    const uint32_t b_off = (uint32_t)(MAT_BYTES +
        (wn * 64 + (lane & 7) + ((lane >> 4) & 1) * 8) * ROWB +
        ((lane >> 3) & 1) * 16);

    for (int c = 0; c < GNC; ++c) {
        const int b = c & 1;
        if (c + 1 < GNC) {
            load_chunk(b ^ 1, c + 1);
            cp_commit();
            cp_wait1();
        } else {
            cp_wait0();
        }
        __syncthreads();
        const uint32_t stg = sbase + b * STAGE2_BYTES;
#pragma unroll
        for (int ks = 0; ks < 4; ks++) {
            uint32_t ah[2][4], bh[4][4];
#pragma unroll
            for (int i = 0; i < 2; i++)
                ldsm4(ah[i], stg + a_off + i * (16 * ROWB) + ks * 32);
#pragma unroll
            for (int jj = 0; jj < 4; jj++)
                ldsm4(bh[jj], stg + b_off + jj * (16 * ROWB) + ks * 32);
#pragma unroll
            for (int i = 0; i < 2; i++)
#pragma unroll
                for (int j = 0; j < 8; j++)
                    mma_f16(d[i][j], ah[i], &bh[j >> 1][(j & 1) * 2]);
        }
        __syncthreads();
    }

    const int r0 = bm + wm * 32 + (lane >> 2);
    const int c0 = bn + wn * 64 + (lane & 3) * 2;
#pragma unroll
    for (int i = 0; i < 2; i++)
#pragma unroll
        for (int j = 0; j < 8; j++) {
            int row = r0 + i * 16;
            int col = c0 + j * 8;
            *(float2*)&C[(size_t)row * N + col] =
                make_float2(d[i][j][0], d[i][j][1]);
            *(float2*)&C[(size_t)(row + 8) * N + col] =
                make_float2(d[i][j][2], d[i][j][3]);
        }
}

// ---------------- flash attention: fp16 HMMA, 2-pass QK -----------------
// smem: Qh [0,32K) Ql [32K,64K); stage s at 64K + s*32K: Kh 16K | V 16K
#define FSTG 65536
#define FSTGB 32768
#define FSMEM (FSTG + 2 * FSTGB)        // 131072
#define NSTILE (TT / 64)                // 32

__global__ __launch_bounds__(256, 1)
void flash_hmma(const __half* __restrict__ Qh, const __half* __restrict__ Ql,
                const __half* __restrict__ Kh, const __half* __restrict__ Vv,
                __half* __restrict__ Ch) {
    extern __shared__ char sm[];
    const uint32_t sb = smem_u32(sm);
    const int tid = threadIdx.x, lane = tid & 31, w = tid >> 5;
    const int t0 = blockIdx.x * 128;
    const int h  = blockIdx.y;
    const int b  = blockIdx.z;
    const int kh = h & 7;

    const __half* qhp = Qh + (((size_t)(b * NH + h) * TT + t0) << 7);
    const __half* qlp = Ql + (((size_t)(b * NH + h) * TT + t0) << 7);
    const __half* khp = Kh + (((size_t)(b * NKV + kh) * TT) << 7);
    const __half* vhp = Vv + (((size_t)(b * NKV + kh) * TT) << 7);

#pragma unroll
    for (int it = 0; it < 16; it++) {
        int i = tid + it * 256;
        int arr = i >> 11, ci = i & 2047;
        int r = ci >> 4, c = ci & 15;
        cpa16(sb + arr * 32768 + r * 256 + ((c ^ (r & 7)) * 16),
              (arr ? qlp : qhp) + r * HD + c * 8);
    }
    cp_commit();

    auto load_kv = [&](int stg, int s) {
        const uint32_t bs = sb + FSTG + stg * FSTGB;
        const __half* srcs[2] = {khp + (size_t)s * 64 * HD,
                                 vhp + (size_t)s * 64 * HD};
#pragma unroll
        for (int it = 0; it < 8; it++) {
            int i = tid + it * 256;
            int arr = i >> 10, ci = i & 1023;
            int r = ci >> 4, c = ci & 15;
            cpa16(bs + arr * 16384 + r * 256 + ((c ^ (r & 7)) * 16),
                  srcs[arr] + r * HD + c * 8);
        }
    };
    load_kv(0, 0); cp_commit();
    load_kv(1, 1); cp_commit();

    float oa[16][4];
#pragma unroll
    for (int nt = 0; nt < 16; nt++)
#pragma unroll
        for (int c = 0; c < 4; c++) oa[nt][c] = 0.f;
    float m0 = -1e30f, m1 = -1e30f, l0 = 0.f, l1 = 0.f;
    const float scale = 0.08838834764831845f;

    const int qr = w * 16 + (lane & 15);
    const uint32_t qrow = sb + qr * 256;
    const int kr = (lane & 7) + ((lane >> 4) & 1) * 8;
    const int vr = lane & 15;

    for (int s = 0; s < NSTILE; s++) {
        if (s + 1 < NSTILE) cp_wait1(); else cp_wait0();
        __syncthreads();
        const uint32_t kb = sb + FSTG + (s & 1) * FSTGB;

        // ---- S = Q K^T (2-pass: qh*kh + ql*kh) ----
        float sa[8][4];
#pragma unroll
        for (int j = 0; j < 8; j++)
#pragma unroll
            for (int c = 0; c < 4; c++) sa[j][c] = 0.f;

#pragma unroll
        for (int kc = 0; kc < 8; kc++) {
            uint32_t qa[4], qb[4];
            {
                int c = 2 * kc + (lane >> 4);
                uint32_t a = qrow + ((c ^ (qr & 7)) * 16);
                ldsm4(qa, a);
                ldsm4(qb, a + 32768);
            }
#pragma unroll
            for (int kt = 0; kt < 4; kt++) {
                uint32_t kfh[4];
                int krr = kt * 16 + kr;
                int kcc = 2 * kc + ((lane >> 3) & 1);
                uint32_t ka = kb + krr * 256 + ((kcc ^ (krr & 7)) * 16);
                ldsm4(kfh, ka);
#pragma unroll
                for (int hn = 0; hn < 2; hn++) {
                    int j = kt * 2 + hn;
                    mma_f16(sa[j], qa, &kfh[hn * 2]);
                    mma_f16(sa[j], qb, &kfh[hn * 2]);
                }
            }
        }

        // ---- online softmax (registers) ----
        float mx0 = -1e30f, mx1 = -1e30f;
#pragma unroll
        for (int j = 0; j < 8; j++) {
#pragma unroll
            for (int c = 0; c < 4; c++) sa[j][c] *= scale;
            mx0 = fmaxf(mx0, fmaxf(sa[j][0], sa[j][1]));
            mx1 = fmaxf(mx1, fmaxf(sa[j][2], sa[j][3]));
        }
#pragma unroll
        for (int off = 1; off <= 2; off <<= 1) {
            mx0 = fmaxf(mx0, __shfl_xor_sync(0xffffffffu, mx0, off));
            mx1 = fmaxf(mx1, __shfl_xor_sync(0xffffffffu, mx1, off));
        }
        float nm0 = fmaxf(m0, mx0), nm1 = fmaxf(m1, mx1);
        float al0 = __expf(m0 - nm0), al1 = __expf(m1 - nm1);
        float rs0 = 0.f, rs1 = 0.f;
#pragma unroll
        for (int j = 0; j < 8; j++) {
            sa[j][0] = __expf(sa[j][0] - nm0);
            sa[j][1] = __expf(sa[j][1] - nm0);
            sa[j][2] = __expf(sa[j][2] - nm1);
            sa[j][3] = __expf(sa[j][3] - nm1);
            rs0 += sa[j][0] + sa[j][1];
            rs1 += sa[j][2] + sa[j][3];
        }
#pragma unroll
        for (int off = 1; off <= 2; off <<= 1) {
            rs0 += __shfl_xor_sync(0xffffffffu, rs0, off);
            rs1 += __shfl_xor_sync(0xffffffffu, rs1, off);
        }
        l0 = l0 * al0 + rs0;  l1 = l1 * al1 + rs1;
        m0 = nm0;  m1 = nm1;
#pragma unroll
        for (int nt = 0; nt < 16; nt++) {
            oa[nt][0] *= al0; oa[nt][1] *= al0;
            oa[nt][2] *= al1; oa[nt][3] *= al1;
        }

        // ---- O += P V ----
#pragma unroll
        for (int kc2 = 0; kc2 < 4; kc2++) {
            uint32_t pa[4];
            pa[0] = pack_h2(sa[2 * kc2][0],     sa[2 * kc2][1]);
            pa[1] = pack_h2(sa[2 * kc2][2],     sa[2 * kc2][3]);
            pa[2] = pack_h2(sa[2 * kc2 + 1][0], sa[2 * kc2 + 1][1]);
            pa[3] = pack_h2(sa[2 * kc2 + 1][2], sa[2 * kc2 + 1][3]);
            int vrr = kc2 * 16 + vr;
            uint32_t vrow = kb + 16384 + vrr * 256;
#pragma unroll
            for (int nt2 = 0; nt2 < 8; nt2++) {
                uint32_t vf[4];
                int vc = nt2 * 2 + (lane >> 4);
                ldsm4t(vf, vrow + ((vc ^ (vrr & 7)) * 16));
                mma_f16(oa[nt2 * 2],     pa, &vf[0]);
                mma_f16(oa[nt2 * 2 + 1], pa, &vf[2]);
            }
        }

        __syncthreads();
        if (s + 2 < NSTILE) { load_kv(s & 1, s + 2); cp_commit(); }
    }

    // ---- epilogue: normalize, store ctx as single fp16 -----------------
    float i0 = 1.f / l0, i1 = 1.f / l1;
    int rg0 = t0 + w * 16 + (lane >> 2);
    size_t row0 = (size_t)(b * TT + rg0) * DIM;
    size_t row1 = row0 + 8 * DIM;
#pragma unroll
    for (int nt = 0; nt < 16; nt++) {
        int col = h * HD + nt * 8 + (lane & 3) * 2;
        {
            __half2 hv = __floats2half2_rn(oa[nt][0] * i0, oa[nt][1] * i0);
            *(uint32_t*)(Ch + row0 + col) = *(uint32_t*)&hv;
        }
        {
            __half2 hv = __floats2half2_rn(oa[nt][2] * i1, oa[nt][3] * i1);
            *(uint32_t*)(Ch + row1 + col) = *(uint32_t*)&hv;
        }
    }
}

// ---------------------------------------------------------------------------
extern "C" void kernel_launch(void* const* d_in, const int* in_sizes, int n_in,
                              void* d_out, int out_size) {
    const float* x  = (const float*)d_in[0];
    const float* wq = (const float*)d_in[1];
    const float* wk = (const float*)d_in[2];
    const float* wv = (const float*)d_in[3];
    const float* wo = (const float*)d_in[4];
    const float* fc = (const float*)d_in[5];
    const float* fs = (const float*)d_in[6];
    float* out = (float*)d_out;

    __half *xh, *xl, *wqkv, *wop, *ch;
    cudaGetSymbolAddress((void**)&xh,   g_xh);
    cudaGetSymbolAddress((void**)&xl,   g_xl);
    cudaGetSymbolAddress((void**)&wqkv, g_wqkv);
    cudaGetSymbolAddress((void**)&wop,  g_wo);
    cudaGetSymbolAddress((void**)&ch,   g_ch);
    __half *fqh, *fql, *fkh, *fv;
    cudaGetSymbolAddress((void**)&fqh, g_fqh); cudaGetSymbolAddress((void**)&fql, g_fql);
    cudaGetSymbolAddress((void**)&fkh, g_fkh);
    cudaGetSymbolAddress((void**)&fv,  g_fv);

    // fused, vectorized prepack (1 launch)
    prep_all<<<(TOTP4 + 255) / 256, 256>>>((const float4*)x, (const float4*)wq,
                                           (const float4*)wk, (const float4*)wv,
                                           (const float4*)wo);

    cudaFuncSetAttribute(gemm_qkv_rope,
                         cudaFuncAttributeMaxDynamicSharedMemorySize, GEMM_SMEM);
    cudaFuncSetAttribute(gemm_wo,
                         cudaFuncAttributeMaxDynamicSharedMemorySize, WO_SMEM);

    // qkv projection + fused rope + head-major fp16 pack
    gemm_qkv_rope<<<dim3(NQKV / 128, MTOK / 128), 256, GEMM_SMEM>>>(xh, xl, wqkv, fc, fs);

    cudaFuncSetAttribute(flash_hmma,
                         cudaFuncAttributeMaxDynamicSharedMemorySize, FSMEM);
    flash_hmma<<<dim3(TT / 128, NH, BB), 256, FSMEM>>>(fqh, fql, fkh, fv, ch);

    // output projection (single-pass A)
    gemm_wo<<<dim3(DIM / 128, MTOK / 128), 256, WO_SMEM>>>(ch, wop, out, DIM);
}

// round 13
// speedup vs baseline: 1.3002x; 1.0189x over previous
#include <cuda_runtime.h>
#include <cuda_bf16.h>
#include <cuda_fp16.h>
#include <math.h>
#include <stdint.h>

#define BB 2
#define TT 2048
#define DIM 4096
#define NH 32
#define NKV 8
#define HD 128
#define MTOK (BB * TT)
#define GK 4096
#define NKVD (NKV * HD)             // 1024
#define NQKV (DIM + 2 * NKVD)       // 6144

// ---------------- device scratch ---------------------------------------
__device__ __align__(16) __half g_xh[(size_t)MTOK * DIM];
__device__ __align__(16) __half g_xl[(size_t)MTOK * DIM];
__device__ __align__(16) __half g_wqkv[(size_t)NQKV * GK];
__device__ __align__(16) __half g_wo[(size_t)DIM * DIM];
__device__ __align__(16) __half g_ch[(size_t)MTOK * DIM];

// head-major fp16 q (hi/lo), k (single), v (single) for flash
__device__ __align__(16) __half g_fqh[(size_t)BB * NH * TT * HD];
__device__ __align__(16) __half g_fql[(size_t)BB * NH * TT * HD];
__device__ __align__(16) __half g_fkh[(size_t)BB * NKV * TT * HD];
__device__ __align__(16) __half g_fv [(size_t)BB * NKV * TT * HD];

// ---------------- helpers ----------------------------------------------
__device__ __forceinline__ uint32_t smem_u32(const void* p) {
    uint32_t a;
    asm("{ .reg .u64 t; cvta.to.shared.u64 t, %1; cvt.u32.u64 %0, t; }"
        : "=r"(a) : "l"(p));
    return a;
}
__device__ __forceinline__ void cpa16(uint32_t dst, const void* src) {
    asm volatile("cp.async.cg.shared.global [%0], [%1], 16;"
                 :: "r"(dst), "l"(src) : "memory");
}
__device__ __forceinline__ void cp_commit() {
    asm volatile("cp.async.commit_group;" ::: "memory");
}
__device__ __forceinline__ void cp_wait1() {
    asm volatile("cp.async.wait_group 1;" ::: "memory");
}
__device__ __forceinline__ void cp_wait0() {
    asm volatile("cp.async.wait_group 0;" ::: "memory");
}
__device__ __forceinline__ void ldsm4(uint32_t* r, uint32_t addr) {
    asm volatile("ldmatrix.sync.aligned.m8n8.x4.shared.b16 {%0,%1,%2,%3}, [%4];"
                 : "=r"(r[0]), "=r"(r[1]), "=r"(r[2]), "=r"(r[3]) : "r"(addr));
}
__device__ __forceinline__ void ldsm4t(uint32_t* r, uint32_t addr) {
    asm volatile("ldmatrix.sync.aligned.m8n8.x4.trans.shared.b16 {%0,%1,%2,%3}, [%4];"
                 : "=r"(r[0]), "=r"(r[1]), "=r"(r[2]), "=r"(r[3]) : "r"(addr));
}
__device__ __forceinline__ void mma_f16(float* d, const uint32_t* a, const uint32_t* b) {
    asm volatile(
        "mma.sync.aligned.m16n8k16.row.col.f32.f16.f16.f32 "
        "{%0,%1,%2,%3}, {%4,%5,%6,%7}, {%8,%9}, {%0,%1,%2,%3};\n"
        : "+f"(d[0]), "+f"(d[1]), "+f"(d[2]), "+f"(d[3])
        : "r"(a[0]), "r"(a[1]), "r"(a[2]), "r"(a[3]), "r"(b[0]), "r"(b[1]));
}
__device__ __forceinline__ uint32_t pack_h2(float lo, float hi) {
    __half2 h = __floats2half2_rn(lo, hi);
    return *(uint32_t*)&h;
}

// ---------------- fused prepack (vectorized, 4 elems/thread) -------------
#define NX  (MTOK * DIM)        // 16777216
#define NWQ (DIM * GK)          // 16777216
#define NWK (NKVD * GK)         // 4194304
#define TOTP4 ((NX + NWQ + 2 * NWK + NWQ) / 4)   // 14680064
__global__ void prep_all(const float4* __restrict__ x,
                         const float4* __restrict__ wq,
                         const float4* __restrict__ wk,
                         const float4* __restrict__ wv,
                         const float4* __restrict__ wo) {
    int i = blockIdx.x * blockDim.x + threadIdx.x;
    if (i >= TOTP4) return;
    if (i < NX / 4) {
        float4 v = x[i];
        __half2 h01 = __floats2half2_rn(v.x, v.y);
        __half2 h23 = __floats2half2_rn(v.z, v.w);
        __half2 l01 = __floats2half2_rn(v.x - __half2float(h01.x),
                                        v.y - __half2float(h01.y));
        __half2 l23 = __floats2half2_rn(v.z - __half2float(h23.x),
                                        v.w - __half2float(h23.y));
        uint2 hp; hp.x = *(uint32_t*)&h01; hp.y = *(uint32_t*)&h23;
        uint2 lp; lp.x = *(uint32_t*)&l01; lp.y = *(uint32_t*)&l23;
        *(uint2*)(g_xh + (size_t)i * 4) = hp;
        *(uint2*)(g_xl + (size_t)i * 4) = lp;
    } else {
        const float4* src;
        __half* dst;
        size_t j;
        if (i < (NX + NWQ) / 4) {
            j = i - NX / 4; src = wq; dst = g_wqkv;
        } else if (i < (NX + NWQ + NWK) / 4) {
            j = i - (NX + NWQ) / 4; src = wk; dst = g_wqkv + (size_t)DIM * GK;
        } else if (i < (NX + NWQ + 2 * NWK) / 4) {
            j = i - (NX + NWQ + NWK) / 4; src = wv;
            dst = g_wqkv + (size_t)(DIM + NKVD) * GK;
        } else {
            j = i - (NX + NWQ + 2 * NWK) / 4; src = wo; dst = g_wo;
        }
        float4 v = src[j];
        __half2 h01 = __floats2half2_rn(v.x, v.y);
        __half2 h23 = __floats2half2_rn(v.z, v.w);
        uint2 hp; hp.x = *(uint32_t*)&h01; hp.y = *(uint32_t*)&h23;
        *(uint2*)(dst + j * 4) = hp;
    }
}

// ---------------- HMMA fp16x2 GEMM mainloop (warp tile 32x64) ------------
#define BKC 64
#define ROWB 144
#define MAT_BYTES (128 * ROWB)         // 18432
#define STAGE_BYTES (3 * MAT_BYTES)    // 55296
#define GNC (GK / BKC)                 // 64
#define GEMM_SMEM (2 * STAGE_BYTES)    // 110592

// warp layout: 4 (m) x 2 (n); warp tile 32x64; accum d[2][8][4]
#define GEMM_MAINLOOP(Ah, Al, Bh)                                              \
    extern __shared__ char sm[];                                               \
    const uint32_t sbase = smem_u32(sm);                                       \
    const int tid  = threadIdx.x;                                              \
    const int lane = tid & 31;                                                 \
    const int wid  = tid >> 5;                                                 \
    const int wm   = wid & 3;                                                  \
    const int wn   = wid >> 2;                                                 \
    const int bm   = blockIdx.y * 128;                                         \
    const int bn   = blockIdx.x * 128;                                         \
    const __half* mats[3] = {Ah, Al, Bh};                                      \
    float d[2][8][4];                                                          \
    _Pragma("unroll")                                                          \
    for (int i = 0; i < 2; i++)                                                \
        _Pragma("unroll")                                                      \
        for (int j = 0; j < 8; j++)                                            \
            _Pragma("unroll")                                                  \
            for (int r = 0; r < 4; r++) d[i][j][r] = 0.f;                      \
    auto load_chunk = [&](int buf, int c) {                                    \
        const int kofs = c * BKC;                                              \
        const uint32_t base = sbase + buf * STAGE_BYTES;                       \
        _Pragma("unroll")                                                      \
        for (int t = 0; t < 12; t++) {                                         \
            int i   = tid + t * 256;                                           \
            int mat = i >> 10;                                                 \
            int idx = i & 1023;                                                \
            int row = idx >> 3;                                                \
            int ch  = idx & 7;                                                 \
            int grow = ((mat < 2) ? bm : bn) + row;                            \
            cpa16(base + mat * MAT_BYTES + row * ROWB + ch * 16,               \
                  mats[mat] + (size_t)grow * GK + kofs + ch * 8);              \
        }                                                                      \
    };                                                                         \
    load_chunk(0, 0); cp_commit();                                             \
    const uint32_t a_off =                                                     \
        (uint32_t)((wm * 32 + (lane & 15)) * ROWB + (lane >> 4) * 16);         \
    const uint32_t b_off = (uint32_t)(2 * MAT_BYTES +                          \
        (wn * 64 + (lane & 7) + ((lane >> 4) & 1) * 8) * ROWB +                \
        ((lane >> 3) & 1) * 16);                                               \
    for (int c = 0; c < GNC; ++c) {                                            \
        const int b = c & 1;                                                   \
        if (c + 1 < GNC) {                                                     \
            load_chunk(b ^ 1, c + 1);                                          \
            cp_commit();                                                       \
            cp_wait1();                                                        \
        } else {                                                               \
            cp_wait0();                                                        \
        }                                                                      \
        __syncthreads();                                                       \
        const uint32_t stg = sbase + b * STAGE_BYTES;                          \
        _Pragma("unroll")                                                      \
        for (int ks = 0; ks < 4; ks++) {                                       \
            uint32_t ah[2][4], al[2][4], bh[4][4];                             \
            _Pragma("unroll")                                                  \
            for (int i = 0; i < 2; i++)                                        \
                ldsm4(ah[i], stg + a_off + i * (16 * ROWB) + ks * 32);         \
            _Pragma("unroll")                                                  \
            for (int i = 0; i < 2; i++)                                        \
                ldsm4(al[i], stg + MAT_BYTES + a_off + i * (16 * ROWB) + ks * 32); \
            _Pragma("unroll")                                                  \
            for (int jj = 0; jj < 4; jj++)                                     \
                ldsm4(bh[jj], stg + b_off + jj * (16 * ROWB) + ks * 32);       \
            _Pragma("unroll")                                                  \
            for (int i = 0; i < 2; i++)                                        \
                _Pragma("unroll")                                              \
                for (int j = 0; j < 8; j++) {                                  \
                    const uint32_t* ph = &bh[j >> 1][(j & 1) * 2];             \
                    mma_f16(d[i][j], ah[i], ph);                               \
                    mma_f16(d[i][j], al[i], ph);                               \
                }                                                              \
        }                                                                      \
        __syncthreads();                                                       \
    }

// ---- GEMM 1: qkv projection with fused RoPE + fp16 pack ----------------
__global__ __launch_bounds__(256, 2)
void gemm_qkv_rope(const __half* __restrict__ Ah,
                   const __half* __restrict__ Al,
                   const __half* __restrict__ Bh,
                   const float* __restrict__ fc,
                   const float* __restrict__ fs) {
    GEMM_MAINLOOP(Ah, Al, Bh)

    const int r0 = bm + wm * 32 + (lane >> 2);
    const int c0 = bn + wn * 64 + (lane & 3) * 2;

    auto store_pair = [&](int row, int col, float v0, float v1) {
        int b = row >> 11, t = row & 2047;
        if (col < DIM) {                       // q: rope, hi/lo
            int hh = col >> 7, dp = (col & 127) >> 1;
            float c = fc[t * 64 + dp], s = fs[t * 64 + dp];
            float o0 = v0 * c - v1 * s;
            float o1 = v0 * s + v1 * c;
            size_t dst = (((size_t)(b * NH + hh) * TT + t) << 7) + 2 * dp;
            __half h0 = __float2half_rn(o0), h1 = __float2half_rn(o1);
            __half2 hv; hv.x = h0; hv.y = h1;
            *(uint32_t*)(g_fqh + dst) = *(uint32_t*)&hv;
            __half2 lv;
            lv.x = __float2half_rn(o0 - __half2float(h0));
            lv.y = __float2half_rn(o1 - __half2float(h1));
            *(uint32_t*)(g_fql + dst) = *(uint32_t*)&lv;
        } else if (col < DIM + NKVD) {         // k: rope, single fp16
            int cc = col - DIM;
            int hh = cc >> 7, dp = (cc & 127) >> 1;
            float c = fc[t * 64 + dp], s = fs[t * 64 + dp];
            float o0 = v0 * c - v1 * s;
            float o1 = v0 * s + v1 * c;
            size_t dst = (((size_t)(b * NKV + hh) * TT + t) << 7) + 2 * dp;
            __half2 hv; hv.x = __float2half_rn(o0); hv.y = __float2half_rn(o1);
            *(uint32_t*)(g_fkh + dst) = *(uint32_t*)&hv;
        } else {                               // v: plain fp16
            int cc = col - DIM - NKVD;
            int hh = cc >> 7, dd = cc & 127;
            size_t dst = (((size_t)(b * NKV + hh) * TT + t) << 7) + dd;
            __half2 hv; hv.x = __float2half_rn(v0); hv.y = __float2half_rn(v1);
            *(uint32_t*)(g_fv + dst) = *(uint32_t*)&hv;
        }
    };

#pragma unroll
    for (int i = 0; i < 2; i++)
#pragma unroll
        for (int j = 0; j < 8; j++) {
            int col = c0 + j * 8;
            store_pair(r0 + i * 16,     col, d[i][j][0], d[i][j][1]);
            store_pair(r0 + i * 16 + 8, col, d[i][j][2], d[i][j][3]);
        }
}

// ---- GEMM 2: output projection, SINGLE-pass A (ctx fp16), fp32 C -------
#define STAGE2_BYTES (2 * MAT_BYTES)    // 36864
#define WO_SMEM (2 * STAGE2_BYTES)      // 73728

__global__ __launch_bounds__(256, 2)
void gemm_wo(const __half* __restrict__ A,
             const __half* __restrict__ Bh,
             float* __restrict__ C, int N) {
    extern __shared__ char sm[];
    const uint32_t sbase = smem_u32(sm);
    const int tid  = threadIdx.x;
    const int lane = tid & 31;
    const int wid  = tid >> 5;
    const int wm   = wid & 3;
    const int wn   = wid >> 2;
    const int bm   = blockIdx.y * 128;
    const int bn   = blockIdx.x * 128;
    const __half* mats[2] = {A, Bh};

    float d[2][8][4];
#pragma unroll
    for (int i = 0; i < 2; i++)
#pragma unroll
        for (int j = 0; j < 8; j++)
#pragma unroll
            for (int r = 0; r < 4; r++) d[i][j][r] = 0.f;

    auto load_chunk = [&](int buf, int c) {
        const int kofs = c * BKC;
        const uint32_t base = sbase + buf * STAGE2_BYTES;
#pragma unroll
        for (int t = 0; t < 8; t++) {
            int i   = tid + t * 256;
            int mat = i >> 10;
            int idx = i & 1023;
            int row = idx >> 3;
            int ch  = idx & 7;
            int grow = ((mat == 0) ? bm : bn) + row;
            cpa16(base + mat * MAT_BYTES + row * ROWB + ch * 16,
                  mats[mat] + (size_t)grow * GK + kofs + ch * 8);
        }
    };

    load_chunk(0, 0); cp_commit();

    const uint32_t a_off =
        (uint32_t)((wm * 32 + (lane & 15)) * ROWB + (lane >> 4) * 16);
    const uint32_t b_off = (uint32_t)(MAT_BYTES +
        (wn * 64 + (lane & 7) + ((lane >> 4) & 1) * 8) * ROWB +
        ((lane >> 3) & 1) * 16);

    for (int c = 0; c < GNC; ++c) {
        const int b = c & 1;
        if (c + 1 < GNC) {
            load_chunk(b ^ 1, c + 1);
            cp_commit();
            cp_wait1();
        } else {
            cp_wait0();
        }
        __syncthreads();
        const uint32_t stg = sbase + b * STAGE2_BYTES;
#pragma unroll
        for (int ks = 0; ks < 4; ks++) {
            uint32_t ah[2][4], bh[4][4];
#pragma unroll
            for (int i = 0; i < 2; i++)
                ldsm4(ah[i], stg + a_off + i * (16 * ROWB) + ks * 32);
#pragma unroll
            for (int jj = 0; jj < 4; jj++)
                ldsm4(bh[jj], stg + b_off + jj * (16 * ROWB) + ks * 32);
#pragma unroll
            for (int i = 0; i < 2; i++)
#pragma unroll
                for (int j = 0; j < 8; j++)
                    mma_f16(d[i][j], ah[i], &bh[j >> 1][(j & 1) * 2]);
        }
        __syncthreads();
    }

    const int r0 = bm + wm * 32 + (lane >> 2);
    const int c0 = bn + wn * 64 + (lane & 3) * 2;
#pragma unroll
    for (int i = 0; i < 2; i++)
#pragma unroll
        for (int j = 0; j < 8; j++) {
            int row = r0 + i * 16;
            int col = c0 + j * 8;
            *(float2*)&C[(size_t)row * N + col] =
                make_float2(d[i][j][0], d[i][j][1]);
            *(float2*)&C[(size_t)(row + 8) * N + col] =
                make_float2(d[i][j][2], d[i][j][3]);
        }
}

// ---------------- flash attention: fp16 HMMA, 2-pass QK ------------------
// Q-tile 64 rows, 128 threads (4 warps), 2 CTAs/SM.
// smem: Qh [0,16K) Ql [16K,32K); stage s at 32K + s*32K: Kh 16K | V 16K
#define FSTG 32768
#define FSTGB 32768
#define FSMEM (FSTG + 2 * FSTGB)        // 98304
#define NSTILE (TT / 64)                // 32

__global__ __launch_bounds__(128, 2)
void flash_hmma(const __half* __restrict__ Qh, const __half* __restrict__ Ql,
                const __half* __restrict__ Kh, const __half* __restrict__ Vv,
                __half* __restrict__ Ch) {
    extern __shared__ char sm[];
    const uint32_t sb = smem_u32(sm);
    const int tid = threadIdx.x, lane = tid & 31, w = tid >> 5;   // w: 0..3
    const int t0 = blockIdx.x * 64;
    const int h  = blockIdx.y;
    const int b  = blockIdx.z;
    const int kh = h & 7;

    const __half* qhp = Qh + (((size_t)(b * NH + h) * TT + t0) << 7);
    const __half* qlp = Ql + (((size_t)(b * NH + h) * TT + t0) << 7);
    const __half* khp = Kh + (((size_t)(b * NKV + kh) * TT) << 7);
    const __half* vhp = Vv + (((size_t)(b * NKV + kh) * TT) << 7);

    // Q tile hi/lo: 64 rows x 16 chunks x 2 arrays = 2048 chunks / 128 thr
#pragma unroll
    for (int it = 0; it < 16; it++) {
        int i = tid + it * 128;
        int arr = i >> 10, ci = i & 1023;
        int r = ci >> 4, c = ci & 15;
        cpa16(sb + arr * 16384 + r * 256 + ((c ^ (r & 7)) * 16),
              (arr ? qlp : qhp) + r * HD + c * 8);
    }
    cp_commit();

    auto load_kv = [&](int stg, int s) {
        const uint32_t bs = sb + FSTG + stg * FSTGB;
        const __half* srcs[2] = {khp + (size_t)s * 64 * HD,
                                 vhp + (size_t)s * 64 * HD};
#pragma unroll
        for (int it = 0; it < 16; it++) {
            int i = tid + it * 128;
            int arr = i >> 10, ci = i & 1023;
            int r = ci >> 4, c = ci & 15;
            cpa16(bs + arr * 16384 + r * 256 + ((c ^ (r & 7)) * 16),
                  srcs[arr] + r * HD + c * 8);
        }
    };
    load_kv(0, 0); cp_commit();
    load_kv(1, 1); cp_commit();

    float oa[16][4];
#pragma unroll
    for (int nt = 0; nt < 16; nt++)
#pragma unroll
        for (int c = 0; c < 4; c++) oa[nt][c] = 0.f;
    float m0 = -1e30f, m1 = -1e30f, l0 = 0.f, l1 = 0.f;
    const float scale = 0.08838834764831845f;

    const int qr = w * 16 + (lane & 15);       // 0..63
    const uint32_t qrow = sb + qr * 256;
    const int kr = (lane & 7) + ((lane >> 4) & 1) * 8;
    const int vr = lane & 15;

    for (int s = 0; s < NSTILE; s++) {
        if (s + 1 < NSTILE) cp_wait1(); else cp_wait0();
        __syncthreads();
        const uint32_t kb = sb + FSTG + (s & 1) * FSTGB;

        // ---- S = Q K^T (2-pass: qh*kh + ql*kh) ----
        float sa[8][4];
#pragma unroll
        for (int j = 0; j < 8; j++)
#pragma unroll
            for (int c = 0; c < 4; c++) sa[j][c] = 0.f;

#pragma unroll
        for (int kc = 0; kc < 8; kc++) {
            uint32_t qa[4], qb[4];
            {
                int c = 2 * kc + (lane >> 4);
                uint32_t a = qrow + ((c ^ (qr & 7)) * 16);
                ldsm4(qa, a);
                ldsm4(qb, a + 16384);
            }
#pragma unroll
            for (int kt = 0; kt < 4; kt++) {
                uint32_t kfh[4];
                int krr = kt * 16 + kr;
                int kcc = 2 * kc + ((lane >> 3) & 1);
                uint32_t ka = kb + krr * 256 + ((kcc ^ (krr & 7)) * 16);
                ldsm4(kfh, ka);
#pragma unroll
                for (int hn = 0; hn < 2; hn++) {
                    int j = kt * 2 + hn;
                    mma_f16(sa[j], qa, &kfh[hn * 2]);
                    mma_f16(sa[j], qb, &kfh[hn * 2]);
                }
            }
        }

        // ---- online softmax (registers) ----
        float mx0 = -1e30f, mx1 = -1e30f;
#pragma unroll
        for (int j = 0; j < 8; j++) {
#pragma unroll
            for (int c = 0; c < 4; c++) sa[j][c] *= scale;
            mx0 = fmaxf(mx0, fmaxf(sa[j][0], sa[j][1]));
            mx1 = fmaxf(mx1, fmaxf(sa[j][2], sa[j][3]));
        }
#pragma unroll
        for (int off = 1; off <= 2; off <<= 1) {
            mx0 = fmaxf(mx0, __shfl_xor_sync(0xffffffffu, mx0, off));
            mx1 = fmaxf(mx1, __shfl_xor_sync(0xffffffffu, mx1, off));
        }
        float nm0 = fmaxf(m0, mx0), nm1 = fmaxf(m1, mx1);
        float al0 = __expf(m0 - nm0), al1 = __expf(m1 - nm1);
        float rs0 = 0.f, rs1 = 0.f;
#pragma unroll
        for (int j = 0; j < 8; j++) {
            sa[j][0] = __expf(sa[j][0] - nm0);
            sa[j][1] = __expf(sa[j][1] - nm0);
            sa[j][2] = __expf(sa[j][2] - nm1);
            sa[j][3] = __expf(sa[j][3] - nm1);
            rs0 += sa[j][0] + sa[j][1];
            rs1 += sa[j][2] + sa[j][3];
        }
#pragma unroll
        for (int off = 1; off <= 2; off <<= 1) {
            rs0 += __shfl_xor_sync(0xffffffffu, rs0, off);
            rs1 += __shfl_xor_sync(0xffffffffu, rs1, off);
        }
        l0 = l0 * al0 + rs0;  l1 = l1 * al1 + rs1;
        m0 = nm0;  m1 = nm1;
#pragma unroll
        for (int nt = 0; nt < 16; nt++) {
            oa[nt][0] *= al0; oa[nt][1] *= al0;
            oa[nt][2] *= al1; oa[nt][3] *= al1;
        }

        // ---- O += P V ----
#pragma unroll
        for (int kc2 = 0; kc2 < 4; kc2++) {
            uint32_t pa[4];
            pa[0] = pack_h2(sa[2 * kc2][0],     sa[2 * kc2][1]);
            pa[1] = pack_h2(sa[2 * kc2][2],     sa[2 * kc2][3]);
            pa[2] = pack_h2(sa[2 * kc2 + 1][0], sa[2 * kc2 + 1][1]);
            pa[3] = pack_h2(sa[2 * kc2 + 1][2], sa[2 * kc2 + 1][3]);
            int vrr = kc2 * 16 + vr;
            uint32_t vrow = kb + 16384 + vrr * 256;
#pragma unroll
            for (int nt2 = 0; nt2 < 8; nt2++) {
                uint32_t vf[4];
                int vc = nt2 * 2 + (lane >> 4);
                ldsm4t(vf, vrow + ((vc ^ (vrr & 7)) * 16));
                mma_f16(oa[nt2 * 2],     pa, &vf[0]);
                mma_f16(oa[nt2 * 2 + 1], pa, &vf[2]);
            }
        }

        __syncthreads();
        if (s + 2 < NSTILE) { load_kv(s & 1, s + 2); cp_commit(); }
    }

    // ---- epilogue: normalize, store ctx as single fp16 -----------------
    float i0 = 1.f / l0, i1 = 1.f / l1;
    int rg0 = t0 + w * 16 + (lane >> 2);
    size_t row0 = (size_t)(b * TT + rg0) * DIM;
    size_t row1 = row0 + 8 * DIM;
#pragma unroll
    for (int nt = 0; nt < 16; nt++) {
        int col = h * HD + nt * 8 + (lane & 3) * 2;
        {
            __half2 hv = __floats2half2_rn(oa[nt][0] * i0, oa[nt][1] * i0);
            *(uint32_t*)(Ch + row0 + col) = *(uint32_t*)&hv;
        }
        {
            __half2 hv = __floats2half2_rn(oa[nt][2] * i1, oa[nt][3] * i1);
            *(uint32_t*)(Ch + row1 + col) = *(uint32_t*)&hv;
        }
    }
}

// ---------------------------------------------------------------------------
extern "C" void kernel_launch(void* const* d_in, const int* in_sizes, int n_in,
                              void* d_out, int out_size) {
    const float* x  = (const float*)d_in[0];
    const float* wq = (const float*)d_in[1];
    const float* wk = (const float*)d_in[2];
    const float* wv = (const float*)d_in[3];
    const float* wo = (const float*)d_in[4];
    const float* fc = (const float*)d_in[5];
    const float* fs = (const float*)d_in[6];
    float* out = (float*)d_out;

    __half *xh, *xl, *wqkv, *wop, *ch;
    cudaGetSymbolAddress((void**)&xh,   g_xh);
    cudaGetSymbolAddress((void**)&xl,   g_xl);
    cudaGetSymbolAddress((void**)&wqkv, g_wqkv);
    cudaGetSymbolAddress((void**)&wop,  g_wo);
    cudaGetSymbolAddress((void**)&ch,   g_ch);
    __half *fqh, *fql, *fkh, *fv;
    cudaGetSymbolAddress((void**)&fqh, g_fqh); cudaGetSymbolAddress((void**)&fql, g_fql);
    cudaGetSymbolAddress((void**)&fkh, g_fkh);
    cudaGetSymbolAddress((void**)&fv,  g_fv);

    // fused, vectorized prepack (1 launch)
    prep_all<<<(TOTP4 + 255) / 256, 256>>>((const float4*)x, (const float4*)wq,
                                           (const float4*)wk, (const float4*)wv,
                                           (const float4*)wo);

    cudaFuncSetAttribute(gemm_qkv_rope,
                         cudaFuncAttributeMaxDynamicSharedMemorySize, GEMM_SMEM);
    cudaFuncSetAttribute(gemm_wo,
                         cudaFuncAttributeMaxDynamicSharedMemorySize, WO_SMEM);

    // qkv projection + fused rope + head-major fp16 pack
    gemm_qkv_rope<<<dim3(NQKV / 128, MTOK / 128), 256, GEMM_SMEM>>>(xh, xl, wqkv, fc, fs);

    cudaFuncSetAttribute(flash_hmma,
                         cudaFuncAttributeMaxDynamicSharedMemorySize, FSMEM);
    flash_hmma<<<dim3(TT / 64, NH, BB), 128, FSMEM>>>(fqh, fql, fkh, fv, ch);

    // output projection (single-pass A)
    gemm_wo<<<dim3(DIM / 128, MTOK / 128), 256, WO_SMEM>>>(ch, wop, out, DIM);
}

// round 14
// speedup vs baseline: 1.3629x; 1.0482x over previous
#include <cuda_runtime.h>
#include <cuda_bf16.h>
#include <cuda_fp16.h>
#include <math.h>
#include <stdint.h>

#define BB 2
#define TT 2048
#define DIM 4096
#define NH 32
#define NKV 8
#define HD 128
#define MTOK (BB * TT)
#define GK 4096
#define NKVD (NKV * HD)             // 1024
#define NQKV (DIM + 2 * NKVD)       // 6144

// ---------------- device scratch ---------------------------------------
__device__ __align__(16) __half g_xh[(size_t)MTOK * DIM];
__device__ __align__(16) __half g_xl[(size_t)MTOK * DIM];
__device__ __align__(16) __half g_wqkv[(size_t)NQKV * GK];
__device__ __align__(16) __half g_wo[(size_t)DIM * DIM];
__device__ __align__(16) __half g_ch[(size_t)MTOK * DIM];

// head-major fp16 q/k/v (all single fp16) for flash
__device__ __align__(16) __half g_fqh[(size_t)BB * NH * TT * HD];
__device__ __align__(16) __half g_fkh[(size_t)BB * NKV * TT * HD];
__device__ __align__(16) __half g_fv [(size_t)BB * NKV * TT * HD];

// ---------------- helpers ----------------------------------------------
__device__ __forceinline__ uint32_t smem_u32(const void* p) {
    uint32_t a;
    asm("{ .reg .u64 t; cvta.to.shared.u64 t, %1; cvt.u32.u64 %0, t; }"
        : "=r"(a) : "l"(p));
    return a;
}
__device__ __forceinline__ void cpa16(uint32_t dst, const void* src) {
    asm volatile("cp.async.cg.shared.global [%0], [%1], 16;"
                 :: "r"(dst), "l"(src) : "memory");
}
__device__ __forceinline__ void cp_commit() {
    asm volatile("cp.async.commit_group;" ::: "memory");
}
__device__ __forceinline__ void cp_wait1() {
    asm volatile("cp.async.wait_group 1;" ::: "memory");
}
__device__ __forceinline__ void cp_wait0() {
    asm volatile("cp.async.wait_group 0;" ::: "memory");
}
__device__ __forceinline__ void ldsm4(uint32_t* r, uint32_t addr) {
    asm volatile("ldmatrix.sync.aligned.m8n8.x4.shared.b16 {%0,%1,%2,%3}, [%4];"
                 : "=r"(r[0]), "=r"(r[1]), "=r"(r[2]), "=r"(r[3]) : "r"(addr));
}
__device__ __forceinline__ void ldsm4t(uint32_t* r, uint32_t addr) {
    asm volatile("ldmatrix.sync.aligned.m8n8.x4.trans.shared.b16 {%0,%1,%2,%3}, [%4];"
                 : "=r"(r[0]), "=r"(r[1]), "=r"(r[2]), "=r"(r[3]) : "r"(addr));
}
__device__ __forceinline__ void mma_f16(float* d, const uint32_t* a, const uint32_t* b) {
    asm volatile(
        "mma.sync.aligned.m16n8k16.row.col.f32.f16.f16.f32 "
        "{%0,%1,%2,%3}, {%4,%5,%6,%7}, {%8,%9}, {%0,%1,%2,%3};\n"
        : "+f"(d[0]), "+f"(d[1]), "+f"(d[2]), "+f"(d[3])
        : "r"(a[0]), "r"(a[1]), "r"(a[2]), "r"(a[3]), "r"(b[0]), "r"(b[1]));
}
__device__ __forceinline__ uint32_t pack_h2(float lo, float hi) {
    __half2 h = __floats2half2_rn(lo, hi);
    return *(uint32_t*)&h;
}

// ---------------- fused prepack (vectorized, 4 elems/thread) -------------
#define NX  (MTOK * DIM)        // 16777216
#define NWQ (DIM * GK)          // 16777216
#define NWK (NKVD * GK)         // 4194304
#define TOTP4 ((NX + NWQ + 2 * NWK + NWQ) / 4)   // 14680064
__global__ void prep_all(const float4* __restrict__ x,
                         const float4* __restrict__ wq,
                         const float4* __restrict__ wk,
                         const float4* __restrict__ wv,
                         const float4* __restrict__ wo) {
    int i = blockIdx.x * blockDim.x + threadIdx.x;
    if (i >= TOTP4) return;
    if (i < NX / 4) {
        float4 v = x[i];
        __half2 h01 = __floats2half2_rn(v.x, v.y);
        __half2 h23 = __floats2half2_rn(v.z, v.w);
        __half2 l01 = __floats2half2_rn(v.x - __half2float(h01.x),
                                        v.y - __half2float(h01.y));
        __half2 l23 = __floats2half2_rn(v.z - __half2float(h23.x),
                                        v.w - __half2float(h23.y));
        uint2 hp; hp.x = *(uint32_t*)&h01; hp.y = *(uint32_t*)&h23;
        uint2 lp; lp.x = *(uint32_t*)&l01; lp.y = *(uint32_t*)&l23;
        *(uint2*)(g_xh + (size_t)i * 4) = hp;
        *(uint2*)(g_xl + (size_t)i * 4) = lp;
    } else {
        const float4* src;
        __half* dst;
        size_t j;
        if (i < (NX + NWQ) / 4) {
            j = i - NX / 4; src = wq; dst = g_wqkv;
        } else if (i < (NX + NWQ + NWK) / 4) {
            j = i - (NX + NWQ) / 4; src = wk; dst = g_wqkv + (size_t)DIM * GK;
        } else if (i < (NX + NWQ + 2 * NWK) / 4) {
            j = i - (NX + NWQ + NWK) / 4; src = wv;
            dst = g_wqkv + (size_t)(DIM + NKVD) * GK;
        } else {
            j = i - (NX + NWQ + 2 * NWK) / 4; src = wo; dst = g_wo;
        }
        float4 v = src[j];
        __half2 h01 = __floats2half2_rn(v.x, v.y);
        __half2 h23 = __floats2half2_rn(v.z, v.w);
        uint2 hp; hp.x = *(uint32_t*)&h01; hp.y = *(uint32_t*)&h23;
        *(uint2*)(dst + j * 4) = hp;
    }
}

// ---------------- HMMA fp16x2 GEMM mainloop (warp tile 32x64) ------------
#define BKC 64
#define ROWB 144
#define MAT_BYTES (128 * ROWB)         // 18432
#define STAGE_BYTES (3 * MAT_BYTES)    // 55296
#define GNC (GK / BKC)                 // 64
#define GEMM_SMEM (2 * STAGE_BYTES)    // 110592

// warp layout: 4 (m) x 2 (n); warp tile 32x64; accum d[2][8][4]
#define GEMM_MAINLOOP(Ah, Al, Bh)                                              \
    extern __shared__ char sm[];                                               \
    const uint32_t sbase = smem_u32(sm);                                       \
    const int tid  = threadIdx.x;                                              \
    const int lane = tid & 31;                                                 \
    const int wid  = tid >> 5;                                                 \
    const int wm   = wid & 3;                                                  \
    const int wn   = wid >> 2;                                                 \
    const int bm   = blockIdx.y * 128;                                         \
    const int bn   = blockIdx.x * 128;                                         \
    const __half* mats[3] = {Ah, Al, Bh};                                      \
    float d[2][8][4];                                                          \
    _Pragma("unroll")                                                          \
    for (int i = 0; i < 2; i++)                                                \
        _Pragma("unroll")                                                      \
        for (int j = 0; j < 8; j++)                                            \
            _Pragma("unroll")                                                  \
            for (int r = 0; r < 4; r++) d[i][j][r] = 0.f;                      \
    auto load_chunk = [&](int buf, int c) {                                    \
        const int kofs = c * BKC;                                              \
        const uint32_t base = sbase + buf * STAGE_BYTES;                       \
        _Pragma("unroll")                                                      \
        for (int t = 0; t < 12; t++) {                                         \
            int i   = tid + t * 256;                                           \
            int mat = i >> 10;                                                 \
            int idx = i & 1023;                                                \
            int row = idx >> 3;                                                \
            int ch  = idx & 7;                                                 \
            int grow = ((mat < 2) ? bm : bn) + row;                            \
            cpa16(base + mat * MAT_BYTES + row * ROWB + ch * 16,               \
                  mats[mat] + (size_t)grow * GK + kofs + ch * 8);              \
        }                                                                      \
    };                                                                         \
    load_chunk(0, 0); cp_commit();                                             \
    const uint32_t a_off =                                                     \
        (uint32_t)((wm * 32 + (lane & 15)) * ROWB + (lane >> 4) * 16);         \
    const uint32_t b_off = (uint32_t)(2 * MAT_BYTES +                          \
        (wn * 64 + (lane & 7) + ((lane >> 4) & 1) * 8) * ROWB +                \
        ((lane >> 3) & 1) * 16);                                               \
    for (int c = 0; c < GNC; ++c) {                                            \
        const int b = c & 1;                                                   \
        if (c + 1 < GNC) {                                                     \
            load_chunk(b ^ 1, c + 1);                                          \
            cp_commit();                                                       \
            cp_wait1();                                                        \
        } else {                                                               \
            cp_wait0();                                                        \
        }                                                                      \
        __syncthreads();                                                       \
        const uint32_t stg = sbase + b * STAGE_BYTES;                          \
        _Pragma("unroll")                                                      \
        for (int ks = 0; ks < 4; ks++) {                                       \
            uint32_t ah[2][4], al[2][4], bh[4][4];                             \
            _Pragma("unroll")                                                  \
            for (int i = 0; i < 2; i++)                                        \
                ldsm4(ah[i], stg + a_off + i * (16 * ROWB) + ks * 32);         \
            _Pragma("unroll")                                                  \
            for (int i = 0; i < 2; i++)                                        \
                ldsm4(al[i], stg + MAT_BYTES + a_off + i * (16 * ROWB) + ks * 32); \
            _Pragma("unroll")                                                  \
            for (int jj = 0; jj < 4; jj++)                                     \
                ldsm4(bh[jj], stg + b_off + jj * (16 * ROWB) + ks * 32);       \
            _Pragma("unroll")                                                  \
            for (int i = 0; i < 2; i++)                                        \
                _Pragma("unroll")                                              \
                for (int j = 0; j < 8; j++) {                                  \
                    const uint32_t* ph = &bh[j >> 1][(j & 1) * 2];             \
                    mma_f16(d[i][j], ah[i], ph);                               \
                    mma_f16(d[i][j], al[i], ph);                               \
                }                                                              \
        }                                                                      \
        __syncthreads();                                                       \
    }

// ---- GEMM 1: qkv projection with fused RoPE + fp16 pack ----------------
__global__ __launch_bounds__(256, 2)
void gemm_qkv_rope(const __half* __restrict__ Ah,
                   const __half* __restrict__ Al,
                   const __half* __restrict__ Bh,
                   const float* __restrict__ fc,
                   const float* __restrict__ fs) {
    GEMM_MAINLOOP(Ah, Al, Bh)

    const int r0 = bm + wm * 32 + (lane >> 2);
    const int c0 = bn + wn * 64 + (lane & 3) * 2;

    auto store_pair = [&](int row, int col, float v0, float v1) {
        int b = row >> 11, t = row & 2047;
        if (col < DIM) {                       // q: rope, single fp16
            int hh = col >> 7, dp = (col & 127) >> 1;
            float c = fc[t * 64 + dp], s = fs[t * 64 + dp];
            float o0 = v0 * c - v1 * s;
            float o1 = v0 * s + v1 * c;
            size_t dst = (((size_t)(b * NH + hh) * TT + t) << 7) + 2 * dp;
            __half2 hv; hv.x = __float2half_rn(o0); hv.y = __float2half_rn(o1);
            *(uint32_t*)(g_fqh + dst) = *(uint32_t*)&hv;
        } else if (col < DIM + NKVD) {         // k: rope, single fp16
            int cc = col - DIM;
            int hh = cc >> 7, dp = (cc & 127) >> 1;
            float c = fc[t * 64 + dp], s = fs[t * 64 + dp];
            float o0 = v0 * c - v1 * s;
            float o1 = v0 * s + v1 * c;
            size_t dst = (((size_t)(b * NKV + hh) * TT + t) << 7) + 2 * dp;
            __half2 hv; hv.x = __float2half_rn(o0); hv.y = __float2half_rn(o1);
            *(uint32_t*)(g_fkh + dst) = *(uint32_t*)&hv;
        } else {                               // v: plain fp16
            int cc = col - DIM - NKVD;
            int hh = cc >> 7, dd = cc & 127;
            size_t dst = (((size_t)(b * NKV + hh) * TT + t) << 7) + dd;
            __half2 hv; hv.x = __float2half_rn(v0); hv.y = __float2half_rn(v1);
            *(uint32_t*)(g_fv + dst) = *(uint32_t*)&hv;
        }
    };

#pragma unroll
    for (int i = 0; i < 2; i++)
#pragma unroll
        for (int j = 0; j < 8; j++) {
            int col = c0 + j * 8;
            store_pair(r0 + i * 16,     col, d[i][j][0], d[i][j][1]);
            store_pair(r0 + i * 16 + 8, col, d[i][j][2], d[i][j][3]);
        }
}

// ---- GEMM 2: output projection, single-pass A, 3-stage, 1 sync/iter -----
#define STAGE2_BYTES (2 * MAT_BYTES)    // 36864
#define WO_SMEM (3 * STAGE2_BYTES)      // 110592

__global__ __launch_bounds__(256, 2)
void gemm_wo(const __half* __restrict__ A,
             const __half* __restrict__ Bh,
             float* __restrict__ C, int N) {
    extern __shared__ char sm[];
    const uint32_t sbase = smem_u32(sm);
    const int tid  = threadIdx.x;
    const int lane = tid & 31;
    const int wid  = tid >> 5;
    const int wm   = wid & 3;
    const int wn   = wid >> 2;
    const int bm   = blockIdx.y * 128;
    const int bn   = blockIdx.x * 128;
    const __half* mats[2] = {A, Bh};

    float d[2][8][4];
#pragma unroll
    for (int i = 0; i < 2; i++)
#pragma unroll
        for (int j = 0; j < 8; j++)
#pragma unroll
            for (int r = 0; r < 4; r++) d[i][j][r] = 0.f;

    auto load_chunk = [&](int buf, int c) {
        const int kofs = c * BKC;
        const uint32_t base = sbase + buf * STAGE2_BYTES;
#pragma unroll
        for (int t = 0; t < 8; t++) {
            int i   = tid + t * 256;
            int mat = i >> 10;
            int idx = i & 1023;
            int row = idx >> 3;
            int ch  = idx & 7;
            int grow = ((mat == 0) ? bm : bn) + row;
            cpa16(base + mat * MAT_BYTES + row * ROWB + ch * 16,
                  mats[mat] + (size_t)grow * GK + kofs + ch * 8);
        }
    };

    load_chunk(0, 0); cp_commit();
    load_chunk(1, 1); cp_commit();

    const uint32_t a_off =
        (uint32_t)((wm * 32 + (lane & 15)) * ROWB + (lane >> 4) * 16);
    const uint32_t b_off = (uint32_t)(MAT_BYTES +
        (wn * 64 + (lane & 7) + ((lane >> 4) & 1) * 8) * ROWB +
        ((lane >> 3) & 1) * 16);

    for (int c = 0; c < GNC; ++c) {
        if (c + 1 < GNC) cp_wait1(); else cp_wait0();
        __syncthreads();
        if (c + 2 < GNC) { load_chunk((c + 2) % 3, c + 2); cp_commit(); }

        const uint32_t stg = sbase + (c % 3) * STAGE2_BYTES;
#pragma unroll
        for (int ks = 0; ks < 4; ks++) {
            uint32_t ah[2][4], bh[4][4];
#pragma unroll
            for (int i = 0; i < 2; i++)
                ldsm4(ah[i], stg + a_off + i * (16 * ROWB) + ks * 32);
#pragma unroll
            for (int jj = 0; jj < 4; jj++)
                ldsm4(bh[jj], stg + b_off + jj * (16 * ROWB) + ks * 32);
#pragma unroll
            for (int i = 0; i < 2; i++)
#pragma unroll
                for (int j = 0; j < 8; j++)
                    mma_f16(d[i][j], ah[i], &bh[j >> 1][(j & 1) * 2]);
        }
    }

    const int r0 = bm + wm * 32 + (lane >> 2);
    const int c0 = bn + wn * 64 + (lane & 3) * 2;
#pragma unroll
    for (int i = 0; i < 2; i++)
#pragma unroll
        for (int j = 0; j < 8; j++) {
            int row = r0 + i * 16;
            int col = c0 + j * 8;
            *(float2*)&C[(size_t)row * N + col] =
                make_float2(d[i][j][0], d[i][j][1]);
            *(float2*)&C[(size_t)(row + 8) * N + col] =
                make_float2(d[i][j][2], d[i][j][3]);
        }
}

// ---------------- flash attention: fp16 HMMA, 1-pass QK ------------------
// Q-tile 64 rows, 128 threads (4 warps), 2 CTAs/SM, 3-stage KV, 1 sync/iter.
// smem: Q [0,16K); stage s at 16K + (s%3)*32K: Kh 16K | V 16K
#define FSTG 16384
#define FSTGB 32768
#define FSMEM (FSTG + 3 * FSTGB)        // 114688
#define NSTILE (TT / 64)                // 32

__global__ __launch_bounds__(128, 2)
void flash_hmma(const __half* __restrict__ Qh,
                const __half* __restrict__ Kh, const __half* __restrict__ Vv,
                __half* __restrict__ Ch) {
    extern __shared__ char sm[];
    const uint32_t sb = smem_u32(sm);
    const int tid = threadIdx.x, lane = tid & 31, w = tid >> 5;   // w: 0..3
    const int t0 = blockIdx.x * 64;
    const int h  = blockIdx.y;
    const int b  = blockIdx.z;
    const int kh = h & 7;

    const __half* qhp = Qh + (((size_t)(b * NH + h) * TT + t0) << 7);
    const __half* khp = Kh + (((size_t)(b * NKV + kh) * TT) << 7);
    const __half* vhp = Vv + (((size_t)(b * NKV + kh) * TT) << 7);

    // Q tile: 64 rows x 16 chunks = 1024 chunks / 128 threads
#pragma unroll
    for (int it = 0; it < 8; it++) {
        int i = tid + it * 128;
        int r = i >> 4, c = i & 15;
        cpa16(sb + r * 256 + ((c ^ (r & 7)) * 16), qhp + r * HD + c * 8);
    }
    cp_commit();

    auto load_kv = [&](int stg, int s) {
        const uint32_t bs = sb + FSTG + stg * FSTGB;
        const __half* srcs[2] = {khp + (size_t)s * 64 * HD,
                                 vhp + (size_t)s * 64 * HD};
#pragma unroll
        for (int it = 0; it < 16; it++) {
            int i = tid + it * 128;
            int arr = i >> 10, ci = i & 1023;
            int r = ci >> 4, c = ci & 15;
            cpa16(bs + arr * 16384 + r * 256 + ((c ^ (r & 7)) * 16),
                  srcs[arr] + r * HD + c * 8);
        }
    };
    load_kv(0, 0); cp_commit();
    load_kv(1, 1); cp_commit();

    float oa[16][4];
#pragma unroll
    for (int nt = 0; nt < 16; nt++)
#pragma unroll
        for (int c = 0; c < 4; c++) oa[nt][c] = 0.f;
    float m0 = -1e30f, m1 = -1e30f, l0 = 0.f, l1 = 0.f;
    const float scale = 0.08838834764831845f;

    const int qr = w * 16 + (lane & 15);       // 0..63
    const uint32_t qrow = sb + qr * 256;
    const int kr = (lane & 7) + ((lane >> 4) & 1) * 8;
    const int vr = lane & 15;

    for (int s = 0; s < NSTILE; s++) {
        if (s + 1 < NSTILE) cp_wait1(); else cp_wait0();
        __syncthreads();
        if (s + 2 < NSTILE) { load_kv((s + 2) % 3, s + 2); cp_commit(); }
        const uint32_t kb = sb + FSTG + (s % 3) * FSTGB;

        // ---- S = Q K^T (1-pass) ----
        float sa[8][4];
#pragma unroll
        for (int j = 0; j < 8; j++)
#pragma unroll
            for (int c = 0; c < 4; c++) sa[j][c] = 0.f;

#pragma unroll
        for (int kc = 0; kc < 8; kc++) {
            uint32_t qa[4];
            {
                int c = 2 * kc + (lane >> 4);
                ldsm4(qa, qrow + ((c ^ (qr & 7)) * 16));
            }
#pragma unroll
            for (int kt = 0; kt < 4; kt++) {
                uint32_t kfh[4];
                int krr = kt * 16 + kr;
                int kcc = 2 * kc + ((lane >> 3) & 1);
                ldsm4(kfh, kb + krr * 256 + ((kcc ^ (krr & 7)) * 16));
#pragma unroll
                for (int hn = 0; hn < 2; hn++)
                    mma_f16(sa[kt * 2 + hn], qa, &kfh[hn * 2]);
            }
        }

        // ---- online softmax (registers) ----
        float mx0 = -1e30f, mx1 = -1e30f;
#pragma unroll
        for (int j = 0; j < 8; j++) {
#pragma unroll
            for (int c = 0; c < 4; c++) sa[j][c] *= scale;
            mx0 = fmaxf(mx0, fmaxf(sa[j][0], sa[j][1]));
            mx1 = fmaxf(mx1, fmaxf(sa[j][2], sa[j][3]));
        }
#pragma unroll
        for (int off = 1; off <= 2; off <<= 1) {
            mx0 = fmaxf(mx0, __shfl_xor_sync(0xffffffffu, mx0, off));
            mx1 = fmaxf(mx1, __shfl_xor_sync(0xffffffffu, mx1, off));
        }
        float nm0 = fmaxf(m0, mx0), nm1 = fmaxf(m1, mx1);
        float al0 = __expf(m0 - nm0), al1 = __expf(m1 - nm1);
        float rs0 = 0.f, rs1 = 0.f;
#pragma unroll
        for (int j = 0; j < 8; j++) {
            sa[j][0] = __expf(sa[j][0] - nm0);
            sa[j][1] = __expf(sa[j][1] - nm0);
            sa[j][2] = __expf(sa[j][2] - nm1);
            sa[j][3] = __expf(sa[j][3] - nm1);
            rs0 += sa[j][0] + sa[j][1];
            rs1 += sa[j][2] + sa[j][3];
        }
#pragma unroll
        for (int off = 1; off <= 2; off <<= 1) {
            rs0 += __shfl_xor_sync(0xffffffffu, rs0, off);
            rs1 += __shfl_xor_sync(0xffffffffu, rs1, off);
        }
        l0 = l0 * al0 + rs0;  l1 = l1 * al1 + rs1;
        m0 = nm0;  m1 = nm1;
#pragma unroll
        for (int nt = 0; nt < 16; nt++) {
            oa[nt][0] *= al0; oa[nt][1] *= al0;
            oa[nt][2] *= al1; oa[nt][3] *= al1;
        }

        // ---- O += P V ----
#pragma unroll
        for (int kc2 = 0; kc2 < 4; kc2++) {
            uint32_t pa[4];
            pa[0] = pack_h2(sa[2 * kc2][0],     sa[2 * kc2][1]);
            pa[1] = pack_h2(sa[2 * kc2][2],     sa[2 * kc2][3]);
            pa[2] = pack_h2(sa[2 * kc2 + 1][0], sa[2 * kc2 + 1][1]);
            pa[3] = pack_h2(sa[2 * kc2 + 1][2], sa[2 * kc2 + 1][3]);
            int vrr = kc2 * 16 + vr;
            uint32_t vrow = kb + 16384 + vrr * 256;
#pragma unroll
            for (int nt2 = 0; nt2 < 8; nt2++) {
                uint32_t vf[4];
                int vc = nt2 * 2 + (lane >> 4);
                ldsm4t(vf, vrow + ((vc ^ (vrr & 7)) * 16));
                mma_f16(oa[nt2 * 2],     pa, &vf[0]);
                mma_f16(oa[nt2 * 2 + 1], pa, &vf[2]);
            }
        }
    }

    // ---- epilogue: normalize, store ctx as single fp16 -----------------
    float i0 = 1.f / l0, i1 = 1.f / l1;
    int rg0 = t0 + w * 16 + (lane >> 2);
    size_t row0 = (size_t)(b * TT + rg0) * DIM;
    size_t row1 = row0 + 8 * DIM;
#pragma unroll
    for (int nt = 0; nt < 16; nt++) {
        int col = h * HD + nt * 8 + (lane & 3) * 2;
        {
            __half2 hv = __floats2half2_rn(oa[nt][0] * i0, oa[nt][1] * i0);
            *(uint32_t*)(Ch + row0 + col) = *(uint32_t*)&hv;
        }
        {
            __half2 hv = __floats2half2_rn(oa[nt][2] * i1, oa[nt][3] * i1);
            *(uint32_t*)(Ch + row1 + col) = *(uint32_t*)&hv;
        }
    }
}

// ---------------------------------------------------------------------------
extern "C" void kernel_launch(void* const* d_in, const int* in_sizes, int n_in,
                              void* d_out, int out_size) {
    const float* x  = (const float*)d_in[0];
    const float* wq = (const float*)d_in[1];
    const float* wk = (const float*)d_in[2];
    const float* wv = (const float*)d_in[3];
    const float* wo = (const float*)d_in[4];
    const float* fc = (const float*)d_in[5];
    const float* fs = (const float*)d_in[6];
    float* out = (float*)d_out;

    __half *xh, *xl, *wqkv, *wop, *ch;
    cudaGetSymbolAddress((void**)&xh,   g_xh);
    cudaGetSymbolAddress((void**)&xl,   g_xl);
    cudaGetSymbolAddress((void**)&wqkv, g_wqkv);
    cudaGetSymbolAddress((void**)&wop,  g_wo);
    cudaGetSymbolAddress((void**)&ch,   g_ch);
    __half *fqh, *fkh, *fv;
    cudaGetSymbolAddress((void**)&fqh, g_fqh);
    cudaGetSymbolAddress((void**)&fkh, g_fkh);
    cudaGetSymbolAddress((void**)&fv,  g_fv);

    // fused, vectorized prepack (1 launch)
    prep_all<<<(TOTP4 + 255) / 256, 256>>>((const float4*)x, (const float4*)wq,
                                           (const float4*)wk, (const float4*)wv,
                                           (const float4*)wo);

    cudaFuncSetAttribute(gemm_qkv_rope,
                         cudaFuncAttributeMaxDynamicSharedMemorySize, GEMM_SMEM);
    cudaFuncSetAttribute(gemm_wo,
                         cudaFuncAttributeMaxDynamicSharedMemorySize, WO_SMEM);

    // qkv projection + fused rope + head-major fp16 pack
    gemm_qkv_rope<<<dim3(NQKV / 128, MTOK / 128), 256, GEMM_SMEM>>>(xh, xl, wqkv, fc, fs);

    cudaFuncSetAttribute(flash_hmma,
                         cudaFuncAttributeMaxDynamicSharedMemorySize, FSMEM);
    flash_hmma<<<dim3(TT / 64, NH, BB), 128, FSMEM>>>(fqh, fkh, fv, ch);

    // output projection (single-pass A, 3-stage)
    gemm_wo<<<dim3(DIM / 128, MTOK / 128), 256, WO_SMEM>>>(ch, wop, out, DIM);
}

// round 15
// speedup vs baseline: 1.3973x; 1.0253x over previous
#include <cuda_runtime.h>
#include <cuda_bf16.h>
#include <cuda_fp16.h>
#include <math.h>
#include <stdint.h>

#define BB 2
#define TT 2048
#define DIM 4096
#define NH 32
#define NKV 8
#define HD 128
#define MTOK (BB * TT)
#define GK 4096
#define NKVD (NKV * HD)             // 1024
#define NQKV (DIM + 2 * NKVD)       // 6144

// ---------------- device scratch ---------------------------------------
__device__ __align__(16) __half g_xh[(size_t)MTOK * DIM];
__device__ __align__(16) __half g_xl[(size_t)MTOK * DIM];
__device__ __align__(16) __half g_wqkv[(size_t)NQKV * GK];
__device__ __align__(16) __half g_wo[(size_t)DIM * DIM];
__device__ __align__(16) __half g_ch[(size_t)MTOK * DIM];

// head-major fp16 q/k/v (all single fp16) for flash
__device__ __align__(16) __half g_fqh[(size_t)BB * NH * TT * HD];
__device__ __align__(16) __half g_fkh[(size_t)BB * NKV * TT * HD];
__device__ __align__(16) __half g_fv [(size_t)BB * NKV * TT * HD];

// ---------------- helpers ----------------------------------------------
__device__ __forceinline__ uint32_t smem_u32(const void* p) {
    uint32_t a;
    asm("{ .reg .u64 t; cvta.to.shared.u64 t, %1; cvt.u32.u64 %0, t; }"
        : "=r"(a) : "l"(p));
    return a;
}
__device__ __forceinline__ void cpa16(uint32_t dst, const void* src) {
    asm volatile("cp.async.cg.shared.global [%0], [%1], 16;"
                 :: "r"(dst), "l"(src) : "memory");
}
__device__ __forceinline__ void cp_commit() {
    asm volatile("cp.async.commit_group;" ::: "memory");
}
__device__ __forceinline__ void cp_wait1() {
    asm volatile("cp.async.wait_group 1;" ::: "memory");
}
__device__ __forceinline__ void cp_wait0() {
    asm volatile("cp.async.wait_group 0;" ::: "memory");
}
__device__ __forceinline__ void ldsm4(uint32_t* r, uint32_t addr) {
    asm volatile("ldmatrix.sync.aligned.m8n8.x4.shared.b16 {%0,%1,%2,%3}, [%4];"
                 : "=r"(r[0]), "=r"(r[1]), "=r"(r[2]), "=r"(r[3]) : "r"(addr));
}
__device__ __forceinline__ void ldsm4t(uint32_t* r, uint32_t addr) {
    asm volatile("ldmatrix.sync.aligned.m8n8.x4.trans.shared.b16 {%0,%1,%2,%3}, [%4];"
                 : "=r"(r[0]), "=r"(r[1]), "=r"(r[2]), "=r"(r[3]) : "r"(addr));
}
__device__ __forceinline__ void mma_f16(float* d, const uint32_t* a, const uint32_t* b) {
    asm volatile(
        "mma.sync.aligned.m16n8k16.row.col.f32.f16.f16.f32 "
        "{%0,%1,%2,%3}, {%4,%5,%6,%7}, {%8,%9}, {%0,%1,%2,%3};\n"
        : "+f"(d[0]), "+f"(d[1]), "+f"(d[2]), "+f"(d[3])
        : "r"(a[0]), "r"(a[1]), "r"(a[2]), "r"(a[3]), "r"(b[0]), "r"(b[1]));
}
__device__ __forceinline__ uint32_t pack_h2(float lo, float hi) {
    __half2 h = __floats2half2_rn(lo, hi);
    return *(uint32_t*)&h;
}

// ---------------- fused prepack (vectorized, 4 elems/thread) -------------
#define NX  (MTOK * DIM)        // 16777216
#define NWQ (DIM * GK)          // 16777216
#define NWK (NKVD * GK)         // 4194304
#define TOTP4 ((NX + NWQ + 2 * NWK + NWQ) / 4)   // 14680064
__global__ void prep_all(const float4* __restrict__ x,
                         const float4* __restrict__ wq,
                         const float4* __restrict__ wk,
                         const float4* __restrict__ wv,
                         const float4* __restrict__ wo) {
    int i = blockIdx.x * blockDim.x + threadIdx.x;
    if (i >= TOTP4) return;
    if (i < NX / 4) {
        float4 v = x[i];
        __half2 h01 = __floats2half2_rn(v.x, v.y);
        __half2 h23 = __floats2half2_rn(v.z, v.w);
        __half2 l01 = __floats2half2_rn(v.x - __half2float(h01.x),
                                        v.y - __half2float(h01.y));
        __half2 l23 = __floats2half2_rn(v.z - __half2float(h23.x),
                                        v.w - __half2float(h23.y));
        uint2 hp; hp.x = *(uint32_t*)&h01; hp.y = *(uint32_t*)&h23;
        uint2 lp; lp.x = *(uint32_t*)&l01; lp.y = *(uint32_t*)&l23;
        *(uint2*)(g_xh + (size_t)i * 4) = hp;
        *(uint2*)(g_xl + (size_t)i * 4) = lp;
    } else {
        const float4* src;
        __half* dst;
        size_t j;
        if (i < (NX + NWQ) / 4) {
            j = i - NX / 4; src = wq; dst = g_wqkv;
        } else if (i < (NX + NWQ + NWK) / 4) {
            j = i - (NX + NWQ) / 4; src = wk; dst = g_wqkv + (size_t)DIM * GK;
        } else if (i < (NX + NWQ + 2 * NWK) / 4) {
            j = i - (NX + NWQ + NWK) / 4; src = wv;
            dst = g_wqkv + (size_t)(DIM + NKVD) * GK;
        } else {
            j = i - (NX + NWQ + 2 * NWK) / 4; src = wo; dst = g_wo;
        }
        float4 v = src[j];
        __half2 h01 = __floats2half2_rn(v.x, v.y);
        __half2 h23 = __floats2half2_rn(v.z, v.w);
        uint2 hp; hp.x = *(uint32_t*)&h01; hp.y = *(uint32_t*)&h23;
        *(uint2*)(dst + j * 4) = hp;
    }
}

// ---------------- shared GEMM constants ----------------------------------
#define BKC 64
#define ROWB 144
#define GNC (GK / BKC)                 // 64
#define MAT128 (128 * ROWB)            // 18432
#define MAT64  (64 * ROWB)             // 9216

// ---- GEMM 1: qkv projection, CTA tile 64x128, 128 thr, 3 CTA/SM --------
// stage: A-hi 9216 | A-lo 9216 | B 18432 = 36864; 2 stages = 73728
#define QK_STAGE 36864
#define QK_SMEM (2 * QK_STAGE)

__global__ __launch_bounds__(128, 3)
void gemm_qkv_rope(const __half* __restrict__ Ah,
                   const __half* __restrict__ Al,
                   const __half* __restrict__ Bh,
                   const float* __restrict__ fc,
                   const float* __restrict__ fs) {
    extern __shared__ char sm[];
    const uint32_t sbase = smem_u32(sm);
    const int tid  = threadIdx.x;
    const int lane = tid & 31;
    const int wid  = tid >> 5;       // 0..3
    const int wm   = wid & 1;        // 2 M-warps
    const int wn   = wid >> 1;       // 2 N-warps
    const int bm   = blockIdx.y * 64;
    const int bn   = blockIdx.x * 128;

    float d[2][8][4];
#pragma unroll
    for (int i = 0; i < 2; i++)
#pragma unroll
        for (int j = 0; j < 8; j++)
#pragma unroll
            for (int r = 0; r < 4; r++) d[i][j][r] = 0.f;

    // per stage: Ah 512 + Al 512 + B 1024 = 2048 chunks, 16/thread
    auto load_chunk = [&](int buf, int c) {
        const int kofs = c * BKC;
        const uint32_t base = sbase + buf * QK_STAGE;
#pragma unroll
        for (int t = 0; t < 16; t++) {
            int i = tid + t * 128;
            if (i < 1024) {
                int mat = i >> 9;           // 0: Ah, 1: Al
                int idx = i & 511;
                int row = idx >> 3, ch = idx & 7;
                cpa16(base + mat * MAT64 + row * ROWB + ch * 16,
                      (mat ? Al : Ah) + (size_t)(bm + row) * GK + kofs + ch * 8);
            } else {
                int idx = i & 1023;
                int row = idx >> 3, ch = idx & 7;
                cpa16(base + 2 * MAT64 + row * ROWB + ch * 16,
                      Bh + (size_t)(bn + row) * GK + kofs + ch * 8);
            }
        }
    };

    load_chunk(0, 0); cp_commit();

    const uint32_t a_off =
        (uint32_t)((wm * 32 + (lane & 15)) * ROWB + (lane >> 4) * 16);
    const uint32_t b_off = (uint32_t)(2 * MAT64 +
        (wn * 64 + (lane & 7) + ((lane >> 4) & 1) * 8) * ROWB +
        ((lane >> 3) & 1) * 16);

    for (int c = 0; c < GNC; ++c) {
        const int b = c & 1;
        if (c + 1 < GNC) {
            load_chunk(b ^ 1, c + 1);
            cp_commit();
            cp_wait1();
        } else {
            cp_wait0();
        }
        __syncthreads();
        const uint32_t stg = sbase + b * QK_STAGE;
#pragma unroll
        for (int ks = 0; ks < 4; ks++) {
            uint32_t ah[2][4], al[2][4], bh[4][4];
#pragma unroll
            for (int i = 0; i < 2; i++)
                ldsm4(ah[i], stg + a_off + i * (16 * ROWB) + ks * 32);
#pragma unroll
            for (int i = 0; i < 2; i++)
                ldsm4(al[i], stg + MAT64 + a_off + i * (16 * ROWB) + ks * 32);
#pragma unroll
            for (int jj = 0; jj < 4; jj++)
                ldsm4(bh[jj], stg + b_off + jj * (16 * ROWB) + ks * 32);
#pragma unroll
            for (int i = 0; i < 2; i++)
#pragma unroll
                for (int j = 0; j < 8; j++) {
                    const uint32_t* ph = &bh[j >> 1][(j & 1) * 2];
                    mma_f16(d[i][j], ah[i], ph);
                    mma_f16(d[i][j], al[i], ph);
                }
        }
        __syncthreads();
    }

    const int r0 = bm + wm * 32 + (lane >> 2);
    const int c0 = bn + wn * 64 + (lane & 3) * 2;

    auto store_pair = [&](int row, int col, float v0, float v1) {
        int b = row >> 11, t = row & 2047;
        if (col < DIM) {                       // q: rope, single fp16
            int hh = col >> 7, dp = (col & 127) >> 1;
            float c = fc[t * 64 + dp], s = fs[t * 64 + dp];
            float o0 = v0 * c - v1 * s;
            float o1 = v0 * s + v1 * c;
            size_t dst = (((size_t)(b * NH + hh) * TT + t) << 7) + 2 * dp;
            __half2 hv; hv.x = __float2half_rn(o0); hv.y = __float2half_rn(o1);
            *(uint32_t*)(g_fqh + dst) = *(uint32_t*)&hv;
        } else if (col < DIM + NKVD) {         // k: rope, single fp16
            int cc = col - DIM;
            int hh = cc >> 7, dp = (cc & 127) >> 1;
            float c = fc[t * 64 + dp], s = fs[t * 64 + dp];
            float o0 = v0 * c - v1 * s;
            float o1 = v0 * s + v1 * c;
            size_t dst = (((size_t)(b * NKV + hh) * TT + t) << 7) + 2 * dp;
            __half2 hv; hv.x = __float2half_rn(o0); hv.y = __float2half_rn(o1);
            *(uint32_t*)(g_fkh + dst) = *(uint32_t*)&hv;
        } else {                               // v: plain fp16
            int cc = col - DIM - NKVD;
            int hh = cc >> 7, dd = cc & 127;
            size_t dst = (((size_t)(b * NKV + hh) * TT + t) << 7) + dd;
            __half2 hv; hv.x = __float2half_rn(v0); hv.y = __float2half_rn(v1);
            *(uint32_t*)(g_fv + dst) = *(uint32_t*)&hv;
        }
    };

#pragma unroll
    for (int i = 0; i < 2; i++)
#pragma unroll
        for (int j = 0; j < 8; j++) {
            int col = c0 + j * 8;
            store_pair(r0 + i * 16,     col, d[i][j][0], d[i][j][1]);
            store_pair(r0 + i * 16 + 8, col, d[i][j][2], d[i][j][3]);
        }
}

// ---- GEMM 2: output projection (round-12 best: 2-stage, 256 thr) --------
#define STAGE2_BYTES (2 * MAT128)       // 36864
#define WO_SMEM (2 * STAGE2_BYTES)      // 73728

__global__ __launch_bounds__(256, 2)
void gemm_wo(const __half* __restrict__ A,
             const __half* __restrict__ Bh,
             float* __restrict__ C, int N) {
    extern __shared__ char sm[];
    const uint32_t sbase = smem_u32(sm);
    const int tid  = threadIdx.x;
    const int lane = tid & 31;
    const int wid  = tid >> 5;
    const int wm   = wid & 3;
    const int wn   = wid >> 2;
    const int bm   = blockIdx.y * 128;
    const int bn   = blockIdx.x * 128;
    const __half* mats[2] = {A, Bh};

    float d[2][8][4];
#pragma unroll
    for (int i = 0; i < 2; i++)
#pragma unroll
        for (int j = 0; j < 8; j++)
#pragma unroll
            for (int r = 0; r < 4; r++) d[i][j][r] = 0.f;

    auto load_chunk = [&](int buf, int c) {
        const int kofs = c * BKC;
        const uint32_t base = sbase + buf * STAGE2_BYTES;
#pragma unroll
        for (int t = 0; t < 8; t++) {
            int i   = tid + t * 256;
            int mat = i >> 10;
            int idx = i & 1023;
            int row = idx >> 3;
            int ch  = idx & 7;
            int grow = ((mat == 0) ? bm : bn) + row;
            cpa16(base + mat * MAT128 + row * ROWB + ch * 16,
                  mats[mat] + (size_t)grow * GK + kofs + ch * 8);
        }
    };

    load_chunk(0, 0); cp_commit();

    const uint32_t a_off =
        (uint32_t)((wm * 32 + (lane & 15)) * ROWB + (lane >> 4) * 16);
    const uint32_t b_off = (uint32_t)(MAT128 +
        (wn * 64 + (lane & 7) + ((lane >> 4) & 1) * 8) * ROWB +
        ((lane >> 3) & 1) * 16);

    for (int c = 0; c < GNC; ++c) {
        const int b = c & 1;
        if (c + 1 < GNC) {
            load_chunk(b ^ 1, c + 1);
            cp_commit();
            cp_wait1();
        } else {
            cp_wait0();
        }
        __syncthreads();
        const uint32_t stg = sbase + b * STAGE2_BYTES;
#pragma unroll
        for (int ks = 0; ks < 4; ks++) {
            uint32_t ah[2][4], bh[4][4];
#pragma unroll
            for (int i = 0; i < 2; i++)
                ldsm4(ah[i], stg + a_off + i * (16 * ROWB) + ks * 32);
#pragma unroll
            for (int jj = 0; jj < 4; jj++)
                ldsm4(bh[jj], stg + b_off + jj * (16 * ROWB) + ks * 32);
#pragma unroll
            for (int i = 0; i < 2; i++)
#pragma unroll
                for (int j = 0; j < 8; j++)
                    mma_f16(d[i][j], ah[i], &bh[j >> 1][(j & 1) * 2]);
        }
        __syncthreads();
    }

    const int r0 = bm + wm * 32 + (lane >> 2);
    const int c0 = bn + wn * 64 + (lane & 3) * 2;
#pragma unroll
    for (int i = 0; i < 2; i++)
#pragma unroll
        for (int j = 0; j < 8; j++) {
            int row = r0 + i * 16;
            int col = c0 + j * 8;
            *(float2*)&C[(size_t)row * N + col] =
                make_float2(d[i][j][0], d[i][j][1]);
            *(float2*)&C[(size_t)(row + 8) * N + col] =
                make_float2(d[i][j][2], d[i][j][3]);
        }
}

// ---------------- flash attention: fp16 HMMA, 1-pass QK ------------------
// Q-tile 64 rows, 128 threads (4 warps), 2 CTAs/SM, 3-stage KV, 1 sync/iter.
// smem: Q [0,16K); stage s at 16K + (s%3)*32K: Kh 16K | V 16K
#define FSTG 16384
#define FSTGB 32768
#define FSMEM (FSTG + 3 * FSTGB)        // 114688
#define NSTILE (TT / 64)                // 32

__global__ __launch_bounds__(128, 2)
void flash_hmma(const __half* __restrict__ Qh,
                const __half* __restrict__ Kh, const __half* __restrict__ Vv,
                __half* __restrict__ Ch) {
    extern __shared__ char sm[];
    const uint32_t sb = smem_u32(sm);
    const int tid = threadIdx.x, lane = tid & 31, w = tid >> 5;   // w: 0..3
    const int t0 = blockIdx.x * 64;
    const int h  = blockIdx.y;
    const int b  = blockIdx.z;
    const int kh = h & 7;

    const __half* qhp = Qh + (((size_t)(b * NH + h) * TT + t0) << 7);
    const __half* khp = Kh + (((size_t)(b * NKV + kh) * TT) << 7);
    const __half* vhp = Vv + (((size_t)(b * NKV + kh) * TT) << 7);

    // Q tile: 64 rows x 16 chunks = 1024 chunks / 128 threads
#pragma unroll
    for (int it = 0; it < 8; it++) {
        int i = tid + it * 128;
        int r = i >> 4, c = i & 15;
        cpa16(sb + r * 256 + ((c ^ (r & 7)) * 16), qhp + r * HD + c * 8);
    }
    cp_commit();

    auto load_kv = [&](int stg, int s) {
        const uint32_t bs = sb + FSTG + stg * FSTGB;
        const __half* srcs[2] = {khp + (size_t)s * 64 * HD,
                                 vhp + (size_t)s * 64 * HD};
#pragma unroll
        for (int it = 0; it < 16; it++) {
            int i = tid + it * 128;
            int arr = i >> 10, ci = i & 1023;
            int r = ci >> 4, c = ci & 15;
            cpa16(bs + arr * 16384 + r * 256 + ((c ^ (r & 7)) * 16),
                  srcs[arr] + r * HD + c * 8);
        }
    };
    load_kv(0, 0); cp_commit();
    load_kv(1, 1); cp_commit();

    float oa[16][4];
#pragma unroll
    for (int nt = 0; nt < 16; nt++)
#pragma unroll
        for (int c = 0; c < 4; c++) oa[nt][c] = 0.f;
    float m0 = -1e30f, m1 = -1e30f, l0 = 0.f, l1 = 0.f;
    const float scale = 0.08838834764831845f;

    const int qr = w * 16 + (lane & 15);       // 0..63
    const uint32_t qrow = sb + qr * 256;
    const int kr = (lane & 7) + ((lane >> 4) & 1) * 8;
    const int vr = lane & 15;

    for (int s = 0; s < NSTILE; s++) {
        if (s + 1 < NSTILE) cp_wait1(); else cp_wait0();
        __syncthreads();
        if (s + 2 < NSTILE) { load_kv((s + 2) % 3, s + 2); cp_commit(); }
        const uint32_t kb = sb + FSTG + (s % 3) * FSTGB;

        // ---- S = Q K^T (1-pass) ----
        float sa[8][4];
#pragma unroll
        for (int j = 0; j < 8; j++)
#pragma unroll
            for (int c = 0; c < 4; c++) sa[j][c] = 0.f;

#pragma unroll
        for (int kc = 0; kc < 8; kc++) {
            uint32_t qa[4];
            {
                int c = 2 * kc + (lane >> 4);
                ldsm4(qa, qrow + ((c ^ (qr & 7)) * 16));
            }
#pragma unroll
            for (int kt = 0; kt < 4; kt++) {
                uint32_t kfh[4];
                int krr = kt * 16 + kr;
                int kcc = 2 * kc + ((lane >> 3) & 1);
                ldsm4(kfh, kb + krr * 256 + ((kcc ^ (krr & 7)) * 16));
#pragma unroll
                for (int hn = 0; hn < 2; hn++)
                    mma_f16(sa[kt * 2 + hn], qa, &kfh[hn * 2]);
            }
        }

        // ---- online softmax (registers) ----
        float mx0 = -1e30f, mx1 = -1e30f;
#pragma unroll
        for (int j = 0; j < 8; j++) {
#pragma unroll
            for (int c = 0; c < 4; c++) sa[j][c] *= scale;
            mx0 = fmaxf(mx0, fmaxf(sa[j][0], sa[j][1]));
            mx1 = fmaxf(mx1, fmaxf(sa[j][2], sa[j][3]));
        }
#pragma unroll
        for (int off = 1; off <= 2; off <<= 1) {
            mx0 = fmaxf(mx0, __shfl_xor_sync(0xffffffffu, mx0, off));
            mx1 = fmaxf(mx1, __shfl_xor_sync(0xffffffffu, mx1, off));
        }
        float nm0 = fmaxf(m0, mx0), nm1 = fmaxf(m1, mx1);
        float al0 = __expf(m0 - nm0), al1 = __expf(m1 - nm1);
        float rs0 = 0.f, rs1 = 0.f;
#pragma unroll
        for (int j = 0; j < 8; j++) {
            sa[j][0] = __expf(sa[j][0] - nm0);
            sa[j][1] = __expf(sa[j][1] - nm0);
            sa[j][2] = __expf(sa[j][2] - nm1);
            sa[j][3] = __expf(sa[j][3] - nm1);
            rs0 += sa[j][0] + sa[j][1];
            rs1 += sa[j][2] + sa[j][3];
        }
#pragma unroll
        for (int off = 1; off <= 2; off <<= 1) {
            rs0 += __shfl_xor_sync(0xffffffffu, rs0, off);
            rs1 += __shfl_xor_sync(0xffffffffu, rs1, off);
        }
        l0 = l0 * al0 + rs0;  l1 = l1 * al1 + rs1;
        m0 = nm0;  m1 = nm1;
#pragma unroll
        for (int nt = 0; nt < 16; nt++) {
            oa[nt][0] *= al0; oa[nt][1] *= al0;
            oa[nt][2] *= al1; oa[nt][3] *= al1;
        }

        // ---- O += P V ----
#pragma unroll
        for (int kc2 = 0; kc2 < 4; kc2++) {
            uint32_t pa[4];
            pa[0] = pack_h2(sa[2 * kc2][0],     sa[2 * kc2][1]);
            pa[1] = pack_h2(sa[2 * kc2][2],     sa[2 * kc2][3]);
            pa[2] = pack_h2(sa[2 * kc2 + 1][0], sa[2 * kc2 + 1][1]);
            pa[3] = pack_h2(sa[2 * kc2 + 1][2], sa[2 * kc2 + 1][3]);
            int vrr = kc2 * 16 + vr;
            uint32_t vrow = kb + 16384 + vrr * 256;
#pragma unroll
            for (int nt2 = 0; nt2 < 8; nt2++) {
                uint32_t vf[4];
                int vc = nt2 * 2 + (lane >> 4);
                ldsm4t(vf, vrow + ((vc ^ (vrr & 7)) * 16));
                mma_f16(oa[nt2 * 2],     pa, &vf[0]);
                mma_f16(oa[nt2 * 2 + 1], pa, &vf[2]);
            }
        }
    }

    // ---- epilogue: normalize, store ctx as single fp16 -----------------
    float i0 = 1.f / l0, i1 = 1.f / l1;
    int rg0 = t0 + w * 16 + (lane >> 2);
    size_t row0 = (size_t)(b * TT + rg0) * DIM;
    size_t row1 = row0 + 8 * DIM;
#pragma unroll
    for (int nt = 0; nt < 16; nt++) {
        int col = h * HD + nt * 8 + (lane & 3) * 2;
        {
            __half2 hv = __floats2half2_rn(oa[nt][0] * i0, oa[nt][1] * i0);
            *(uint32_t*)(Ch + row0 + col) = *(uint32_t*)&hv;
        }
        {
            __half2 hv = __floats2half2_rn(oa[nt][2] * i1, oa[nt][3] * i1);
            *(uint32_t*)(Ch + row1 + col) = *(uint32_t*)&hv;
        }
    }
}

// ---------------------------------------------------------------------------
extern "C" void kernel_launch(void* const* d_in, const int* in_sizes, int n_in,
                              void* d_out, int out_size) {
    const float* x  = (const float*)d_in[0];
    const float* wq = (const float*)d_in[1];
    const float* wk = (const float*)d_in[2];
    const float* wv = (const float*)d_in[3];
    const float* wo = (const float*)d_in[4];
    const float* fc = (const float*)d_in[5];
    const float* fs = (const float*)d_in[6];
    float* out = (float*)d_out;

    __half *xh, *xl, *wqkv, *wop, *ch;
    cudaGetSymbolAddress((void**)&xh,   g_xh);
    cudaGetSymbolAddress((void**)&xl,   g_xl);
    cudaGetSymbolAddress((void**)&wqkv, g_wqkv);
    cudaGetSymbolAddress((void**)&wop,  g_wo);
    cudaGetSymbolAddress((void**)&ch,   g_ch);
    __half *fqh, *fkh, *fv;
    cudaGetSymbolAddress((void**)&fqh, g_fqh);
    cudaGetSymbolAddress((void**)&fkh, g_fkh);
    cudaGetSymbolAddress((void**)&fv,  g_fv);

    // fused, vectorized prepack (1 launch)
    prep_all<<<(TOTP4 + 255) / 256, 256>>>((const float4*)x, (const float4*)wq,
                                           (const float4*)wk, (const float4*)wv,
                                           (const float4*)wo);

    cudaFuncSetAttribute(gemm_qkv_rope,
                         cudaFuncAttributeMaxDynamicSharedMemorySize, QK_SMEM);
    cudaFuncSetAttribute(gemm_wo,
                         cudaFuncAttributeMaxDynamicSharedMemorySize, WO_SMEM);

    // qkv projection + fused rope + head-major fp16 pack (64-row tiles)
    gemm_qkv_rope<<<dim3(NQKV / 128, MTOK / 64), 128, QK_SMEM>>>(xh, xl, wqkv, fc, fs);

    cudaFuncSetAttribute(flash_hmma,
                         cudaFuncAttributeMaxDynamicSharedMemorySize, FSMEM);
    flash_hmma<<<dim3(TT / 64, NH, BB), 128, FSMEM>>>(fqh, fkh, fv, ch);

    // output projection (single-pass A, 2-stage)
    gemm_wo<<<dim3(DIM / 128, MTOK / 128), 256, WO_SMEM>>>(ch, wop, out, DIM);
}

// round 16
// speedup vs baseline: 1.4038x; 1.0046x over previous
#include <cuda_runtime.h>
#include <cuda_bf16.h>
#include <cuda_fp16.h>
#include <math.h>
#include <stdint.h>

#define BB 2
#define TT 2048
#define DIM 4096
#define NH 32
#define NKV 8
#define HD 128
#define MTOK (BB * TT)
#define GK 4096
#define NKVD (NKV * HD)             // 1024
#define NQKV (DIM + 2 * NKVD)       // 6144

// ---------------- device scratch ---------------------------------------
__device__ __align__(16) __half g_xh[(size_t)MTOK * DIM];
__device__ __align__(16) __half g_xl[(size_t)MTOK * DIM];
__device__ __align__(16) __half g_wqkv[(size_t)NQKV * GK];
__device__ __align__(16) __half g_wo[(size_t)DIM * DIM];
__device__ __align__(16) __half g_ch[(size_t)MTOK * DIM];

// head-major fp16 q/k/v (all single fp16) for flash
__device__ __align__(16) __half g_fqh[(size_t)BB * NH * TT * HD];
__device__ __align__(16) __half g_fkh[(size_t)BB * NKV * TT * HD];
__device__ __align__(16) __half g_fv [(size_t)BB * NKV * TT * HD];

// ---------------- helpers ----------------------------------------------
__device__ __forceinline__ uint32_t smem_u32(const void* p) {
    uint32_t a;
    asm("{ .reg .u64 t; cvta.to.shared.u64 t, %1; cvt.u32.u64 %0, t; }"
        : "=r"(a) : "l"(p));
    return a;
}
__device__ __forceinline__ void cpa16(uint32_t dst, const void* src) {
    asm volatile("cp.async.cg.shared.global [%0], [%1], 16;"
                 :: "r"(dst), "l"(src) : "memory");
}
__device__ __forceinline__ void cp_commit() {
    asm volatile("cp.async.commit_group;" ::: "memory");
}
__device__ __forceinline__ void cp_wait1() {
    asm volatile("cp.async.wait_group 1;" ::: "memory");
}
__device__ __forceinline__ void cp_wait0() {
    asm volatile("cp.async.wait_group 0;" ::: "memory");
}
__device__ __forceinline__ void ldsm4(uint32_t* r, uint32_t addr) {
    asm volatile("ldmatrix.sync.aligned.m8n8.x4.shared.b16 {%0,%1,%2,%3}, [%4];"
                 : "=r"(r[0]), "=r"(r[1]), "=r"(r[2]), "=r"(r[3]) : "r"(addr));
}
__device__ __forceinline__ void ldsm4t(uint32_t* r, uint32_t addr) {
    asm volatile("ldmatrix.sync.aligned.m8n8.x4.trans.shared.b16 {%0,%1,%2,%3}, [%4];"
                 : "=r"(r[0]), "=r"(r[1]), "=r"(r[2]), "=r"(r[3]) : "r"(addr));
}
__device__ __forceinline__ void mma_f16(float* d, const uint32_t* a, const uint32_t* b) {
    asm volatile(
        "mma.sync.aligned.m16n8k16.row.col.f32.f16.f16.f32 "
        "{%0,%1,%2,%3}, {%4,%5,%6,%7}, {%8,%9}, {%0,%1,%2,%3};\n"
        : "+f"(d[0]), "+f"(d[1]), "+f"(d[2]), "+f"(d[3])
        : "r"(a[0]), "r"(a[1]), "r"(a[2]), "r"(a[3]), "r"(b[0]), "r"(b[1]));
}
__device__ __forceinline__ uint32_t pack_h2(float lo, float hi) {
    __half2 h = __floats2half2_rn(lo, hi);
    return *(uint32_t*)&h;
}

// ---------------- fused prepack (vectorized, 4 elems/thread) -------------
#define NX  (MTOK * DIM)        // 16777216
#define NWQ (DIM * GK)          // 16777216
#define NWK (NKVD * GK)         // 4194304
#define TOTP4 ((NX + NWQ + 2 * NWK + NWQ) / 4)   // 14680064
__global__ void prep_all(const float4* __restrict__ x,
                         const float4* __restrict__ wq,
                         const float4* __restrict__ wk,
                         const float4* __restrict__ wv,
                         const float4* __restrict__ wo) {
    int i = blockIdx.x * blockDim.x + threadIdx.x;
    if (i >= TOTP4) return;
    if (i < NX / 4) {
        float4 v = x[i];
        __half2 h01 = __floats2half2_rn(v.x, v.y);
        __half2 h23 = __floats2half2_rn(v.z, v.w);
        __half2 l01 = __floats2half2_rn(v.x - __half2float(h01.x),
                                        v.y - __half2float(h01.y));
        __half2 l23 = __floats2half2_rn(v.z - __half2float(h23.x),
                                        v.w - __half2float(h23.y));
        uint2 hp; hp.x = *(uint32_t*)&h01; hp.y = *(uint32_t*)&h23;
        uint2 lp; lp.x = *(uint32_t*)&l01; lp.y = *(uint32_t*)&l23;
        *(uint2*)(g_xh + (size_t)i * 4) = hp;
        *(uint2*)(g_xl + (size_t)i * 4) = lp;
    } else {
        const float4* src;
        __half* dst;
        size_t j;
        if (i < (NX + NWQ) / 4) {
            j = i - NX / 4; src = wq; dst = g_wqkv;
        } else if (i < (NX + NWQ + NWK) / 4) {
            j = i - (NX + NWQ) / 4; src = wk; dst = g_wqkv + (size_t)DIM * GK;
        } else if (i < (NX + NWQ + 2 * NWK) / 4) {
            j = i - (NX + NWQ + NWK) / 4; src = wv;
            dst = g_wqkv + (size_t)(DIM + NKVD) * GK;
        } else {
            j = i - (NX + NWQ + 2 * NWK) / 4; src = wo; dst = g_wo;
        }
        float4 v = src[j];
        __half2 h01 = __floats2half2_rn(v.x, v.y);
        __half2 h23 = __floats2half2_rn(v.z, v.w);
        uint2 hp; hp.x = *(uint32_t*)&h01; hp.y = *(uint32_t*)&h23;
        *(uint2*)(dst + j * 4) = hp;
    }
}

// ---------------- shared GEMM constants ----------------------------------
#define BKC 64
#define ROWB 144
#define GNC (GK / BKC)                 // 64
#define MAT128 (128 * ROWB)            // 18432
#define MAT64  (64 * ROWB)             // 9216

// ---- GEMM 1: qkv projection, CTA tile 64x128, 128 thr, 3 CTA/SM --------
// stage: A-hi 9216 | A-lo 9216 | B 18432 = 36864; 2 stages = 73728
#define QK_STAGE 36864
#define QK_SMEM (2 * QK_STAGE)

__global__ __launch_bounds__(128, 3)
void gemm_qkv_rope(const __half* __restrict__ Ah,
                   const __half* __restrict__ Al,
                   const __half* __restrict__ Bh,
                   const float* __restrict__ fc,
                   const float* __restrict__ fs) {
    extern __shared__ char sm[];
    const uint32_t sbase = smem_u32(sm);
    const int tid  = threadIdx.x;
    const int lane = tid & 31;
    const int wid  = tid >> 5;       // 0..3
    const int wm   = wid & 1;        // 2 M-warps
    const int wn   = wid >> 1;       // 2 N-warps
    const int bm   = blockIdx.y * 64;
    const int bn   = blockIdx.x * 128;

    float d[2][8][4];
#pragma unroll
    for (int i = 0; i < 2; i++)
#pragma unroll
        for (int j = 0; j < 8; j++)
#pragma unroll
            for (int r = 0; r < 4; r++) d[i][j][r] = 0.f;

    // per stage: Ah 512 + Al 512 + B 1024 = 2048 chunks, 16/thread
    auto load_chunk = [&](int buf, int c) {
        const int kofs = c * BKC;
        const uint32_t base = sbase + buf * QK_STAGE;
#pragma unroll
        for (int t = 0; t < 16; t++) {
            int i = tid + t * 128;
            if (i < 1024) {
                int mat = i >> 9;           // 0: Ah, 1: Al
                int idx = i & 511;
                int row = idx >> 3, ch = idx & 7;
                cpa16(base + mat * MAT64 + row * ROWB + ch * 16,
                      (mat ? Al : Ah) + (size_t)(bm + row) * GK + kofs + ch * 8);
            } else {
                int idx = i & 1023;
                int row = idx >> 3, ch = idx & 7;
                cpa16(base + 2 * MAT64 + row * ROWB + ch * 16,
                      Bh + (size_t)(bn + row) * GK + kofs + ch * 8);
            }
        }
    };

    load_chunk(0, 0); cp_commit();

    const uint32_t a_off =
        (uint32_t)((wm * 32 + (lane & 15)) * ROWB + (lane >> 4) * 16);
    const uint32_t b_off = (uint32_t)(2 * MAT64 +
        (wn * 64 + (lane & 7) + ((lane >> 4) & 1) * 8) * ROWB +
        ((lane >> 3) & 1) * 16);

    for (int c = 0; c < GNC; ++c) {
        const int b = c & 1;
        if (c + 1 < GNC) {
            load_chunk(b ^ 1, c + 1);
            cp_commit();
            cp_wait1();
        } else {
            cp_wait0();
        }
        __syncthreads();
        const uint32_t stg = sbase + b * QK_STAGE;
#pragma unroll
        for (int ks = 0; ks < 4; ks++) {
            uint32_t ah[2][4], al[2][4], bh[4][4];
#pragma unroll
            for (int i = 0; i < 2; i++)
                ldsm4(ah[i], stg + a_off + i * (16 * ROWB) + ks * 32);
#pragma unroll
            for (int i = 0; i < 2; i++)
                ldsm4(al[i], stg + MAT64 + a_off + i * (16 * ROWB) + ks * 32);
#pragma unroll
            for (int jj = 0; jj < 4; jj++)
                ldsm4(bh[jj], stg + b_off + jj * (16 * ROWB) + ks * 32);
#pragma unroll
            for (int i = 0; i < 2; i++)
#pragma unroll
                for (int j = 0; j < 8; j++) {
                    const uint32_t* ph = &bh[j >> 1][(j & 1) * 2];
                    mma_f16(d[i][j], ah[i], ph);
                    mma_f16(d[i][j], al[i], ph);
                }
        }
        __syncthreads();
    }

    const int r0 = bm + wm * 32 + (lane >> 2);
    const int c0 = bn + wn * 64 + (lane & 3) * 2;

    auto store_pair = [&](int row, int col, float v0, float v1) {
        int b = row >> 11, t = row & 2047;
        if (col < DIM) {                       // q: rope, single fp16
            int hh = col >> 7, dp = (col & 127) >> 1;
            float c = fc[t * 64 + dp], s = fs[t * 64 + dp];
            float o0 = v0 * c - v1 * s;
            float o1 = v0 * s + v1 * c;
            size_t dst = (((size_t)(b * NH + hh) * TT + t) << 7) + 2 * dp;
            __half2 hv; hv.x = __float2half_rn(o0); hv.y = __float2half_rn(o1);
            *(uint32_t*)(g_fqh + dst) = *(uint32_t*)&hv;
        } else if (col < DIM + NKVD) {         // k: rope, single fp16
            int cc = col - DIM;
            int hh = cc >> 7, dp = (cc & 127) >> 1;
            float c = fc[t * 64 + dp], s = fs[t * 64 + dp];
            float o0 = v0 * c - v1 * s;
            float o1 = v0 * s + v1 * c;
            size_t dst = (((size_t)(b * NKV + hh) * TT + t) << 7) + 2 * dp;
            __half2 hv; hv.x = __float2half_rn(o0); hv.y = __float2half_rn(o1);
            *(uint32_t*)(g_fkh + dst) = *(uint32_t*)&hv;
        } else {                               // v: plain fp16
            int cc = col - DIM - NKVD;
            int hh = cc >> 7, dd = cc & 127;
            size_t dst = (((size_t)(b * NKV + hh) * TT + t) << 7) + dd;
            __half2 hv; hv.x = __float2half_rn(v0); hv.y = __float2half_rn(v1);
            *(uint32_t*)(g_fv + dst) = *(uint32_t*)&hv;
        }
    };

#pragma unroll
    for (int i = 0; i < 2; i++)
#pragma unroll
        for (int j = 0; j < 8; j++) {
            int col = c0 + j * 8;
            store_pair(r0 + i * 16,     col, d[i][j][0], d[i][j][1]);
            store_pair(r0 + i * 16 + 8, col, d[i][j][2], d[i][j][3]);
        }
}

// ---- GEMM 2: output projection, CTA tile 64x128, 128 thr, 3 CTA/SM -----
// stage: A 9216 | B 18432 = 27648; 2 stages = 55296
#define WO_STAGE 27648
#define WO_SMEM (2 * WO_STAGE)

__global__ __launch_bounds__(128, 3)
void gemm_wo(const __half* __restrict__ A,
             const __half* __restrict__ Bh,
             float* __restrict__ C, int N) {
    extern __shared__ char sm[];
    const uint32_t sbase = smem_u32(sm);
    const int tid  = threadIdx.x;
    const int lane = tid & 31;
    const int wid  = tid >> 5;
    const int wm   = wid & 1;
    const int wn   = wid >> 1;
    const int bm   = blockIdx.y * 64;
    const int bn   = blockIdx.x * 128;

    float d[2][8][4];
#pragma unroll
    for (int i = 0; i < 2; i++)
#pragma unroll
        for (int j = 0; j < 8; j++)
#pragma unroll
            for (int r = 0; r < 4; r++) d[i][j][r] = 0.f;

    // per stage: A 512 + B 1024 = 1536 chunks, 12/thread
    auto load_chunk = [&](int buf, int c) {
        const int kofs = c * BKC;
        const uint32_t base = sbase + buf * WO_STAGE;
#pragma unroll
        for (int t = 0; t < 12; t++) {
            int i = tid + t * 128;
            if (i < 512) {
                int row = i >> 3, ch = i & 7;
                cpa16(base + row * ROWB + ch * 16,
                      A + (size_t)(bm + row) * GK + kofs + ch * 8);
            } else {
                int idx = i - 512;
                int row = idx >> 3, ch = idx & 7;
                cpa16(base + MAT64 + row * ROWB + ch * 16,
                      Bh + (size_t)(bn + row) * GK + kofs + ch * 8);
            }
        }
    };

    load_chunk(0, 0); cp_commit();

    const uint32_t a_off =
        (uint32_t)((wm * 32 + (lane & 15)) * ROWB + (lane >> 4) * 16);
    const uint32_t b_off = (uint32_t)(MAT64 +
        (wn * 64 + (lane & 7) + ((lane >> 4) & 1) * 8) * ROWB +
        ((lane >> 3) & 1) * 16);

    for (int c = 0; c < GNC; ++c) {
        const int b = c & 1;
        if (c + 1 < GNC) {
            load_chunk(b ^ 1, c + 1);
            cp_commit();
            cp_wait1();
        } else {
            cp_wait0();
        }
        __syncthreads();
        const uint32_t stg = sbase + b * WO_STAGE;
#pragma unroll
        for (int ks = 0; ks < 4; ks++) {
            uint32_t ah[2][4], bh[4][4];
#pragma unroll
            for (int i = 0; i < 2; i++)
                ldsm4(ah[i], stg + a_off + i * (16 * ROWB) + ks * 32);
#pragma unroll
            for (int jj = 0; jj < 4; jj++)
                ldsm4(bh[jj], stg + b_off + jj * (16 * ROWB) + ks * 32);
#pragma unroll
            for (int i = 0; i < 2; i++)
#pragma unroll
                for (int j = 0; j < 8; j++)
                    mma_f16(d[i][j], ah[i], &bh[j >> 1][(j & 1) * 2]);
        }
        __syncthreads();
    }

    const int r0 = bm + wm * 32 + (lane >> 2);
    const int c0 = bn + wn * 64 + (lane & 3) * 2;
#pragma unroll
    for (int i = 0; i < 2; i++)
#pragma unroll
        for (int j = 0; j < 8; j++) {
            int row = r0 + i * 16;
            int col = c0 + j * 8;
            *(float2*)&C[(size_t)row * N + col] =
                make_float2(d[i][j][0], d[i][j][1]);
            *(float2*)&C[(size_t)(row + 8) * N + col] =
                make_float2(d[i][j][2], d[i][j][3]);
        }
}

// ---------------- flash attention: fp16 HMMA, 1-pass QK ------------------
// Q-tile 64 rows, 128 threads (4 warps), 2 CTAs/SM, 3-stage KV, 1 sync/iter.
// smem: Q [0,16K); stage s at 16K + (s%3)*32K: Kh 16K | V 16K
#define FSTG 16384
#define FSTGB 32768
#define FSMEM (FSTG + 3 * FSTGB)        // 114688
#define NSTILE (TT / 64)                // 32

__global__ __launch_bounds__(128, 2)
void flash_hmma(const __half* __restrict__ Qh,
                const __half* __restrict__ Kh, const __half* __restrict__ Vv,
                __half* __restrict__ Ch) {
    extern __shared__ char sm[];
    const uint32_t sb = smem_u32(sm);
    const int tid = threadIdx.x, lane = tid & 31, w = tid >> 5;   // w: 0..3
    const int t0 = blockIdx.x * 64;
    const int h  = blockIdx.y;
    const int b  = blockIdx.z;
    const int kh = h & 7;

    const __half* qhp = Qh + (((size_t)(b * NH + h) * TT + t0) << 7);
    const __half* khp = Kh + (((size_t)(b * NKV + kh) * TT) << 7);
    const __half* vhp = Vv + (((size_t)(b * NKV + kh) * TT) << 7);

    // Q tile: 64 rows x 16 chunks = 1024 chunks / 128 threads
#pragma unroll
    for (int it = 0; it < 8; it++) {
        int i = tid + it * 128;
        int r = i >> 4, c = i & 15;
        cpa16(sb + r * 256 + ((c ^ (r & 7)) * 16), qhp + r * HD + c * 8);
    }
    cp_commit();

    auto load_kv = [&](int stg, int s) {
        const uint32_t bs = sb + FSTG + stg * FSTGB;
        const __half* srcs[2] = {khp + (size_t)s * 64 * HD,
                                 vhp + (size_t)s * 64 * HD};
#pragma unroll
        for (int it = 0; it < 16; it++) {
            int i = tid + it * 128;
            int arr = i >> 10, ci = i & 1023;
            int r = ci >> 4, c = ci & 15;
            cpa16(bs + arr * 16384 + r * 256 + ((c ^ (r & 7)) * 16),
                  srcs[arr] + r * HD + c * 8);
        }
    };
    load_kv(0, 0); cp_commit();
    load_kv(1, 1); cp_commit();

    float oa[16][4];
#pragma unroll
    for (int nt = 0; nt < 16; nt++)
#pragma unroll
        for (int c = 0; c < 4; c++) oa[nt][c] = 0.f;
    float m0 = -1e30f, m1 = -1e30f, l0 = 0.f, l1 = 0.f;
    const float scale = 0.08838834764831845f;

    const int qr = w * 16 + (lane & 15);       // 0..63
    const uint32_t qrow = sb + qr * 256;
    const int kr = (lane & 7) + ((lane >> 4) & 1) * 8;
    const int vr = lane & 15;

    for (int s = 0; s < NSTILE; s++) {
        if (s + 1 < NSTILE) cp_wait1(); else cp_wait0();
        __syncthreads();
        if (s + 2 < NSTILE) { load_kv((s + 2) % 3, s + 2); cp_commit(); }
        const uint32_t kb = sb + FSTG + (s % 3) * FSTGB;

        // ---- S = Q K^T (1-pass) ----
        float sa[8][4];
#pragma unroll
        for (int j = 0; j < 8; j++)
#pragma unroll
            for (int c = 0; c < 4; c++) sa[j][c] = 0.f;

#pragma unroll
        for (int kc = 0; kc < 8; kc++) {
            uint32_t qa[4];
            {
                int c = 2 * kc + (lane >> 4);
                ldsm4(qa, qrow + ((c ^ (qr & 7)) * 16));
            }
#pragma unroll
            for (int kt = 0; kt < 4; kt++) {
                uint32_t kfh[4];
                int krr = kt * 16 + kr;
                int kcc = 2 * kc + ((lane >> 3) & 1);
                ldsm4(kfh, kb + krr * 256 + ((kcc ^ (krr & 7)) * 16));
#pragma unroll
                for (int hn = 0; hn < 2; hn++)
                    mma_f16(sa[kt * 2 + hn], qa, &kfh[hn * 2]);
            }
        }

        // ---- online softmax (registers) ----
        float mx0 = -1e30f, mx1 = -1e30f;
#pragma unroll
        for (int j = 0; j < 8; j++) {
#pragma unroll
            for (int c = 0; c < 4; c++) sa[j][c] *= scale;
            mx0 = fmaxf(mx0, fmaxf(sa[j][0], sa[j][1]));
            mx1 = fmaxf(mx1, fmaxf(sa[j][2], sa[j][3]));
        }
#pragma unroll
        for (int off = 1; off <= 2; off <<= 1) {
            mx0 = fmaxf(mx0, __shfl_xor_sync(0xffffffffu, mx0, off));
            mx1 = fmaxf(mx1, __shfl_xor_sync(0xffffffffu, mx1, off));
        }
        float nm0 = fmaxf(m0, mx0), nm1 = fmaxf(m1, mx1);
        float al0 = __expf(m0 - nm0), al1 = __expf(m1 - nm1);
        float rs0 = 0.f, rs1 = 0.f;
#pragma unroll
        for (int j = 0; j < 8; j++) {
            sa[j][0] = __expf(sa[j][0] - nm0);
            sa[j][1] = __expf(sa[j][1] - nm0);
            sa[j][2] = __expf(sa[j][2] - nm1);
            sa[j][3] = __expf(sa[j][3] - nm1);
            rs0 += sa[j][0] + sa[j][1];
            rs1 += sa[j][2] + sa[j][3];
        }
#pragma unroll
        for (int off = 1; off <= 2; off <<= 1) {
            rs0 += __shfl_xor_sync(0xffffffffu, rs0, off);
            rs1 += __shfl_xor_sync(0xffffffffu, rs1, off);
        }
        l0 = l0 * al0 + rs0;  l1 = l1 * al1 + rs1;
        m0 = nm0;  m1 = nm1;
#pragma unroll
        for (int nt = 0; nt < 16; nt++) {
            oa[nt][0] *= al0; oa[nt][1] *= al0;
            oa[nt][2] *= al1; oa[nt][3] *= al1;
        }

        // ---- O += P V ----
#pragma unroll
        for (int kc2 = 0; kc2 < 4; kc2++) {
            uint32_t pa[4];
            pa[0] = pack_h2(sa[2 * kc2][0],     sa[2 * kc2][1]);
            pa[1] = pack_h2(sa[2 * kc2][2],     sa[2 * kc2][3]);
            pa[2] = pack_h2(sa[2 * kc2 + 1][0], sa[2 * kc2 + 1][1]);
            pa[3] = pack_h2(sa[2 * kc2 + 1][2], sa[2 * kc2 + 1][3]);
            int vrr = kc2 * 16 + vr;
            uint32_t vrow = kb + 16384 + vrr * 256;
#pragma unroll
            for (int nt2 = 0; nt2 < 8; nt2++) {
                uint32_t vf[4];
                int vc = nt2 * 2 + (lane >> 4);
                ldsm4t(vf, vrow + ((vc ^ (vrr & 7)) * 16));
                mma_f16(oa[nt2 * 2],     pa, &vf[0]);
                mma_f16(oa[nt2 * 2 + 1], pa, &vf[2]);
            }
        }
    }

    // ---- epilogue: normalize, store ctx as single fp16 -----------------
    float i0 = 1.f / l0, i1 = 1.f / l1;
    int rg0 = t0 + w * 16 + (lane >> 2);
    size_t row0 = (size_t)(b * TT + rg0) * DIM;
    size_t row1 = row0 + 8 * DIM;
#pragma unroll
    for (int nt = 0; nt < 16; nt++) {
        int col = h * HD + nt * 8 + (lane & 3) * 2;
        {
            __half2 hv = __floats2half2_rn(oa[nt][0] * i0, oa[nt][1] * i0);
            *(uint32_t*)(Ch + row0 + col) = *(uint32_t*)&hv;
        }
        {
            __half2 hv = __floats2half2_rn(oa[nt][2] * i1, oa[nt][3] * i1);
            *(uint32_t*)(Ch + row1 + col) = *(uint32_t*)&hv;
        }
    }
}

// ---------------------------------------------------------------------------
extern "C" void kernel_launch(void* const* d_in, const int* in_sizes, int n_in,
                              void* d_out, int out_size) {
    const float* x  = (const float*)d_in[0];
    const float* wq = (const float*)d_in[1];
    const float* wk = (const float*)d_in[2];
    const float* wv = (const float*)d_in[3];
    const float* wo = (const float*)d_in[4];
    const float* fc = (const float*)d_in[5];
    const float* fs = (const float*)d_in[6];
    float* out = (float*)d_out;

    __half *xh, *xl, *wqkv, *wop, *ch;
    cudaGetSymbolAddress((void**)&xh,   g_xh);
    cudaGetSymbolAddress((void**)&xl,   g_xl);
    cudaGetSymbolAddress((void**)&wqkv, g_wqkv);
    cudaGetSymbolAddress((void**)&wop,  g_wo);
    cudaGetSymbolAddress((void**)&ch,   g_ch);
    __half *fqh, *fkh, *fv;
    cudaGetSymbolAddress((void**)&fqh, g_fqh);
    cudaGetSymbolAddress((void**)&fkh, g_fkh);
    cudaGetSymbolAddress((void**)&fv,  g_fv);

    // fused, vectorized prepack (1 launch)
    prep_all<<<(TOTP4 + 255) / 256, 256>>>((const float4*)x, (const float4*)wq,
                                           (const float4*)wk, (const float4*)wv,
                                           (const float4*)wo);

    cudaFuncSetAttribute(gemm_qkv_rope,
                         cudaFuncAttributeMaxDynamicSharedMemorySize, QK_SMEM);
    cudaFuncSetAttribute(gemm_wo,
                         cudaFuncAttributeMaxDynamicSharedMemorySize, WO_SMEM);

    // qkv projection + fused rope + head-major fp16 pack (64-row tiles)
    gemm_qkv_rope<<<dim3(NQKV / 128, MTOK / 64), 128, QK_SMEM>>>(xh, xl, wqkv, fc, fs);

    cudaFuncSetAttribute(flash_hmma,
                         cudaFuncAttributeMaxDynamicSharedMemorySize, FSMEM);
    flash_hmma<<<dim3(TT / 64, NH, BB), 128, FSMEM>>>(fqh, fkh, fv, ch);

    // output projection (single-pass A, 64-row tiles, 3 CTA/SM)
    gemm_wo<<<dim3(DIM / 128, MTOK / 64), 128, WO_SMEM>>>(ch, wop, out, DIM);
}

// round 17
// speedup vs baseline: 1.4316x; 1.0198x over previous
#include <cuda_runtime.h>
#include <cuda_bf16.h>
#include <cuda_fp16.h>
#include <math.h>
#include <stdint.h>

#define BB 2
#define TT 2048
#define DIM 4096
#define NH 32
#define NKV 8
#define HD 128
#define MTOK (BB * TT)
#define GK 4096
#define NKVD (NKV * HD)             // 1024
#define NQKV (DIM + 2 * NKVD)       // 6144

// ---------------- device scratch ---------------------------------------
__device__ __align__(16) __half g_xh[(size_t)MTOK * DIM];
__device__ __align__(16) __half g_xl[(size_t)MTOK * DIM];
__device__ __align__(16) __half g_wqkv[(size_t)NQKV * GK];
__device__ __align__(16) __half g_wo[(size_t)DIM * DIM];
__device__ __align__(16) __half g_ch[(size_t)MTOK * DIM];

// head-major fp16 q/k/v (all single fp16) for flash
__device__ __align__(16) __half g_fqh[(size_t)BB * NH * TT * HD];
__device__ __align__(16) __half g_fkh[(size_t)BB * NKV * TT * HD];
__device__ __align__(16) __half g_fv [(size_t)BB * NKV * TT * HD];

// ---------------- helpers ----------------------------------------------
__device__ __forceinline__ uint32_t smem_u32(const void* p) {
    uint32_t a;
    asm("{ .reg .u64 t; cvta.to.shared.u64 t, %1; cvt.u32.u64 %0, t; }"
        : "=r"(a) : "l"(p));
    return a;
}
__device__ __forceinline__ void cpa16(uint32_t dst, const void* src) {
    asm volatile("cp.async.cg.shared.global [%0], [%1], 16;"
                 :: "r"(dst), "l"(src) : "memory");
}
__device__ __forceinline__ void cp_commit() {
    asm volatile("cp.async.commit_group;" ::: "memory");
}
__device__ __forceinline__ void cp_wait1() {
    asm volatile("cp.async.wait_group 1;" ::: "memory");
}
__device__ __forceinline__ void cp_wait0() {
    asm volatile("cp.async.wait_group 0;" ::: "memory");
}
__device__ __forceinline__ void ldsm4(uint32_t* r, uint32_t addr) {
    asm volatile("ldmatrix.sync.aligned.m8n8.x4.shared.b16 {%0,%1,%2,%3}, [%4];"
                 : "=r"(r[0]), "=r"(r[1]), "=r"(r[2]), "=r"(r[3]) : "r"(addr));
}
__device__ __forceinline__ void ldsm4t(uint32_t* r, uint32_t addr) {
    asm volatile("ldmatrix.sync.aligned.m8n8.x4.trans.shared.b16 {%0,%1,%2,%3}, [%4];"
                 : "=r"(r[0]), "=r"(r[1]), "=r"(r[2]), "=r"(r[3]) : "r"(addr));
}
__device__ __forceinline__ void mma_f16(float* d, const uint32_t* a, const uint32_t* b) {
    asm volatile(
        "mma.sync.aligned.m16n8k16.row.col.f32.f16.f16.f32 "
        "{%0,%1,%2,%3}, {%4,%5,%6,%7}, {%8,%9}, {%0,%1,%2,%3};\n"
        : "+f"(d[0]), "+f"(d[1]), "+f"(d[2]), "+f"(d[3])
        : "r"(a[0]), "r"(a[1]), "r"(a[2]), "r"(a[3]), "r"(b[0]), "r"(b[1]));
}
__device__ __forceinline__ uint32_t pack_h2(float lo, float hi) {
    __half2 h = __floats2half2_rn(lo, hi);
    return *(uint32_t*)&h;
}

// ---------------- fused prepack (vectorized, 4 elems/thread) -------------
#define NX  (MTOK * DIM)        // 16777216
#define NWQ (DIM * GK)          // 16777216
#define NWK (NKVD * GK)         // 4194304
#define TOTP4 ((NX + NWQ + 2 * NWK + NWQ) / 4)   // 14680064
__global__ void prep_all(const float4* __restrict__ x,
                         const float4* __restrict__ wq,
                         const float4* __restrict__ wk,
                         const float4* __restrict__ wv,
                         const float4* __restrict__ wo) {
    int i = blockIdx.x * blockDim.x + threadIdx.x;
    if (i >= TOTP4) return;
    if (i < NX / 4) {
        float4 v = x[i];
        __half2 h01 = __floats2half2_rn(v.x, v.y);
        __half2 h23 = __floats2half2_rn(v.z, v.w);
        __half2 l01 = __floats2half2_rn(v.x - __half2float(h01.x),
                                        v.y - __half2float(h01.y));
        __half2 l23 = __floats2half2_rn(v.z - __half2float(h23.x),
                                        v.w - __half2float(h23.y));
        uint2 hp; hp.x = *(uint32_t*)&h01; hp.y = *(uint32_t*)&h23;
        uint2 lp; lp.x = *(uint32_t*)&l01; lp.y = *(uint32_t*)&l23;
        *(uint2*)(g_xh + (size_t)i * 4) = hp;
        *(uint2*)(g_xl + (size_t)i * 4) = lp;
    } else {
        const float4* src;
        __half* dst;
        size_t j;
        if (i < (NX + NWQ) / 4) {
            j = i - NX / 4; src = wq; dst = g_wqkv;
        } else if (i < (NX + NWQ + NWK) / 4) {
            j = i - (NX + NWQ) / 4; src = wk; dst = g_wqkv + (size_t)DIM * GK;
        } else if (i < (NX + NWQ + 2 * NWK) / 4) {
            j = i - (NX + NWQ + NWK) / 4; src = wv;
            dst = g_wqkv + (size_t)(DIM + NKVD) * GK;
        } else {
            j = i - (NX + NWQ + 2 * NWK) / 4; src = wo; dst = g_wo;
        }
        float4 v = src[j];
        __half2 h01 = __floats2half2_rn(v.x, v.y);
        __half2 h23 = __floats2half2_rn(v.z, v.w);
        uint2 hp; hp.x = *(uint32_t*)&h01; hp.y = *(uint32_t*)&h23;
        *(uint2*)(dst + j * 4) = hp;
    }
}

// ---------------- shared GEMM constants ----------------------------------
#define BKC 64
#define ROWB 144
#define GNC (GK / BKC)                 // 64
#define MAT128 (128 * ROWB)            // 18432
#define MAT64  (64 * ROWB)             // 9216

// ---- GEMM 1: qkv projection, CTA tile 64x128, 128 thr, 3 CTA/SM --------
// stage: A-hi 9216 | A-lo 9216 | B 18432 = 36864; 2 stages = 73728
// V-column tiles (bn >= DIM+NKVD) skip the A-lo pass entirely.
#define QK_STAGE 36864
#define QK_SMEM (2 * QK_STAGE)

__global__ __launch_bounds__(128, 3)
void gemm_qkv_rope(const __half* __restrict__ Ah,
                   const __half* __restrict__ Al,
                   const __half* __restrict__ Bh,
                   const float* __restrict__ fc,
                   const float* __restrict__ fs) {
    extern __shared__ char sm[];
    const uint32_t sbase = smem_u32(sm);
    const int tid  = threadIdx.x;
    const int lane = tid & 31;
    const int wid  = tid >> 5;       // 0..3
    const int wm   = wid & 1;        // 2 M-warps
    const int wn   = wid >> 1;       // 2 N-warps
    const int bm   = blockIdx.y * 64;
    const int bn   = blockIdx.x * 128;
    const bool vtile = (bn >= DIM + NKVD);   // uniform per CTA

    float d[2][8][4];
#pragma unroll
    for (int i = 0; i < 2; i++)
#pragma unroll
        for (int j = 0; j < 8; j++)
#pragma unroll
            for (int r = 0; r < 4; r++) d[i][j][r] = 0.f;

    // per stage: Ah 512 + Al 512 (skipped for vtile) + B 1024 chunks
    auto load_chunk = [&](int buf, int c) {
        const int kofs = c * BKC;
        const uint32_t base = sbase + buf * QK_STAGE;
#pragma unroll
        for (int t = 0; t < 16; t++) {
            int i = tid + t * 128;
            if (i < 1024) {
                int mat = i >> 9;           // 0: Ah, 1: Al
                if (mat == 1 && vtile) continue;
                int idx = i & 511;
                int row = idx >> 3, ch = idx & 7;
                cpa16(base + mat * MAT64 + row * ROWB + ch * 16,
                      (mat ? Al : Ah) + (size_t)(bm + row) * GK + kofs + ch * 8);
            } else {
                int idx = i & 1023;
                int row = idx >> 3, ch = idx & 7;
                cpa16(base + 2 * MAT64 + row * ROWB + ch * 16,
                      Bh + (size_t)(bn + row) * GK + kofs + ch * 8);
            }
        }
    };

    load_chunk(0, 0); cp_commit();

    const uint32_t a_off =
        (uint32_t)((wm * 32 + (lane & 15)) * ROWB + (lane >> 4) * 16);
    const uint32_t b_off = (uint32_t)(2 * MAT64 +
        (wn * 64 + (lane & 7) + ((lane >> 4) & 1) * 8) * ROWB +
        ((lane >> 3) & 1) * 16);

    for (int c = 0; c < GNC; ++c) {
        const int b = c & 1;
        if (c + 1 < GNC) {
            load_chunk(b ^ 1, c + 1);
            cp_commit();
            cp_wait1();
        } else {
            cp_wait0();
        }
        __syncthreads();
        const uint32_t stg = sbase + b * QK_STAGE;
#pragma unroll
        for (int ks = 0; ks < 4; ks++) {
            uint32_t ah[2][4], al[2][4], bh[4][4];
#pragma unroll
            for (int i = 0; i < 2; i++)
                ldsm4(ah[i], stg + a_off + i * (16 * ROWB) + ks * 32);
            if (!vtile) {
#pragma unroll
                for (int i = 0; i < 2; i++)
                    ldsm4(al[i], stg + MAT64 + a_off + i * (16 * ROWB) + ks * 32);
            }
#pragma unroll
            for (int jj = 0; jj < 4; jj++)
                ldsm4(bh[jj], stg + b_off + jj * (16 * ROWB) + ks * 32);
#pragma unroll
            for (int i = 0; i < 2; i++)
#pragma unroll
                for (int j = 0; j < 8; j++) {
                    const uint32_t* ph = &bh[j >> 1][(j & 1) * 2];
                    mma_f16(d[i][j], ah[i], ph);
                    if (!vtile) mma_f16(d[i][j], al[i], ph);
                }
        }
        __syncthreads();
    }

    const int r0 = bm + wm * 32 + (lane >> 2);
    const int c0 = bn + wn * 64 + (lane & 3) * 2;

    auto store_pair = [&](int row, int col, float v0, float v1) {
        int b = row >> 11, t = row & 2047;
        if (col < DIM) {                       // q: rope, single fp16
            int hh = col >> 7, dp = (col & 127) >> 1;
            float c = fc[t * 64 + dp], s = fs[t * 64 + dp];
            float o0 = v0 * c - v1 * s;
            float o1 = v0 * s + v1 * c;
            size_t dst = (((size_t)(b * NH + hh) * TT + t) << 7) + 2 * dp;
            __half2 hv; hv.x = __float2half_rn(o0); hv.y = __float2half_rn(o1);
            *(uint32_t*)(g_fqh + dst) = *(uint32_t*)&hv;
        } else if (col < DIM + NKVD) {         // k: rope, single fp16
            int cc = col - DIM;
            int hh = cc >> 7, dp = (cc & 127) >> 1;
            float c = fc[t * 64 + dp], s = fs[t * 64 + dp];
            float o0 = v0 * c - v1 * s;
            float o1 = v0 * s + v1 * c;
            size_t dst = (((size_t)(b * NKV + hh) * TT + t) << 7) + 2 * dp;
            __half2 hv; hv.x = __float2half_rn(o0); hv.y = __float2half_rn(o1);
            *(uint32_t*)(g_fkh + dst) = *(uint32_t*)&hv;
        } else {                               // v: plain fp16
            int cc = col - DIM - NKVD;
            int hh = cc >> 7, dd = cc & 127;
            size_t dst = (((size_t)(b * NKV + hh) * TT + t) << 7) + dd;
            __half2 hv; hv.x = __float2half_rn(v0); hv.y = __float2half_rn(v1);
            *(uint32_t*)(g_fv + dst) = *(uint32_t*)&hv;
        }
    };

#pragma unroll
    for (int i = 0; i < 2; i++)
#pragma unroll
        for (int j = 0; j < 8; j++) {
            int col = c0 + j * 8;
            store_pair(r0 + i * 16,     col, d[i][j][0], d[i][j][1]);
            store_pair(r0 + i * 16 + 8, col, d[i][j][2], d[i][j][3]);
        }
}

// ---- GEMM 2: output projection, CTA tile 64x128, 128 thr, 3 CTA/SM -----
#define WO_STAGE 27648
#define WO_SMEM (2 * WO_STAGE)

__global__ __launch_bounds__(128, 3)
void gemm_wo(const __half* __restrict__ A,
             const __half* __restrict__ Bh,
             float* __restrict__ C, int N) {
    extern __shared__ char sm[];
    const uint32_t sbase = smem_u32(sm);
    const int tid  = threadIdx.x;
    const int lane = tid & 31;
    const int wid  = tid >> 5;
    const int wm   = wid & 1;
    const int wn   = wid >> 1;
    const int bm   = blockIdx.y * 64;
    const int bn   = blockIdx.x * 128;

    float d[2][8][4];
#pragma unroll
    for (int i = 0; i < 2; i++)
#pragma unroll
        for (int j = 0; j < 8; j++)
#pragma unroll
            for (int r = 0; r < 4; r++) d[i][j][r] = 0.f;

    auto load_chunk = [&](int buf, int c) {
        const int kofs = c * BKC;
        const uint32_t base = sbase + buf * WO_STAGE;
#pragma unroll
        for (int t = 0; t < 12; t++) {
            int i = tid + t * 128;
            if (i < 512) {
                int row = i >> 3, ch = i & 7;
                cpa16(base + row * ROWB + ch * 16,
                      A + (size_t)(bm + row) * GK + kofs + ch * 8);
            } else {
                int idx = i - 512;
                int row = idx >> 3, ch = idx & 7;
                cpa16(base + MAT64 + row * ROWB + ch * 16,
                      Bh + (size_t)(bn + row) * GK + kofs + ch * 8);
            }
        }
    };

    load_chunk(0, 0); cp_commit();

    const uint32_t a_off =
        (uint32_t)((wm * 32 + (lane & 15)) * ROWB + (lane >> 4) * 16);
    const uint32_t b_off = (uint32_t)(MAT64 +
        (wn * 64 + (lane & 7) + ((lane >> 4) & 1) * 8) * ROWB +
        ((lane >> 3) & 1) * 16);

    for (int c = 0; c < GNC; ++c) {
        const int b = c & 1;
        if (c + 1 < GNC) {
            load_chunk(b ^ 1, c + 1);
            cp_commit();
            cp_wait1();
        } else {
            cp_wait0();
        }
        __syncthreads();
        const uint32_t stg = sbase + b * WO_STAGE;
#pragma unroll
        for (int ks = 0; ks < 4; ks++) {
            uint32_t ah[2][4], bh[4][4];
#pragma unroll
            for (int i = 0; i < 2; i++)
                ldsm4(ah[i], stg + a_off + i * (16 * ROWB) + ks * 32);
#pragma unroll
            for (int jj = 0; jj < 4; jj++)
                ldsm4(bh[jj], stg + b_off + jj * (16 * ROWB) + ks * 32);
#pragma unroll
            for (int i = 0; i < 2; i++)
#pragma unroll
                for (int j = 0; j < 8; j++)
                    mma_f16(d[i][j], ah[i], &bh[j >> 1][(j & 1) * 2]);
        }
        __syncthreads();
    }

    const int r0 = bm + wm * 32 + (lane >> 2);
    const int c0 = bn + wn * 64 + (lane & 3) * 2;
#pragma unroll
    for (int i = 0; i < 2; i++)
#pragma unroll
        for (int j = 0; j < 8; j++) {
            int row = r0 + i * 16;
            int col = c0 + j * 8;
            *(float2*)&C[(size_t)row * N + col] =
                make_float2(d[i][j][0], d[i][j][1]);
            *(float2*)&C[(size_t)(row + 8) * N + col] =
                make_float2(d[i][j][2], d[i][j][3]);
        }
}

// ---------------- flash attention: fp16 HMMA, 1-pass QK ------------------
#define FSTG 16384
#define FSTGB 32768
#define FSMEM (FSTG + 3 * FSTGB)        // 114688
#define NSTILE (TT / 64)                // 32

__global__ __launch_bounds__(128, 2)
void flash_hmma(const __half* __restrict__ Qh,
                const __half* __restrict__ Kh, const __half* __restrict__ Vv,
                __half* __restrict__ Ch) {
    extern __shared__ char sm[];
    const uint32_t sb = smem_u32(sm);
    const int tid = threadIdx.x, lane = tid & 31, w = tid >> 5;   // w: 0..3
    const int t0 = blockIdx.x * 64;
    const int h  = blockIdx.y;
    const int b  = blockIdx.z;
    const int kh = h & 7;

    const __half* qhp = Qh + (((size_t)(b * NH + h) * TT + t0) << 7);
    const __half* khp = Kh + (((size_t)(b * NKV + kh) * TT) << 7);
    const __half* vhp = Vv + (((size_t)(b * NKV + kh) * TT) << 7);

#pragma unroll
    for (int it = 0; it < 8; it++) {
        int i = tid + it * 128;
        int r = i >> 4, c = i & 15;
        cpa16(sb + r * 256 + ((c ^ (r & 7)) * 16), qhp + r * HD + c * 8);
    }
    cp_commit();

    auto load_kv = [&](int stg, int s) {
        const uint32_t bs = sb + FSTG + stg * FSTGB;
        const __half* srcs[2] = {khp + (size_t)s * 64 * HD,
                                 vhp + (size_t)s * 64 * HD};
#pragma unroll
        for (int it = 0; it < 16; it++) {
            int i = tid + it * 128;
            int arr = i >> 10, ci = i & 1023;
            int r = ci >> 4, c = ci & 15;
            cpa16(bs + arr * 16384 + r * 256 + ((c ^ (r & 7)) * 16),
                  srcs[arr] + r * HD + c * 8);
        }
    };
    load_kv(0, 0); cp_commit();
    load_kv(1, 1); cp_commit();

    float oa[16][4];
#pragma unroll
    for (int nt = 0; nt < 16; nt++)
#pragma unroll
        for (int c = 0; c < 4; c++) oa[nt][c] = 0.f;
    float m0 = -1e30f, m1 = -1e30f, l0 = 0.f, l1 = 0.f;
    const float scale = 0.08838834764831845f;

    const int qr = w * 16 + (lane & 15);
    const uint32_t qrow = sb + qr * 256;
    const int kr = (lane & 7) + ((lane >> 4) & 1) * 8;
    const int vr = lane & 15;

    for (int s = 0; s < NSTILE; s++) {
        if (s + 1 < NSTILE) cp_wait1(); else cp_wait0();
        __syncthreads();
        if (s + 2 < NSTILE) { load_kv((s + 2) % 3, s + 2); cp_commit(); }
        const uint32_t kb = sb + FSTG + (s % 3) * FSTGB;

        float sa[8][4];
#pragma unroll
        for (int j = 0; j < 8; j++)
#pragma unroll
            for (int c = 0; c < 4; c++) sa[j][c] = 0.f;

#pragma unroll
        for (int kc = 0; kc < 8; kc++) {
            uint32_t qa[4];
            {
                int c = 2 * kc + (lane >> 4);
                ldsm4(qa, qrow + ((c ^ (qr & 7)) * 16));
            }
#pragma unroll
            for (int kt = 0; kt < 4; kt++) {
                uint32_t kfh[4];
                int krr = kt * 16 + kr;
                int kcc = 2 * kc + ((lane >> 3) & 1);
                ldsm4(kfh, kb + krr * 256 + ((kcc ^ (krr & 7)) * 16));
#pragma unroll
                for (int hn = 0; hn < 2; hn++)
                    mma_f16(sa[kt * 2 + hn], qa, &kfh[hn * 2]);
            }
        }

        float mx0 = -1e30f, mx1 = -1e30f;
#pragma unroll
        for (int j = 0; j < 8; j++) {
#pragma unroll
            for (int c = 0; c < 4; c++) sa[j][c] *= scale;
            mx0 = fmaxf(mx0, fmaxf(sa[j][0], sa[j][1]));
            mx1 = fmaxf(mx1, fmaxf(sa[j][2], sa[j][3]));
        }
#pragma unroll
        for (int off = 1; off <= 2; off <<= 1) {
            mx0 = fmaxf(mx0, __shfl_xor_sync(0xffffffffu, mx0, off));
            mx1 = fmaxf(mx1, __shfl_xor_sync(0xffffffffu, mx1, off));
        }
        float nm0 = fmaxf(m0, mx0), nm1 = fmaxf(m1, mx1);
        float al0 = __expf(m0 - nm0), al1 = __expf(m1 - nm1);
        float rs0 = 0.f, rs1 = 0.f;
#pragma unroll
        for (int j = 0; j < 8; j++) {
            sa[j][0] = __expf(sa[j][0] - nm0);
            sa[j][1] = __expf(sa[j][1] - nm0);
            sa[j][2] = __expf(sa[j][2] - nm1);
            sa[j][3] = __expf(sa[j][3] - nm1);
            rs0 += sa[j][0] + sa[j][1];
            rs1 += sa[j][2] + sa[j][3];
        }
#pragma unroll
        for (int off = 1; off <= 2; off <<= 1) {
            rs0 += __shfl_xor_sync(0xffffffffu, rs0, off);
            rs1 += __shfl_xor_sync(0xffffffffu, rs1, off);
        }
        l0 = l0 * al0 + rs0;  l1 = l1 * al1 + rs1;
        m0 = nm0;  m1 = nm1;
#pragma unroll
        for (int nt = 0; nt < 16; nt++) {
            oa[nt][0] *= al0; oa[nt][1] *= al0;
            oa[nt][2] *= al1; oa[nt][3] *= al1;
        }

#pragma unroll
        for (int kc2 = 0; kc2 < 4; kc2++) {
            uint32_t pa[4];
            pa[0] = pack_h2(sa[2 * kc2][0],     sa[2 * kc2][1]);
            pa[1] = pack_h2(sa[2 * kc2][2],     sa[2 * kc2][3]);
            pa[2] = pack_h2(sa[2 * kc2 + 1][0], sa[2 * kc2 + 1][1]);
            pa[3] = pack_h2(sa[2 * kc2 + 1][2], sa[2 * kc2 + 1][3]);
            int vrr = kc2 * 16 + vr;
            uint32_t vrow = kb + 16384 + vrr * 256;
#pragma unroll
            for (int nt2 = 0; nt2 < 8; nt2++) {
                uint32_t vf[4];
                int vc = nt2 * 2 + (lane >> 4);
                ldsm4t(vf, vrow + ((vc ^ (vrr & 7)) * 16));
                mma_f16(oa[nt2 * 2],     pa, &vf[0]);
                mma_f16(oa[nt2 * 2 + 1], pa, &vf[2]);
            }
        }
    }

    float i0 = 1.f / l0, i1 = 1.f / l1;
    int rg0 = t0 + w * 16 + (lane >> 2);
    size_t row0 = (size_t)(b * TT + rg0) * DIM;
    size_t row1 = row0 + 8 * DIM;
#pragma unroll
    for (int nt = 0; nt < 16; nt++) {
        int col = h * HD + nt * 8 + (lane & 3) * 2;
        {
            __half2 hv = __floats2half2_rn(oa[nt][0] * i0, oa[nt][1] * i0);
            *(uint32_t*)(Ch + row0 + col) = *(uint32_t*)&hv;
        }
        {
            __half2 hv = __floats2half2_rn(oa[nt][2] * i1, oa[nt][3] * i1);
            *(uint32_t*)(Ch + row1 + col) = *(uint32_t*)&hv;
        }
    }
}

// ---------------------------------------------------------------------------
extern "C" void kernel_launch(void* const* d_in, const int* in_sizes, int n_in,
                              void* d_out, int out_size) {
    const float* x  = (const float*)d_in[0];
    const float* wq = (const float*)d_in[1];
    const float* wk = (const float*)d_in[2];
    const float* wv = (const float*)d_in[3];
    const float* wo = (const float*)d_in[4];
    const float* fc = (const float*)d_in[5];
    const float* fs = (const float*)d_in[6];
    float* out = (float*)d_out;

    __half *xh, *xl, *wqkv, *wop, *ch;
    cudaGetSymbolAddress((void**)&xh,   g_xh);
    cudaGetSymbolAddress((void**)&xl,   g_xl);
    cudaGetSymbolAddress((void**)&wqkv, g_wqkv);
    cudaGetSymbolAddress((void**)&wop,  g_wo);
    cudaGetSymbolAddress((void**)&ch,   g_ch);
    __half *fqh, *fkh, *fv;
    cudaGetSymbolAddress((void**)&fqh, g_fqh);
    cudaGetSymbolAddress((void**)&fkh, g_fkh);
    cudaGetSymbolAddress((void**)&fv,  g_fv);

    // fused, vectorized prepack (1 launch)
    prep_all<<<(TOTP4 + 255) / 256, 256>>>((const float4*)x, (const float4*)wq,
                                           (const float4*)wk, (const float4*)wv,
                                           (const float4*)wo);

    cudaFuncSetAttribute(gemm_qkv_rope,
                         cudaFuncAttributeMaxDynamicSharedMemorySize, QK_SMEM);
    cudaFuncSetAttribute(gemm_wo,
                         cudaFuncAttributeMaxDynamicSharedMemorySize, WO_SMEM);

    // qkv projection + fused rope + head-major fp16 pack (64-row tiles)
    gemm_qkv_rope<<<dim3(NQKV / 128, MTOK / 64), 128, QK_SMEM>>>(xh, xl, wqkv, fc, fs);

    cudaFuncSetAttribute(flash_hmma,
                         cudaFuncAttributeMaxDynamicSharedMemorySize, FSMEM);
    flash_hmma<<<dim3(TT / 64, NH, BB), 128, FSMEM>>>(fqh, fkh, fv, ch);

    // output projection (single-pass A, 64-row tiles, 3 CTA/SM)
    gemm_wo<<<dim3(DIM / 128, MTOK / 64), 128, WO_SMEM>>>(ch, wop, out, DIM);
}